// round 8
// baseline (speedup 1.0000x reference)
#include <cuda_runtime.h>
#include <math.h>

#define S_TOT 2560      // B*N sequences
#define T_LEN 70
#define HIDN  200
#define G3    600
#define IND   60
#define NBAG  128
#define NSEN  20
#define NREL  100

typedef unsigned long long ULL;

// ---------------- scratch (static device memory) ----------------------------
__device__ float g_x[S_TOT * T_LEN * IND];
__device__ float g_xp_f[(size_t)T_LEN * S_TOT * G3];
__device__ float g_xp_b[(size_t)T_LEN * S_TOT * G3];
__device__ float g_seq_f[(size_t)T_LEN * S_TOT * HIDN];
__device__ float g_seq_b[(size_t)T_LEN * S_TOT * HIDN];
__device__ float g_zero[S_TOT * HIDN];          // h0 = 0
__device__ float g_H[S_TOT * HIDN];
__device__ float g_bagloss[NBAG];
__device__ int   g_ctr[2][20];                  // per (dir,row-tile) step counters

__device__ __forceinline__ float sigm(float x) { return 1.f / (1.f + expf(-x)); }

__device__ __forceinline__ ULL pack2(float x, float y) {
    ULL r; asm("mov.b64 %0, {%1, %2};" : "=l"(r) : "f"(x), "f"(y)); return r;
}
__device__ __forceinline__ void ffma2(ULL& d, ULL a, ULL b) {
    asm("fma.rn.f32x2 %0, %1, %2, %0;" : "+l"(d) : "l"(a), "l"(b));
}
__device__ __forceinline__ void unpack2(ULL v, float& x, float& y) {
    asm("mov.b64 {%0, %1}, %2;" : "=f"(x), "=f"(y) : "l"(v));
}

// ---------------- init: zero h0 buffer + counters ----------------------------
__global__ void init_kernel() {
    int i = blockIdx.x * blockDim.x + threadIdx.x;
    if (i < S_TOT * HIDN) g_zero[i] = 0.f;
    if (i < 40) ((int*)g_ctr)[i] = 0;
}

// ---------------- embedding gather + concat ---------------------------------
__global__ void gather_kernel(const int* __restrict__ tok, const int* __restrict__ p1,
                              const int* __restrict__ p2, const float* __restrict__ emb,
                              const float* __restrict__ pemb) {
    int idx = blockIdx.x * blockDim.x + threadIdx.x;
    if (idx >= S_TOT * T_LEN * IND) return;
    int st = idx / IND;
    int c  = idx - st * IND;
    float v;
    if (c < 50)      v = emb[(size_t)tok[st] * 50 + c];
    else if (c < 55) v = pemb[(size_t)p1[st] * 5 + (c - 50)];
    else             v = pemb[(size_t)p2[st] * 5 + (c - 55)];
    g_x[idx] = v;
}

// ---------------- xp = x @ W_ih^T + b_ih  (both directions) -----------------
// grid: (179200/256=700, 6, 2)  block: 320
// tile: 256 rows x 100 cols, K=60 (3 chunks of 20). 8 rows x 10 cols / thread.
// A staged natural (no duplication), pairs built in registers.
__global__ void __launch_bounds__(320) xp_gemm_kernel(
    const float* __restrict__ Wf, const float* __restrict__ Wb,
    const float* __restrict__ bf, const float* __restrict__ bb)
{
    const int dir = blockIdx.z;
    const float* W    = dir ? Wb : Wf;
    const float* bias = dir ? bb : bf;
    float* xp = dir ? g_xp_b : g_xp_f;

    const int m0 = blockIdx.x * 256;
    const int c0 = blockIdx.y * 100;

    __shared__ float As[2][20][256];
    __shared__ float Bs[2][20][104];

    const int tid = threadIdx.x;
    const int tx = tid % 10;       // 10 cols
    const int ty = tid / 10;       // 0..31 -> 8 rows each

    ULL acc[8][5];
    #pragma unroll
    for (int r = 0; r < 8; r++)
        #pragma unroll
        for (int p = 0; p < 5; p++) acc[r][p] = 0ULL;

    // ---- stage chunk 0 ----
    #pragma unroll
    for (int i = 0; i < 4; i++) {
        int task = tid + 320 * i;               // 0..1279
        int row = task & 255, kq = task >> 8;   // kq 0..4
        float4 v = *(const float4*)&g_x[(size_t)(m0 + row) * IND + 4 * kq];
        As[0][4 * kq + 0][row] = v.x;
        As[0][4 * kq + 1][row] = v.y;
        As[0][4 * kq + 2][row] = v.z;
        As[0][4 * kq + 3][row] = v.w;
    }
    #pragma unroll
    for (int i = 0; i < 2; i++) {
        int task = tid + 320 * i;               // need < 500
        if (task < 500) {
            int col = task % 100, kq = task / 100;
            float4 v = *(const float4*)&W[(size_t)(c0 + col) * IND + 4 * kq];
            Bs[0][4 * kq + 0][col] = v.x;
            Bs[0][4 * kq + 1][col] = v.y;
            Bs[0][4 * kq + 2][col] = v.z;
            Bs[0][4 * kq + 3][col] = v.w;
        }
    }
    __syncthreads();

    for (int c = 0; c < 3; c++) {
        const int buf = c & 1;
        const bool more = (c < 2);
        float4 sta[4], stb[2];
        if (more) {
            int k0n = (c + 1) * 20;
            #pragma unroll
            for (int i = 0; i < 4; i++) {
                int task = tid + 320 * i;
                int row = task & 255, kq = task >> 8;
                sta[i] = *(const float4*)&g_x[(size_t)(m0 + row) * IND + k0n + 4 * kq];
            }
            #pragma unroll
            for (int i = 0; i < 2; i++) {
                int task = tid + 320 * i;
                if (task < 500) {
                    int col = task % 100, kq = task / 100;
                    stb[i] = *(const float4*)&W[(size_t)(c0 + col) * IND + k0n + 4 * kq];
                }
            }
        }
        #pragma unroll 5
        for (int k = 0; k < 20; k++) {
            float4 a0 = *(const float4*)&As[buf][k][8 * ty];
            float4 a1 = *(const float4*)&As[buf][k][8 * ty + 4];
            ULL ap[8];
            ap[0] = pack2(a0.x, a0.x); ap[1] = pack2(a0.y, a0.y);
            ap[2] = pack2(a0.z, a0.z); ap[3] = pack2(a0.w, a0.w);
            ap[4] = pack2(a1.x, a1.x); ap[5] = pack2(a1.y, a1.y);
            ap[6] = pack2(a1.z, a1.z); ap[7] = pack2(a1.w, a1.w);
            ULL bv[5];
            #pragma unroll
            for (int p = 0; p < 5; p++)
                bv[p] = *(const ULL*)&Bs[buf][k][10 * tx + 2 * p];
            #pragma unroll
            for (int r = 0; r < 8; r++)
                #pragma unroll
                for (int p = 0; p < 5; p++) ffma2(acc[r][p], ap[r], bv[p]);
        }
        __syncthreads();
        if (more) {
            #pragma unroll
            for (int i = 0; i < 4; i++) {
                int task = tid + 320 * i;
                int row = task & 255, kq = task >> 8;
                As[buf ^ 1][4 * kq + 0][row] = sta[i].x;
                As[buf ^ 1][4 * kq + 1][row] = sta[i].y;
                As[buf ^ 1][4 * kq + 2][row] = sta[i].z;
                As[buf ^ 1][4 * kq + 3][row] = sta[i].w;
            }
            #pragma unroll
            for (int i = 0; i < 2; i++) {
                int task = tid + 320 * i;
                if (task < 500) {
                    int col = task % 100, kq = task / 100;
                    Bs[buf ^ 1][4 * kq + 0][col] = stb[i].x;
                    Bs[buf ^ 1][4 * kq + 1][col] = stb[i].y;
                    Bs[buf ^ 1][4 * kq + 2][col] = stb[i].z;
                    Bs[buf ^ 1][4 * kq + 3][col] = stb[i].w;
                }
            }
            __syncthreads();
        }
    }

    #pragma unroll
    for (int r = 0; r < 8; r++) {
        int m = m0 + 8 * ty + r;
        int s = m / T_LEN, t = m - s * T_LEN;
        size_t base = ((size_t)t * S_TOT + s) * G3 + c0 + 10 * tx;
        #pragma unroll
        for (int p = 0; p < 5; p++) {
            float lo, hi;
            unpack2(acc[r][p], lo, hi);
            int cc = c0 + 10 * tx + 2 * p;
            *(float2*)&xp[base + 2 * p] = make_float2(lo + bias[cc], hi + bias[cc + 1]);
        }
    }
}

// ---------------- persistent bidirectional GRU ------------------------------
// grid (7,20,2) = 280 CTAs, 128 threads, 2/SM -> one wave.
// Per thread: 8 rows x 4 cols x 3 gates. A staged natural, pairs in registers.
// W slice resident in smem. hprev = seq[t_prev]. Spin-sync among 7 CTAs.
#define KCH 20
#define NCHUNK 10           // 10*20 = 200 exact

__global__ void __launch_bounds__(128, 2) gru_persistent_kernel(
    const float* __restrict__ Whh_f, const float* __restrict__ Whh_b,
    const float* __restrict__ bhh_f, const float* __restrict__ bhh_b)
{
    extern __shared__ char smraw[];
    float* Ws = (float*)smraw;                     // [200][96]
    float* As = (float*)(smraw + 200 * 96 * 4);    // [2][20][128]

    const int jb   = blockIdx.x;        // 0..6
    const int rowt = blockIdx.y;        // 0..19
    const int dir  = blockIdx.z;
    const int tid  = threadIdx.x;
    const int tx   = tid & 7;           // col group: 4 cols
    const int ty   = tid >> 3;          // 0..15 -> 8 rows each
    const int row0 = rowt * 128;
    const int j0   = jb * 32;
    const int j    = j0 + 4 * tx;
    const bool jv  = (j < HIDN);

    const float* W    = dir ? Whh_b : Whh_f;
    const float* bhh  = dir ? bhh_b : bhh_f;
    const float* xpb  = dir ? g_xp_b : g_xp_f;
    float*       seqb = dir ? g_seq_b : g_seq_f;

    // ---- W slice to smem once ----
    for (int e = tid; e < 96 * HIDN; e += 128) {
        int c = e / HIDN;
        int k = e - c * HIDN;
        int g = c >> 5, h = c & 31;
        int col = j0 + h;
        Ws[k * 96 + c] = (col < HIDN)
            ? W[((size_t)g * HIDN + col) * HIDN + k] : 0.f;
    }

    float br[4] = {0,0,0,0}, bz[4] = {0,0,0,0}, bn[4] = {0,0,0,0};
    if (jv) {
        #pragma unroll
        for (int cc = 0; cc < 4; cc++) {
            br[cc] = bhh[j + cc];
            bz[cc] = bhh[HIDN + j + cc];
            bn[cc] = bhh[2 * HIDN + j + cc];
        }
    }
    __syncthreads();

    int* ctr = &g_ctr[dir][rowt];
    const int myrow = row0 + tid;       // staging: one row per thread

    for (int s = 0; s < T_LEN; s++) {
        const int t = dir ? (T_LEN - 1 - s) : s;
        const int tprev = dir ? (t + 1) : (t - 1);
        const float* hprev = (s == 0) ? g_zero
                                      : seqb + (size_t)tprev * S_TOT * HIDN;
        const float* xp_t  = xpb + (size_t)t * S_TOT * G3;
        float*       seq_t = seqb + (size_t)t * S_TOT * HIDN;

        // prefetch this step's xp working set to L2 (row = tid covers tile)
        {
            const float* pf = xp_t + (size_t)myrow * G3 + j0;
            #pragma unroll
            for (int g = 0; g < 3; g++) {
                asm volatile("prefetch.global.L2 [%0];" :: "l"(pf + g * HIDN));
                asm volatile("prefetch.global.L2 [%0];" :: "l"(pf + g * HIDN + 31));
            }
        }

        ULL acc[3][8][2];
        #pragma unroll
        for (int g = 0; g < 3; g++)
            #pragma unroll
            for (int r = 0; r < 8; r++) { acc[g][r][0] = 0ULL; acc[g][r][1] = 0ULL; }

        if (s > 0) {
            // preload chunk 0 (natural layout, one row per thread)
            #pragma unroll
            for (int i = 0; i < 5; i++) {
                float4 v = *(const float4*)&hprev[(size_t)myrow * HIDN + 4 * i];
                As[(4 * i + 0) * 128 + tid] = v.x;
                As[(4 * i + 1) * 128 + tid] = v.y;
                As[(4 * i + 2) * 128 + tid] = v.z;
                As[(4 * i + 3) * 128 + tid] = v.w;
            }
            __syncthreads();

            for (int c = 0; c < NCHUNK; c++) {
                const int buf = c & 1;
                const bool more = (c + 1 < NCHUNK);
                float4 st[5];
                if (more) {
                    int k0n = (c + 1) * KCH;
                    #pragma unroll
                    for (int i = 0; i < 5; i++)
                        st[i] = *(const float4*)&hprev[(size_t)myrow * HIDN + k0n + 4 * i];
                }

                const float* Ab = As + buf * (KCH * 128);
                #pragma unroll 5
                for (int k = 0; k < KCH; k++) {
                    float4 a0 = *(const float4*)&Ab[k * 128 + 8 * ty];
                    float4 a1 = *(const float4*)&Ab[k * 128 + 8 * ty + 4];
                    ULL ap[8];
                    ap[0] = pack2(a0.x, a0.x); ap[1] = pack2(a0.y, a0.y);
                    ap[2] = pack2(a0.z, a0.z); ap[3] = pack2(a0.w, a0.w);
                    ap[4] = pack2(a1.x, a1.x); ap[5] = pack2(a1.y, a1.y);
                    ap[6] = pack2(a1.z, a1.z); ap[7] = pack2(a1.w, a1.w);
                    const float* bk = Ws + (size_t)(c * KCH + k) * 96 + 4 * tx;
                    ulonglong2 b0 = *(const ulonglong2*)(bk);
                    ulonglong2 b1 = *(const ulonglong2*)(bk + 32);
                    ulonglong2 b2 = *(const ulonglong2*)(bk + 64);
                    #pragma unroll
                    for (int r = 0; r < 8; r++) {
                        ffma2(acc[0][r][0], ap[r], b0.x);
                        ffma2(acc[0][r][1], ap[r], b0.y);
                        ffma2(acc[1][r][0], ap[r], b1.x);
                        ffma2(acc[1][r][1], ap[r], b1.y);
                        ffma2(acc[2][r][0], ap[r], b2.x);
                        ffma2(acc[2][r][1], ap[r], b2.y);
                    }
                }
                __syncthreads();
                if (more) {
                    float* An = As + (buf ^ 1) * (KCH * 128);
                    #pragma unroll
                    for (int i = 0; i < 5; i++) {
                        An[(4 * i + 0) * 128 + tid] = st[i].x;
                        An[(4 * i + 1) * 128 + tid] = st[i].y;
                        An[(4 * i + 2) * 128 + tid] = st[i].z;
                        An[(4 * i + 3) * 128 + tid] = st[i].w;
                    }
                    __syncthreads();
                }
            }
        }

        // ---- epilogue: gates -> h, write seq[t] ----
        if (jv) {
            #pragma unroll
            for (int rr = 0; rr < 8; rr++) {
                int row = row0 + 8 * ty + rr;
                const float* xr = xp_t + (size_t)row * G3;
                float4 xrv = *(const float4*)&xr[j];
                float4 xzv = *(const float4*)&xr[HIDN + j];
                float4 xnv = *(const float4*)&xr[2 * HIDN + j];
                float4 hpv = *(const float4*)&hprev[(size_t)row * HIDN + j];
                float gr[4], gz[4], gn[4];
                unpack2(acc[0][rr][0], gr[0], gr[1]); unpack2(acc[0][rr][1], gr[2], gr[3]);
                unpack2(acc[1][rr][0], gz[0], gz[1]); unpack2(acc[1][rr][1], gz[2], gz[3]);
                unpack2(acc[2][rr][0], gn[0], gn[1]); unpack2(acc[2][rr][1], gn[2], gn[3]);
                float xv[4] = {xrv.x, xrv.y, xrv.z, xrv.w};
                float zv[4] = {xzv.x, xzv.y, xzv.z, xzv.w};
                float nv[4] = {xnv.x, xnv.y, xnv.z, xnv.w};
                float hv[4] = {hpv.x, hpv.y, hpv.z, hpv.w};
                float out[4];
                #pragma unroll
                for (int cc = 0; cc < 4; cc++) {
                    float rg = sigm(xv[cc] + gr[cc] + br[cc]);
                    float zg = sigm(zv[cc] + gz[cc] + bz[cc]);
                    float ng = tanhf(nv[cc] + rg * (gn[cc] + bn[cc]));
                    out[cc] = (1.f - zg) * ng + zg * hv[cc];
                }
                *(float4*)&seq_t[(size_t)row * HIDN + j] =
                    make_float4(out[0], out[1], out[2], out[3]);
            }
        }

        // ---- group sync: 7 CTAs sharing (dir,row-tile) ----
        __threadfence();
        __syncthreads();
        if (tid == 0) {
            atomicAdd(ctr, 1);
            int target = 7 * (s + 1);
            while (*(volatile int*)ctr < target) { }
            __threadfence();
        }
        __syncthreads();
    }
}

// ---------------- word-level attention (tup cached in smem) -----------------
__global__ void __launch_bounds__(256) word_attn_kernel(const float* __restrict__ aw)
{
    extern __shared__ float tup[];       // [70][200]
    __shared__ float sc[T_LEN];
    const int s = blockIdx.x;
    const int lane = threadIdx.x & 31, wid = threadIdx.x >> 5;

    for (int t = wid; t < T_LEN; t += 8) {
        const float* f = g_seq_f + ((size_t)t * S_TOT + s) * HIDN;
        const float* b = g_seq_b + ((size_t)t * S_TOT + s) * HIDN;
        float sum = 0.f;
        for (int d = lane; d < HIDN; d += 32) {
            float v = f[d] + b[d];
            tup[t * HIDN + d] = v;
            sum += tanhf(v) * aw[d];
        }
        #pragma unroll
        for (int o = 16; o > 0; o >>= 1) sum += __shfl_xor_sync(0xffffffffu, sum, o);
        if (lane == 0) sc[t] = sum;
    }
    __syncthreads();
    if (threadIdx.x == 0) {
        float m = sc[0];
        for (int t = 1; t < T_LEN; t++) m = fmaxf(m, sc[t]);
        float ssum = 0.f;
        for (int t = 0; t < T_LEN; t++) { float e2 = expf(sc[t] - m); sc[t] = e2; ssum += e2; }
        float inv = 1.f / ssum;
        for (int t = 0; t < T_LEN; t++) sc[t] *= inv;
    }
    __syncthreads();
    for (int d = threadIdx.x; d < HIDN; d += 256) {
        float acc = 0.f;
        #pragma unroll 7
        for (int t = 0; t < T_LEN; t++) acc += sc[t] * tup[t * HIDN + d];
        g_H[(size_t)s * HIDN + d] = acc;
    }
}

// ---------------- bag attention + logits + BCE ------------------------------
__global__ void __launch_bounds__(128) bag_kernel(
    const float* __restrict__ sen_a, const float* __restrict__ sen_r,
    const float* __restrict__ rel, const float* __restrict__ sen_d,
    const int* __restrict__ label, float* __restrict__ logits)
{
    const int b = blockIdx.x;
    __shared__ float Hs[NSEN][HIDN];
    __shared__ float ew[NSEN];
    __shared__ float Sv[HIDN];
    __shared__ float red[128];

    for (int e = threadIdx.x; e < NSEN * HIDN; e += 128)
        Hs[e / HIDN][e % HIDN] = g_H[(size_t)b * NSEN * HIDN + e];
    __syncthreads();

    const int lane = threadIdx.x & 31, wid = threadIdx.x >> 5;
    for (int n = wid; n < NSEN; n += 4) {
        float sum = 0.f;
        for (int d = lane; d < HIDN; d += 32)
            sum += Hs[n][d] * sen_a[d] * sen_r[d];
        #pragma unroll
        for (int o = 16; o > 0; o >>= 1) sum += __shfl_xor_sync(0xffffffffu, sum, o);
        if (lane == 0) ew[n] = sum;
    }
    __syncthreads();
    if (threadIdx.x == 0) {
        float m = ew[0];
        for (int n = 1; n < NSEN; n++) m = fmaxf(m, ew[n]);
        float s2 = 0.f;
        for (int n = 0; n < NSEN; n++) { float e2 = expf(ew[n] - m); ew[n] = e2; s2 += e2; }
        float inv = 1.f / s2;
        for (int n = 0; n < NSEN; n++) ew[n] *= inv;
    }
    __syncthreads();
    for (int d = threadIdx.x; d < HIDN; d += 128) {
        float acc = 0.f;
        for (int n = 0; n < NSEN; n++) acc += ew[n] * Hs[n][d];
        Sv[d] = acc;
    }
    __syncthreads();

    int lab = label[b];
    float bce = 0.f;
    if (threadIdx.x < NREL) {
        int r = threadIdx.x;
        float l = sen_d[r];
        for (int d = 0; d < HIDN; d++) l += Sv[d] * rel[(size_t)r * HIDN + d];
        logits[(size_t)b * NREL + r] = l;
        float tgt = (lab == r) ? 1.f : 0.f;
        bce = fmaxf(l, 0.f) - l * tgt + log1pf(expf(-fabsf(l)));
    }
    red[threadIdx.x] = bce;
    __syncthreads();
    for (int o = 64; o > 0; o >>= 1) {
        if (threadIdx.x < o) red[threadIdx.x] += red[threadIdx.x + o];
        __syncthreads();
    }
    if (threadIdx.x == 0) g_bagloss[b] = red[0] / (float)NREL;
}

__global__ void loss_sum_kernel(float* __restrict__ out) {
    __shared__ float red[128];
    red[threadIdx.x] = g_bagloss[threadIdx.x];
    __syncthreads();
    for (int o = 64; o > 0; o >>= 1) {
        if (threadIdx.x < o) red[threadIdx.x] += red[threadIdx.x + o];
        __syncthreads();
    }
    if (threadIdx.x == 0) out[0] = red[0];
}

// ---------------- launch ----------------------------------------------------
extern "C" void kernel_launch(void* const* d_in, const int* in_sizes, int n_in,
                              void* d_out, int out_size)
{
    const int*   tok    = (const int*)d_in[0];
    const int*   p1     = (const int*)d_in[1];
    const int*   p2     = (const int*)d_in[2];
    const int*   lab    = (const int*)d_in[3];
    const float* emb    = (const float*)d_in[4];
    const float* pemb   = (const float*)d_in[5];
    const float* Wih_f  = (const float*)d_in[6];
    const float* Whh_f  = (const float*)d_in[7];
    const float* bih_f  = (const float*)d_in[8];
    const float* bhh_f  = (const float*)d_in[9];
    const float* Wih_b  = (const float*)d_in[10];
    const float* Whh_b  = (const float*)d_in[11];
    const float* bih_b  = (const float*)d_in[12];
    const float* bhh_b  = (const float*)d_in[13];
    const float* aw     = (const float*)d_in[14];
    const float* sen_a  = (const float*)d_in[15];
    const float* sen_r  = (const float*)d_in[16];
    const float* rel    = (const float*)d_in[17];
    const float* sen_d  = (const float*)d_in[18];
    float* out = (float*)d_out;

    init_kernel<<<(S_TOT * HIDN + 255) / 256, 256>>>();
    gather_kernel<<<(S_TOT * T_LEN * IND + 255) / 256, 256>>>(tok, p1, p2, emb, pemb);

    dim3 g2(S_TOT * T_LEN / 256, G3 / 100, 2);
    xp_gemm_kernel<<<g2, 320>>>(Wih_f, Wih_b, bih_f, bih_b);

    static const int gru_smem = HIDN * 96 * 4 + 2 * KCH * 128 * 4;   // 76800+20480
    cudaFuncSetAttribute(gru_persistent_kernel,
                         cudaFuncAttributeMaxDynamicSharedMemorySize, gru_smem);
    dim3 g3(7, 20, 2);
    gru_persistent_kernel<<<g3, 128, gru_smem>>>(Whh_f, Whh_b, bhh_f, bhh_b);

    static const int attn_smem = T_LEN * HIDN * (int)sizeof(float);  // 56000
    cudaFuncSetAttribute(word_attn_kernel,
                         cudaFuncAttributeMaxDynamicSharedMemorySize, attn_smem);
    word_attn_kernel<<<S_TOT, 256, attn_smem>>>(aw);
    bag_kernel<<<NBAG, 128>>>(sen_a, sen_r, rel, sen_d, lab, out + 1);
    loss_sum_kernel<<<1, 128>>>(out);
}

// round 11
// speedup vs baseline: 1.2202x; 1.2202x over previous
#include <cuda_runtime.h>
#include <cuda_bf16.h>
#include <math.h>
#include <stdint.h>

#define S_TOT 2560
#define T_LEN 70
#define HIDN  200
#define G3    600
#define IND   60
#define NBAG  128
#define NSEN  20
#define NREL  100
#define HPAD  208

typedef unsigned long long ULL;

__device__ float g_x[S_TOT * T_LEN * IND];
__device__ float g_xp_f[(size_t)T_LEN * S_TOT * G3];
__device__ float g_xp_b[(size_t)T_LEN * S_TOT * G3];
__device__ float g_seq_f[(size_t)T_LEN * S_TOT * HIDN];
__device__ float g_seq_b[(size_t)T_LEN * S_TOT * HIDN];
__device__ __nv_bfloat16 g_hbh[2][2][S_TOT * HPAD];   // [dir][parity]
__device__ __nv_bfloat16 g_hbl[2][2][S_TOT * HPAD];
__device__ float g_H[S_TOT * HIDN];
__device__ float g_bagloss[NBAG];
__device__ int   g_ctr[2][20];

__device__ __forceinline__ float sigm(float x) { return 1.f / (1.f + expf(-x)); }
__device__ __forceinline__ ULL pack2(float x, float y) {
    ULL r; asm("mov.b64 %0, {%1, %2};" : "=l"(r) : "f"(x), "f"(y)); return r;
}
__device__ __forceinline__ void ffma2(ULL& d, ULL a, ULL b) {
    asm("fma.rn.f32x2 %0, %1, %2, %0;" : "+l"(d) : "l"(a), "l"(b));
}
__device__ __forceinline__ void unpack2(ULL v, float& x, float& y) {
    asm("mov.b64 {%0, %1}, %2;" : "=f"(x), "=f"(y) : "l"(v));
}
__device__ __forceinline__ uint32_t smem_u32(const void* p) {
    uint32_t a;
    asm("{ .reg .u64 t; cvta.to.shared.u64 t, %1; cvt.u32.u64 %0, t; }" : "=r"(a) : "l"(p));
    return a;
}
__device__ __forceinline__ void ldsm4(uint32_t& r0, uint32_t& r1, uint32_t& r2,
                                      uint32_t& r3, uint32_t addr) {
    asm volatile("ldmatrix.sync.aligned.m8n8.x4.shared.b16 {%0,%1,%2,%3}, [%4];"
                 : "=r"(r0), "=r"(r1), "=r"(r2), "=r"(r3) : "r"(addr));
}
__device__ __forceinline__ void mma_bf16(float* d, const uint32_t* a,
                                         uint32_t b0, uint32_t b1) {
    asm volatile(
        "mma.sync.aligned.m16n8k16.row.col.f32.bf16.bf16.f32 "
        "{%0,%1,%2,%3}, {%4,%5,%6,%7}, {%8,%9}, {%0,%1,%2,%3};"
        : "+f"(d[0]), "+f"(d[1]), "+f"(d[2]), "+f"(d[3])
        : "r"(a[0]), "r"(a[1]), "r"(a[2]), "r"(a[3]), "r"(b0), "r"(b1));
}

// zero h ping-pong buffers (pads must be 0) + counters
__global__ void init_kernel() {
    size_t i = (size_t)blockIdx.x * blockDim.x + threadIdx.x;
    size_t n = (size_t)2 * 2 * S_TOT * HPAD / 2;   // uint count
    if (i < n) { ((uint32_t*)g_hbh)[i] = 0u; ((uint32_t*)g_hbl)[i] = 0u; }
    if (i < 40) ((int*)g_ctr)[i] = 0;
}

__global__ void gather_kernel(const int* __restrict__ tok, const int* __restrict__ p1,
                              const int* __restrict__ p2, const float* __restrict__ emb,
                              const float* __restrict__ pemb) {
    int idx = blockIdx.x * blockDim.x + threadIdx.x;
    if (idx >= S_TOT * T_LEN * IND) return;
    int st = idx / IND, c = idx - st * IND;
    float v;
    if (c < 50)      v = emb[(size_t)tok[st] * 50 + c];
    else if (c < 55) v = pemb[(size_t)p1[st] * 5 + (c - 50)];
    else             v = pemb[(size_t)p2[st] * 5 + (c - 55)];
    g_x[idx] = v;
}

// xp = x @ W_ih^T + b_ih (FFMA2, unchanged from best)
__global__ void __launch_bounds__(320) xp_gemm_kernel(
    const float* __restrict__ Wf, const float* __restrict__ Wb,
    const float* __restrict__ bf, const float* __restrict__ bb)
{
    const int dir = blockIdx.z;
    const float* W    = dir ? Wb : Wf;
    const float* bias = dir ? bb : bf;
    float* xp = dir ? g_xp_b : g_xp_f;
    const int m0 = blockIdx.x * 256, c0 = blockIdx.y * 100;
    __shared__ float As[2][20][256];
    __shared__ float Bs[2][20][104];
    const int tid = threadIdx.x, tx = tid % 10, ty = tid / 10;
    ULL acc[8][5];
    #pragma unroll
    for (int r = 0; r < 8; r++)
        #pragma unroll
        for (int p = 0; p < 5; p++) acc[r][p] = 0ULL;
    #pragma unroll
    for (int i = 0; i < 4; i++) {
        int task = tid + 320 * i, row = task & 255, kq = task >> 8;
        float4 v = *(const float4*)&g_x[(size_t)(m0 + row) * IND + 4 * kq];
        As[0][4*kq][row] = v.x; As[0][4*kq+1][row] = v.y;
        As[0][4*kq+2][row] = v.z; As[0][4*kq+3][row] = v.w;
    }
    #pragma unroll
    for (int i = 0; i < 2; i++) {
        int task = tid + 320 * i;
        if (task < 500) {
            int col = task % 100, kq = task / 100;
            float4 v = *(const float4*)&W[(size_t)(c0 + col) * IND + 4 * kq];
            Bs[0][4*kq][col] = v.x; Bs[0][4*kq+1][col] = v.y;
            Bs[0][4*kq+2][col] = v.z; Bs[0][4*kq+3][col] = v.w;
        }
    }
    __syncthreads();
    for (int c = 0; c < 3; c++) {
        const int buf = c & 1;
        const bool more = (c < 2);
        float4 sta[4], stb[2];
        if (more) {
            int k0n = (c + 1) * 20;
            #pragma unroll
            for (int i = 0; i < 4; i++) {
                int task = tid + 320 * i, row = task & 255, kq = task >> 8;
                sta[i] = *(const float4*)&g_x[(size_t)(m0 + row) * IND + k0n + 4 * kq];
            }
            #pragma unroll
            for (int i = 0; i < 2; i++) {
                int task = tid + 320 * i;
                if (task < 500) {
                    int col = task % 100, kq = task / 100;
                    stb[i] = *(const float4*)&W[(size_t)(c0 + col) * IND + k0n + 4 * kq];
                }
            }
        }
        #pragma unroll 5
        for (int k = 0; k < 20; k++) {
            float4 a0 = *(const float4*)&As[buf][k][8 * ty];
            float4 a1 = *(const float4*)&As[buf][k][8 * ty + 4];
            ULL ap[8];
            ap[0]=pack2(a0.x,a0.x); ap[1]=pack2(a0.y,a0.y); ap[2]=pack2(a0.z,a0.z); ap[3]=pack2(a0.w,a0.w);
            ap[4]=pack2(a1.x,a1.x); ap[5]=pack2(a1.y,a1.y); ap[6]=pack2(a1.z,a1.z); ap[7]=pack2(a1.w,a1.w);
            ULL bv[5];
            #pragma unroll
            for (int p = 0; p < 5; p++) bv[p] = *(const ULL*)&Bs[buf][k][10 * tx + 2 * p];
            #pragma unroll
            for (int r = 0; r < 8; r++)
                #pragma unroll
                for (int p = 0; p < 5; p++) ffma2(acc[r][p], ap[r], bv[p]);
        }
        __syncthreads();
        if (more) {
            #pragma unroll
            for (int i = 0; i < 4; i++) {
                int task = tid + 320 * i, row = task & 255, kq = task >> 8;
                As[buf^1][4*kq][row] = sta[i].x; As[buf^1][4*kq+1][row] = sta[i].y;
                As[buf^1][4*kq+2][row] = sta[i].z; As[buf^1][4*kq+3][row] = sta[i].w;
            }
            #pragma unroll
            for (int i = 0; i < 2; i++) {
                int task = tid + 320 * i;
                if (task < 500) {
                    int col = task % 100, kq = task / 100;
                    Bs[buf^1][4*kq][col] = stb[i].x; Bs[buf^1][4*kq+1][col] = stb[i].y;
                    Bs[buf^1][4*kq+2][col] = stb[i].z; Bs[buf^1][4*kq+3][col] = stb[i].w;
                }
            }
            __syncthreads();
        }
    }
    #pragma unroll
    for (int r = 0; r < 8; r++) {
        int m = m0 + 8 * ty + r, s = m / T_LEN, t = m - s * T_LEN;
        size_t base = ((size_t)t * S_TOT + s) * G3 + c0 + 10 * tx;
        #pragma unroll
        for (int p = 0; p < 5; p++) {
            float lo, hi;
            unpack2(acc[r][p], lo, hi);
            int cc = c0 + 10 * tx + 2 * p;
            *(float2*)&xp[base + 2 * p] = make_float2(lo + bias[cc], hi + bias[cc + 1]);
        }
    }
}

// ---------------- warp-MMA persistent GRU (HMMA bf16 hi/lo split) -----------
// grid (7,20,2), 128 thr, 2 CTA/SM (one wave). CTA tile 128 rows x 96 gatecols.
// W hi/lo in smem (n-major, k stride 216). h staged per 16-K chunk (dbl buf).
#define KW   216
#define SBIAS 0
#define ASTG  512
#define ABUF  6144              // 128*48 bytes
#define ALOFF (ASTG + 2*ABUF)   // 12800
#define WHI   25088
#define WBYT  (96 * KW * 2)     // 41472
#define WLO   (WHI + WBYT)
#define GRU_SMEM (WLO + WBYT)   // 108032

__global__ void __launch_bounds__(128, 2) gru_mma_kernel(
    const float* __restrict__ Whh_f, const float* __restrict__ Whh_b,
    const float* __restrict__ bhh_f, const float* __restrict__ bhh_b)
{
    extern __shared__ char smem[];
    float* bias_sm = (float*)(smem + SBIAS);
    const uint32_t smb = smem_u32(smem);
    const int jb = blockIdx.x, rowt = blockIdx.y, dir = blockIdx.z;
    const int tid = threadIdx.x, wid = tid >> 5, lane = tid & 31;
    const int row0 = rowt * 128, j0 = jb * 32;
    const int myrow = row0 + tid;

    const float* W   = dir ? Whh_b : Whh_f;
    const float* bhh = dir ? bhh_b : bhh_f;
    const float* xpb = dir ? g_xp_b : g_xp_f;
    float*      seqb = dir ? g_seq_b : g_seq_f;

    // W slice -> smem bf16 hi/lo, n-major [96][216]
    for (int e = tid; e < 96 * KW; e += 128) {
        int n = e / KW, k = e - n * KW;
        int g = n >> 5, jj = n & 31, col = j0 + jj;
        float w = (col < HIDN && k < HIDN) ? W[((size_t)g * HIDN + col) * HIDN + k] : 0.f;
        __nv_bfloat16 hi = __float2bfloat16(w);
        __nv_bfloat16 lo = __float2bfloat16(w - __bfloat162float(hi));
        *(__nv_bfloat16*)(smem + WHI + (size_t)e * 2) = hi;
        *(__nv_bfloat16*)(smem + WLO + (size_t)e * 2) = lo;
    }
    for (int n = tid; n < 96; n += 128) {
        int g = n >> 5, jj = n & 31, col = j0 + jj;
        bias_sm[n] = (col < HIDN) ? bhh[g * HIDN + col] : 0.f;
    }
    __syncthreads();

    // ldmatrix lane addresses (constant parts)
    const int a_r = (lane & 7) + ((lane >> 3) & 1) * 8;          // row in m-tile
    const int a_c2 = ((lane >> 4) & 1) * 16;                     // byte offset for k-half
    const int b_n = ((lane >> 4) ? 8 : 0) + (lane & 7);          // row in n-group
    const int b_k2 = ((lane >> 3) & 1) * 16;                     // byte offset
    int* ctr = &g_ctr[dir][rowt];

    for (int s = 0; s < T_LEN; s++) {
        const int t = dir ? (T_LEN - 1 - s) : s;
        const int tprev = dir ? (t + 1) : (t - 1);
        const float* xp_t  = xpb + (size_t)t * S_TOT * G3;
        float*       seq_t = seqb + (size_t)t * S_TOT * HIDN;
        const float* seqp  = seqb + (size_t)tprev * S_TOT * HIDN;
        const int par = s & 1;
        const bool mm = (s > 0);

        float acc[2][12][4];
        #pragma unroll
        for (int m = 0; m < 2; m++)
            #pragma unroll
            for (int n = 0; n < 12; n++)
                #pragma unroll
                for (int e = 0; e < 4; e++) acc[m][n][e] = 0.f;

        if (mm) {
            const __nv_bfloat16* hh = g_hbh[dir][par ^ 1] + (size_t)myrow * HPAD;
            const __nv_bfloat16* hl = g_hbl[dir][par ^ 1] + (size_t)myrow * HPAD;
            // stage chunk 0
            {
                uint4 h0 = *(const uint4*)&hh[0], h1 = *(const uint4*)&hh[8];
                uint4 l0 = *(const uint4*)&hl[0], l1 = *(const uint4*)&hl[8];
                char* ah = smem + ASTG + tid * 48;
                char* al = smem + ALOFF + tid * 48;
                *(uint4*)ah = h0; *(uint4*)(ah + 16) = h1;
                *(uint4*)al = l0; *(uint4*)(al + 16) = l1;
            }
            __syncthreads();

            for (int kc = 0; kc < 13; kc++) {
                const int buf = kc & 1;
                const bool more = (kc < 12);
                uint4 nh0, nh1, nl0, nl1;
                if (more) {
                    int k0 = (kc + 1) * 16;
                    nh0 = *(const uint4*)&hh[k0]; nh1 = *(const uint4*)&hh[k0 + 8];
                    nl0 = *(const uint4*)&hl[k0]; nl1 = *(const uint4*)&hl[k0 + 8];
                }
                // A fragments for this warp (2 m-tiles, hi+lo)
                uint32_t AH[2][4], AL[2][4];
                #pragma unroll
                for (int mt = 0; mt < 2; mt++) {
                    uint32_t ra = smb + ASTG + buf * ABUF
                                + (wid * 32 + mt * 16 + a_r) * 48 + a_c2;
                    ldsm4(AH[mt][0], AH[mt][1], AH[mt][2], AH[mt][3], ra);
                    uint32_t rl = ra + (ALOFF - ASTG);
                    ldsm4(AL[mt][0], AL[mt][1], AL[mt][2], AL[mt][3], rl);
                }
                #pragma unroll
                for (int ng = 0; ng < 6; ng++) {
                    uint32_t bh0, bh1, bh2, bh3, bl0, bl1, bl2, bl3;
                    uint32_t rb = smb + WHI + (ng * 16 + b_n) * (KW * 2) + kc * 32 + b_k2;
                    ldsm4(bh0, bh1, bh2, bh3, rb);
                    ldsm4(bl0, bl1, bl2, bl3, rb + WBYT);
                    #pragma unroll
                    for (int mt = 0; mt < 2; mt++) {
                        mma_bf16(acc[mt][2*ng],   AH[mt], bh0, bh1);
                        mma_bf16(acc[mt][2*ng],   AL[mt], bh0, bh1);
                        mma_bf16(acc[mt][2*ng],   AH[mt], bl0, bl1);
                        mma_bf16(acc[mt][2*ng+1], AH[mt], bh2, bh3);
                        mma_bf16(acc[mt][2*ng+1], AL[mt], bh2, bh3);
                        mma_bf16(acc[mt][2*ng+1], AH[mt], bl2, bl3);
                    }
                }
                __syncthreads();
                if (more) {
                    char* ah = smem + ASTG + (buf ^ 1) * ABUF + tid * 48;
                    char* al = smem + ALOFF + (buf ^ 1) * ABUF + tid * 48;
                    *(uint4*)ah = nh0; *(uint4*)(ah + 16) = nh1;
                    *(uint4*)al = nl0; *(uint4*)(al + 16) = nl1;
                    __syncthreads();
                }
            }
        }

        // fused GRU epilogue on mma fragment layout
        {
            const int rb0 = row0 + wid * 32 + (lane >> 2);
            const int cb  = (lane & 3) * 2;
            #pragma unroll
            for (int mt = 0; mt < 2; mt++) {
                #pragma unroll
                for (int q = 0; q < 4; q++) {
                    int jj = q * 8 + cb;
                    int j = j0 + jj;
                    if (j >= HIDN) continue;
                    float rbias0 = bias_sm[q * 8 + cb],      rbias1 = bias_sm[q * 8 + cb + 1];
                    float zbias0 = bias_sm[32 + q * 8 + cb], zbias1 = bias_sm[32 + q * 8 + cb + 1];
                    float nbias0 = bias_sm[64 + q * 8 + cb], nbias1 = bias_sm[64 + q * 8 + cb + 1];
                    #pragma unroll
                    for (int hf = 0; hf < 2; hf++) {
                        int row = rb0 + mt * 16 + hf * 8;
                        int e0 = hf * 2, e1 = hf * 2 + 1;
                        const float* xr = xp_t + (size_t)row * G3;
                        float2 xrv = *(const float2*)&xr[j];
                        float2 xzv = *(const float2*)&xr[HIDN + j];
                        float2 xnv = *(const float2*)&xr[2 * HIDN + j];
                        float2 hpv = mm ? *(const float2*)&seqp[(size_t)row * HIDN + j]
                                        : make_float2(0.f, 0.f);
                        float gr0 = acc[mt][q][e0],     gr1 = acc[mt][q][e1];
                        float gz0 = acc[mt][q + 4][e0], gz1 = acc[mt][q + 4][e1];
                        float gn0 = acc[mt][q + 8][e0], gn1 = acc[mt][q + 8][e1];
                        float r0 = sigm(xrv.x + gr0 + rbias0);
                        float z0 = sigm(xzv.x + gz0 + zbias0);
                        float n0 = tanhf(xnv.x + r0 * (gn0 + nbias0));
                        float h0 = (1.f - z0) * n0 + z0 * hpv.x;
                        float r1 = sigm(xrv.y + gr1 + rbias1);
                        float z1 = sigm(xzv.y + gz1 + zbias1);
                        float n1 = tanhf(xnv.y + r1 * (gn1 + nbias1));
                        float h1 = (1.f - z1) * n1 + z1 * hpv.y;
                        *(float2*)&seq_t[(size_t)row * HIDN + j] = make_float2(h0, h1);
                        __nv_bfloat16 a0 = __float2bfloat16(h0), a1 = __float2bfloat16(h1);
                        __nv_bfloat162 vh; vh.x = a0; vh.y = a1;
                        __nv_bfloat162 vl;
                        vl.x = __float2bfloat16(h0 - __bfloat162float(a0));
                        vl.y = __float2bfloat16(h1 - __bfloat162float(a1));
                        *(uint32_t*)&g_hbh[dir][par][(size_t)row * HPAD + j] = *(uint32_t*)&vh;
                        *(uint32_t*)&g_hbl[dir][par][(size_t)row * HPAD + j] = *(uint32_t*)&vl;
                    }
                }
            }
        }

        __threadfence();
        __syncthreads();
        if (tid == 0) {
            atomicAdd(ctr, 1);
            int target = 7 * (s + 1);
            while (*(volatile int*)ctr < target) { }
            __threadfence();
        }
        __syncthreads();
    }
}

__global__ void __launch_bounds__(256) word_attn_kernel(const float* __restrict__ aw)
{
    extern __shared__ float tup[];
    __shared__ float sc[T_LEN];
    const int s = blockIdx.x;
    const int lane = threadIdx.x & 31, wid = threadIdx.x >> 5;
    for (int t = wid; t < T_LEN; t += 8) {
        const float* f = g_seq_f + ((size_t)t * S_TOT + s) * HIDN;
        const float* b = g_seq_b + ((size_t)t * S_TOT + s) * HIDN;
        float sum = 0.f;
        for (int d = lane; d < HIDN; d += 32) {
            float v = f[d] + b[d];
            tup[t * HIDN + d] = v;
            sum += tanhf(v) * aw[d];
        }
        #pragma unroll
        for (int o = 16; o > 0; o >>= 1) sum += __shfl_xor_sync(0xffffffffu, sum, o);
        if (lane == 0) sc[t] = sum;
    }
    __syncthreads();
    if (threadIdx.x == 0) {
        float m = sc[0];
        for (int t = 1; t < T_LEN; t++) m = fmaxf(m, sc[t]);
        float ssum = 0.f;
        for (int t = 0; t < T_LEN; t++) { float e2 = expf(sc[t] - m); sc[t] = e2; ssum += e2; }
        float inv = 1.f / ssum;
        for (int t = 0; t < T_LEN; t++) sc[t] *= inv;
    }
    __syncthreads();
    for (int d = threadIdx.x; d < HIDN; d += 256) {
        float acc = 0.f;
        #pragma unroll 7
        for (int t = 0; t < T_LEN; t++) acc += sc[t] * tup[t * HIDN + d];
        g_H[(size_t)s * HIDN + d] = acc;
    }
}

__global__ void __launch_bounds__(128) bag_kernel(
    const float* __restrict__ sen_a, const float* __restrict__ sen_r,
    const float* __restrict__ rel, const float* __restrict__ sen_d,
    const int* __restrict__ label, float* __restrict__ logits)
{
    const int b = blockIdx.x;
    __shared__ float Hs[NSEN][HIDN];
    __shared__ float ew[NSEN];
    __shared__ float Sv[HIDN];
    __shared__ float red[128];
    for (int e = threadIdx.x; e < NSEN * HIDN; e += 128)
        Hs[e / HIDN][e % HIDN] = g_H[(size_t)b * NSEN * HIDN + e];
    __syncthreads();
    const int lane = threadIdx.x & 31, wid = threadIdx.x >> 5;
    for (int n = wid; n < NSEN; n += 4) {
        float sum = 0.f;
        for (int d = lane; d < HIDN; d += 32)
            sum += Hs[n][d] * sen_a[d] * sen_r[d];
        #pragma unroll
        for (int o = 16; o > 0; o >>= 1) sum += __shfl_xor_sync(0xffffffffu, sum, o);
        if (lane == 0) ew[n] = sum;
    }
    __syncthreads();
    if (threadIdx.x == 0) {
        float m = ew[0];
        for (int n = 1; n < NSEN; n++) m = fmaxf(m, ew[n]);
        float s2 = 0.f;
        for (int n = 0; n < NSEN; n++) { float e2 = expf(ew[n] - m); ew[n] = e2; s2 += e2; }
        float inv = 1.f / s2;
        for (int n = 0; n < NSEN; n++) ew[n] *= inv;
    }
    __syncthreads();
    for (int d = threadIdx.x; d < HIDN; d += 128) {
        float acc = 0.f;
        for (int n = 0; n < NSEN; n++) acc += ew[n] * Hs[n][d];
        Sv[d] = acc;
    }
    __syncthreads();
    int lab = label[b];
    float bce = 0.f;
    if (threadIdx.x < NREL) {
        int r = threadIdx.x;
        float l = sen_d[r];
        for (int d = 0; d < HIDN; d++) l += Sv[d] * rel[(size_t)r * HIDN + d];
        logits[(size_t)b * NREL + r] = l;
        float tgt = (lab == r) ? 1.f : 0.f;
        bce = fmaxf(l, 0.f) - l * tgt + log1pf(expf(-fabsf(l)));
    }
    red[threadIdx.x] = bce;
    __syncthreads();
    for (int o = 64; o > 0; o >>= 1) {
        if (threadIdx.x < o) red[threadIdx.x] += red[threadIdx.x + o];
        __syncthreads();
    }
    if (threadIdx.x == 0) g_bagloss[b] = red[0] / (float)NREL;
}

__global__ void loss_sum_kernel(float* __restrict__ out) {
    __shared__ float red[128];
    red[threadIdx.x] = g_bagloss[threadIdx.x];
    __syncthreads();
    for (int o = 64; o > 0; o >>= 1) {
        if (threadIdx.x < o) red[threadIdx.x] += red[threadIdx.x + o];
        __syncthreads();
    }
    if (threadIdx.x == 0) out[0] = red[0];
}

extern "C" void kernel_launch(void* const* d_in, const int* in_sizes, int n_in,
                              void* d_out, int out_size)
{
    const int*   tok   = (const int*)d_in[0];
    const int*   p1    = (const int*)d_in[1];
    const int*   p2    = (const int*)d_in[2];
    const int*   lab   = (const int*)d_in[3];
    const float* emb   = (const float*)d_in[4];
    const float* pemb  = (const float*)d_in[5];
    const float* Wih_f = (const float*)d_in[6];
    const float* Whh_f = (const float*)d_in[7];
    const float* bih_f = (const float*)d_in[8];
    const float* bhh_f = (const float*)d_in[9];
    const float* Wih_b = (const float*)d_in[10];
    const float* Whh_b = (const float*)d_in[11];
    const float* bih_b = (const float*)d_in[12];
    const float* bhh_b = (const float*)d_in[13];
    const float* aw    = (const float*)d_in[14];
    const float* sen_a = (const float*)d_in[15];
    const float* sen_r = (const float*)d_in[16];
    const float* rel   = (const float*)d_in[17];
    const float* sen_d = (const float*)d_in[18];
    float* out = (float*)d_out;

    int initN = 2 * 2 * S_TOT * HPAD / 2;
    init_kernel<<<(initN + 255) / 256, 256>>>();
    gather_kernel<<<(S_TOT * T_LEN * IND + 255) / 256, 256>>>(tok, p1, p2, emb, pemb);

    dim3 g2(S_TOT * T_LEN / 256, G3 / 100, 2);
    xp_gemm_kernel<<<g2, 320>>>(Wih_f, Wih_b, bih_f, bih_b);

    cudaFuncSetAttribute(gru_mma_kernel,
                         cudaFuncAttributeMaxDynamicSharedMemorySize, GRU_SMEM);
    dim3 g3(7, 20, 2);
    gru_mma_kernel<<<g3, 128, GRU_SMEM>>>(Whh_f, Whh_b, bhh_f, bhh_b);

    static const int attn_smem = T_LEN * HIDN * (int)sizeof(float);
    cudaFuncSetAttribute(word_attn_kernel,
                         cudaFuncAttributeMaxDynamicSharedMemorySize, attn_smem);
    word_attn_kernel<<<S_TOT, 256, attn_smem>>>(aw);
    bag_kernel<<<NBAG, 128>>>(sen_a, sen_r, rel, sen_d, lab, out + 1);
    loss_sum_kernel<<<1, 128>>>(out);
}

// round 12
// speedup vs baseline: 1.4822x; 1.2147x over previous
#include <cuda_runtime.h>
#include <cuda_bf16.h>
#include <math.h>
#include <stdint.h>

#define S_TOT 2560
#define T_LEN 70
#define HIDN  200
#define G3    600
#define IND   60
#define NBAG  128
#define NSEN  20
#define NREL  100
#define HPAD  208

typedef unsigned long long ULL;

__device__ float g_x[S_TOT * T_LEN * IND];
__device__ float g_xp_f[(size_t)T_LEN * S_TOT * G3];
__device__ float g_xp_b[(size_t)T_LEN * S_TOT * G3];
__device__ float g_seq_f[(size_t)T_LEN * S_TOT * HIDN];
__device__ float g_seq_b[(size_t)T_LEN * S_TOT * HIDN];
__device__ __nv_bfloat16 g_hbh[2][2][S_TOT * HPAD];   // [dir][parity]
__device__ __nv_bfloat16 g_hbl[2][2][S_TOT * HPAD];
__device__ float g_H[S_TOT * HIDN];
__device__ float g_bagloss[NBAG];
__device__ int   g_ctr[2][20];

__device__ __forceinline__ float sigm(float x) { return 1.f / (1.f + expf(-x)); }
__device__ __forceinline__ uint32_t smem_u32(const void* p) {
    uint32_t a;
    asm("{ .reg .u64 t; cvta.to.shared.u64 t, %1; cvt.u32.u64 %0, t; }" : "=r"(a) : "l"(p));
    return a;
}
__device__ __forceinline__ void ldsm4(uint32_t& r0, uint32_t& r1, uint32_t& r2,
                                      uint32_t& r3, uint32_t addr) {
    asm volatile("ldmatrix.sync.aligned.m8n8.x4.shared.b16 {%0,%1,%2,%3}, [%4];"
                 : "=r"(r0), "=r"(r1), "=r"(r2), "=r"(r3) : "r"(addr));
}
__device__ __forceinline__ void mma_bf16(float* d, const uint32_t* a,
                                         uint32_t b0, uint32_t b1) {
    asm volatile(
        "mma.sync.aligned.m16n8k16.row.col.f32.bf16.bf16.f32 "
        "{%0,%1,%2,%3}, {%4,%5,%6,%7}, {%8,%9}, {%0,%1,%2,%3};"
        : "+f"(d[0]), "+f"(d[1]), "+f"(d[2]), "+f"(d[3])
        : "r"(a[0]), "r"(a[1]), "r"(a[2]), "r"(a[3]), "r"(b0), "r"(b1));
}
__device__ __forceinline__ uint32_t bf16x2_hi(float x, float y) {
    __nv_bfloat162 v; v.x = __float2bfloat16(x); v.y = __float2bfloat16(y);
    return *(uint32_t*)&v;
}
__device__ __forceinline__ uint32_t bf16x2_lo(float x, float y) {
    __nv_bfloat16 hx = __float2bfloat16(x), hy = __float2bfloat16(y);
    __nv_bfloat162 v;
    v.x = __float2bfloat16(x - __bfloat162float(hx));
    v.y = __float2bfloat16(y - __bfloat162float(hy));
    return *(uint32_t*)&v;
}

// zero h ping-pong buffers (pads must be 0) + counters
__global__ void init_kernel() {
    size_t i = (size_t)blockIdx.x * blockDim.x + threadIdx.x;
    size_t n = (size_t)2 * 2 * S_TOT * HPAD / 2;   // uint count
    if (i < n) { ((uint32_t*)g_hbh)[i] = 0u; ((uint32_t*)g_hbl)[i] = 0u; }
    if (i < 40) ((int*)g_ctr)[i] = 0;
}

__global__ void gather_kernel(const int* __restrict__ tok, const int* __restrict__ p1,
                              const int* __restrict__ p2, const float* __restrict__ emb,
                              const float* __restrict__ pemb) {
    int idx = blockIdx.x * blockDim.x + threadIdx.x;
    if (idx >= S_TOT * T_LEN * IND) return;
    int st = idx / IND, c = idx - st * IND;
    float v;
    if (c < 50)      v = emb[(size_t)tok[st] * 50 + c];
    else if (c < 55) v = pemb[(size_t)p1[st] * 5 + (c - 50)];
    else             v = pemb[(size_t)p2[st] * 5 + (c - 55)];
    g_x[idx] = v;
}

// ---------------- xp = x @ W_ih^T + b_ih via warp-MMA (bf16 hi/lo) ----------
// grid (1400, 7, 2), 128 thr. CTA tile 128 rows x 96 cols, K=64 (60 padded).
#define XKA   144                 // bytes per k-row (72 bf16 slots, 64 used)
#define XBIAS 0
#define XAHI  512
#define XABYT (128 * XKA)         // 18432
#define XALO  (XAHI + XABYT)
#define XWHI  (XALO + XABYT)      // 37376
#define XWBYT (96 * XKA)          // 13824
#define XWLO  (XWHI + XWBYT)
#define XP_SMEM (XWLO + XWBYT)    // 65024

__global__ void __launch_bounds__(128) xp_mma_kernel(
    const float* __restrict__ Wf, const float* __restrict__ Wb,
    const float* __restrict__ bf, const float* __restrict__ bb)
{
    extern __shared__ char smem[];
    float* bias_sm = (float*)(smem + XBIAS);
    const uint32_t smb = smem_u32(smem);
    const int mb = blockIdx.x, jbb = blockIdx.y, dir = blockIdx.z;
    const float* W    = dir ? Wb : Wf;
    const float* bias = dir ? bb : bf;
    float* xp = dir ? g_xp_b : g_xp_f;
    const int m0 = mb * 128, c0 = jbb * 96;
    const int tid = threadIdx.x, wid = tid >> 5, lane = tid & 31;

    // stage A: thread = row; 60 floats -> bf16 hi/lo, pad k 60..63 with 0
    {
        const float* xr = g_x + (size_t)(m0 + tid) * IND;
        uint32_t* ah = (uint32_t*)(smem + XAHI + tid * XKA);
        uint32_t* al = (uint32_t*)(smem + XALO + tid * XKA);
        #pragma unroll
        for (int i = 0; i < 30; i++) {
            float2 v = *(const float2*)&xr[2 * i];
            ah[i] = bf16x2_hi(v.x, v.y);
            al[i] = bf16x2_lo(v.x, v.y);
        }
        ah[30] = 0u; ah[31] = 0u; al[30] = 0u; al[31] = 0u;
    }
    // stage W: 96 n-rows x 64 k (hi/lo)
    for (int e = tid; e < 96 * 32; e += 128) {
        int n = e >> 5, i = e & 31;
        int col = c0 + n, k = 2 * i;
        float w0 = 0.f, w1 = 0.f;
        if (col < G3) {
            if (k < IND)     w0 = W[(size_t)col * IND + k];
            if (k + 1 < IND) w1 = W[(size_t)col * IND + k + 1];
        }
        ((uint32_t*)(smem + XWHI + n * XKA))[i] = bf16x2_hi(w0, w1);
        ((uint32_t*)(smem + XWLO + n * XKA))[i] = bf16x2_lo(w0, w1);
    }
    for (int n = tid; n < 96; n += 128)
        bias_sm[n] = (c0 + n < G3) ? bias[c0 + n] : 0.f;
    __syncthreads();

    const int a_r  = (lane & 7) + ((lane >> 3) & 1) * 8;
    const int a_c2 = ((lane >> 4) & 1) * 16;
    const int b_n  = ((lane >> 4) ? 8 : 0) + (lane & 7);
    const int b_k2 = ((lane >> 3) & 1) * 16;

    float acc[2][12][4];
    #pragma unroll
    for (int m = 0; m < 2; m++)
        #pragma unroll
        for (int n = 0; n < 12; n++)
            #pragma unroll
            for (int e = 0; e < 4; e++) acc[m][n][e] = 0.f;

    #pragma unroll
    for (int kc = 0; kc < 4; kc++) {
        uint32_t AH[2][4], AL[2][4];
        #pragma unroll
        for (int mt = 0; mt < 2; mt++) {
            uint32_t ra = smb + XAHI + (wid * 32 + mt * 16 + a_r) * XKA + kc * 32 + a_c2;
            ldsm4(AH[mt][0], AH[mt][1], AH[mt][2], AH[mt][3], ra);
            ldsm4(AL[mt][0], AL[mt][1], AL[mt][2], AL[mt][3], ra + XABYT);
        }
        #pragma unroll
        for (int ng = 0; ng < 6; ng++) {
            uint32_t bh0, bh1, bh2, bh3, bl0, bl1, bl2, bl3;
            uint32_t rb = smb + XWHI + (ng * 16 + b_n) * XKA + kc * 32 + b_k2;
            ldsm4(bh0, bh1, bh2, bh3, rb);
            ldsm4(bl0, bl1, bl2, bl3, rb + XWBYT);
            #pragma unroll
            for (int mt = 0; mt < 2; mt++) {
                mma_bf16(acc[mt][2*ng],   AH[mt], bh0, bh1);
                mma_bf16(acc[mt][2*ng],   AL[mt], bh0, bh1);
                mma_bf16(acc[mt][2*ng],   AH[mt], bl0, bl1);
                mma_bf16(acc[mt][2*ng+1], AH[mt], bh2, bh3);
                mma_bf16(acc[mt][2*ng+1], AL[mt], bh2, bh3);
                mma_bf16(acc[mt][2*ng+1], AH[mt], bl2, bl3);
            }
        }
    }

    // epilogue: fragment (row = lane/4 + {0,8} + 16*mt, colpair = (lane%4)*2)
    const int r_l = lane >> 2, cb = (lane & 3) * 2;
    #pragma unroll
    for (int mt = 0; mt < 2; mt++) {
        #pragma unroll
        for (int q = 0; q < 12; q++) {
            int c = c0 + q * 8 + cb;
            if (c >= G3) continue;
            float b0 = bias_sm[q * 8 + cb], b1 = bias_sm[q * 8 + cb + 1];
            #pragma unroll
            for (int hf = 0; hf < 2; hf++) {
                int m = m0 + wid * 32 + mt * 16 + hf * 8 + r_l;
                int s = m / T_LEN, t = m - s * T_LEN;
                int e0 = hf * 2;
                float2 out = make_float2(acc[mt][q][e0] + b0, acc[mt][q][e0 + 1] + b1);
                *(float2*)&xp[((size_t)t * S_TOT + s) * G3 + c] = out;
            }
        }
    }
}

// ---------------- warp-MMA persistent GRU (HMMA bf16 hi/lo split) -----------
// grid (7,20,2), 128 thr, 2 CTA/SM (one wave). CTA tile 128 rows x 96 gatecols.
// W hi/lo in smem (n-major, k stride 216). h staged per 16-K chunk (dbl buf,
// single sync per chunk).
#define KW   216
#define SBIAS 0
#define ASTG  512
#define ABUF  6144              // 128*48 bytes
#define ALOFF (ASTG + 2*ABUF)   // 12800
#define WHI   25088
#define WBYT  (96 * KW * 2)     // 41472
#define WLO   (WHI + WBYT)
#define GRU_SMEM (WLO + WBYT)   // 108032

__global__ void __launch_bounds__(128, 2) gru_mma_kernel(
    const float* __restrict__ Whh_f, const float* __restrict__ Whh_b,
    const float* __restrict__ bhh_f, const float* __restrict__ bhh_b)
{
    extern __shared__ char smem[];
    float* bias_sm = (float*)(smem + SBIAS);
    const uint32_t smb = smem_u32(smem);
    const int jb = blockIdx.x, rowt = blockIdx.y, dir = blockIdx.z;
    const int tid = threadIdx.x, wid = tid >> 5, lane = tid & 31;
    const int row0 = rowt * 128, j0 = jb * 32;
    const int myrow = row0 + tid;

    const float* W   = dir ? Whh_b : Whh_f;
    const float* bhh = dir ? bhh_b : bhh_f;
    const float* xpb = dir ? g_xp_b : g_xp_f;
    float*      seqb = dir ? g_seq_b : g_seq_f;

    // W slice -> smem bf16 hi/lo, n-major [96][216]
    for (int e = tid; e < 96 * KW; e += 128) {
        int n = e / KW, k = e - n * KW;
        int g = n >> 5, jj = n & 31, col = j0 + jj;
        float w = (col < HIDN && k < HIDN) ? W[((size_t)g * HIDN + col) * HIDN + k] : 0.f;
        __nv_bfloat16 hi = __float2bfloat16(w);
        __nv_bfloat16 lo = __float2bfloat16(w - __bfloat162float(hi));
        *(__nv_bfloat16*)(smem + WHI + (size_t)e * 2) = hi;
        *(__nv_bfloat16*)(smem + WLO + (size_t)e * 2) = lo;
    }
    for (int n = tid; n < 96; n += 128) {
        int g = n >> 5, jj = n & 31, col = j0 + jj;
        bias_sm[n] = (col < HIDN) ? bhh[g * HIDN + col] : 0.f;
    }
    __syncthreads();

    const int a_r  = (lane & 7) + ((lane >> 3) & 1) * 8;
    const int a_c2 = ((lane >> 4) & 1) * 16;
    const int b_n  = ((lane >> 4) ? 8 : 0) + (lane & 7);
    const int b_k2 = ((lane >> 3) & 1) * 16;
    int* ctr = &g_ctr[dir][rowt];

    for (int s = 0; s < T_LEN; s++) {
        const int t = dir ? (T_LEN - 1 - s) : s;
        const int tprev = dir ? (t + 1) : (t - 1);
        const float* xp_t  = xpb + (size_t)t * S_TOT * G3;
        float*       seq_t = seqb + (size_t)t * S_TOT * HIDN;
        const float* seqp  = seqb + (size_t)tprev * S_TOT * HIDN;
        const int par = s & 1;
        const bool mm = (s > 0);

        float acc[2][12][4];
        #pragma unroll
        for (int m = 0; m < 2; m++)
            #pragma unroll
            for (int n = 0; n < 12; n++)
                #pragma unroll
                for (int e = 0; e < 4; e++) acc[m][n][e] = 0.f;

        if (mm) {
            const __nv_bfloat16* hh = g_hbh[dir][par ^ 1] + (size_t)myrow * HPAD;
            const __nv_bfloat16* hl = g_hbl[dir][par ^ 1] + (size_t)myrow * HPAD;
            // stage chunk 0
            {
                uint4 h0 = *(const uint4*)&hh[0], h1 = *(const uint4*)&hh[8];
                uint4 l0 = *(const uint4*)&hl[0], l1 = *(const uint4*)&hl[8];
                char* ah = smem + ASTG + tid * 48;
                char* al = smem + ALOFF + tid * 48;
                *(uint4*)ah = h0; *(uint4*)(ah + 16) = h1;
                *(uint4*)al = l0; *(uint4*)(al + 16) = l1;
            }
            __syncthreads();

            for (int kc = 0; kc < 13; kc++) {
                const int buf = kc & 1;
                const bool more = (kc < 12);
                uint4 nh0, nh1, nl0, nl1;
                if (more) {
                    int k0 = (kc + 1) * 16;
                    nh0 = *(const uint4*)&hh[k0]; nh1 = *(const uint4*)&hh[k0 + 8];
                    nl0 = *(const uint4*)&hl[k0]; nl1 = *(const uint4*)&hl[k0 + 8];
                }
                // A fragments for this warp (2 m-tiles, hi+lo)
                uint32_t AH[2][4], AL[2][4];
                #pragma unroll
                for (int mt = 0; mt < 2; mt++) {
                    uint32_t ra = smb + ASTG + buf * ABUF
                                + (wid * 32 + mt * 16 + a_r) * 48 + a_c2;
                    ldsm4(AH[mt][0], AH[mt][1], AH[mt][2], AH[mt][3], ra);
                    uint32_t rl = ra + (ALOFF - ASTG);
                    ldsm4(AL[mt][0], AL[mt][1], AL[mt][2], AL[mt][3], rl);
                }
                #pragma unroll
                for (int ng = 0; ng < 6; ng++) {
                    uint32_t bh0, bh1, bh2, bh3, bl0, bl1, bl2, bl3;
                    uint32_t rb = smb + WHI + (ng * 16 + b_n) * (KW * 2) + kc * 32 + b_k2;
                    ldsm4(bh0, bh1, bh2, bh3, rb);
                    ldsm4(bl0, bl1, bl2, bl3, rb + WBYT);
                    #pragma unroll
                    for (int mt = 0; mt < 2; mt++) {
                        mma_bf16(acc[mt][2*ng],   AH[mt], bh0, bh1);
                        mma_bf16(acc[mt][2*ng],   AL[mt], bh0, bh1);
                        mma_bf16(acc[mt][2*ng],   AH[mt], bl0, bl1);
                        mma_bf16(acc[mt][2*ng+1], AH[mt], bh2, bh3);
                        mma_bf16(acc[mt][2*ng+1], AL[mt], bh2, bh3);
                        mma_bf16(acc[mt][2*ng+1], AH[mt], bl2, bl3);
                    }
                }
                // single sync per chunk: stores target buf^1, whose last readers
                // were all released by the sync at the end of the previous chunk.
                if (more) {
                    char* ah = smem + ASTG + (buf ^ 1) * ABUF + tid * 48;
                    char* al = smem + ALOFF + (buf ^ 1) * ABUF + tid * 48;
                    *(uint4*)ah = nh0; *(uint4*)(ah + 16) = nh1;
                    *(uint4*)al = nl0; *(uint4*)(al + 16) = nl1;
                }
                __syncthreads();
            }
        }

        // fused GRU epilogue on mma fragment layout
        {
            const int rb0 = row0 + wid * 32 + (lane >> 2);
            const int cb  = (lane & 3) * 2;
            #pragma unroll
            for (int mt = 0; mt < 2; mt++) {
                #pragma unroll
                for (int q = 0; q < 4; q++) {
                    int jj = q * 8 + cb;
                    int j = j0 + jj;
                    if (j >= HIDN) continue;
                    float rbias0 = bias_sm[q * 8 + cb],      rbias1 = bias_sm[q * 8 + cb + 1];
                    float zbias0 = bias_sm[32 + q * 8 + cb], zbias1 = bias_sm[32 + q * 8 + cb + 1];
                    float nbias0 = bias_sm[64 + q * 8 + cb], nbias1 = bias_sm[64 + q * 8 + cb + 1];
                    #pragma unroll
                    for (int hf = 0; hf < 2; hf++) {
                        int row = rb0 + mt * 16 + hf * 8;
                        int e0 = hf * 2, e1 = hf * 2 + 1;
                        const float* xr = xp_t + (size_t)row * G3;
                        float2 xrv = *(const float2*)&xr[j];
                        float2 xzv = *(const float2*)&xr[HIDN + j];
                        float2 xnv = *(const float2*)&xr[2 * HIDN + j];
                        float2 hpv = mm ? *(const float2*)&seqp[(size_t)row * HIDN + j]
                                        : make_float2(0.f, 0.f);
                        float gr0 = acc[mt][q][e0],     gr1 = acc[mt][q][e1];
                        float gz0 = acc[mt][q + 4][e0], gz1 = acc[mt][q + 4][e1];
                        float gn0 = acc[mt][q + 8][e0], gn1 = acc[mt][q + 8][e1];
                        float r0 = sigm(xrv.x + gr0 + rbias0);
                        float z0 = sigm(xzv.x + gz0 + zbias0);
                        float n0 = tanhf(xnv.x + r0 * (gn0 + nbias0));
                        float h0 = (1.f - z0) * n0 + z0 * hpv.x;
                        float r1 = sigm(xrv.y + gr1 + rbias1);
                        float z1 = sigm(xzv.y + gz1 + zbias1);
                        float n1 = tanhf(xnv.y + r1 * (gn1 + nbias1));
                        float h1 = (1.f - z1) * n1 + z1 * hpv.y;
                        *(float2*)&seq_t[(size_t)row * HIDN + j] = make_float2(h0, h1);
                        *(uint32_t*)&g_hbh[dir][par][(size_t)row * HPAD + j] = bf16x2_hi(h0, h1);
                        *(uint32_t*)&g_hbl[dir][par][(size_t)row * HPAD + j] = bf16x2_lo(h0, h1);
                    }
                }
            }
        }

        __threadfence();
        __syncthreads();
        if (tid == 0) {
            atomicAdd(ctr, 1);
            int target = 7 * (s + 1);
            while (*(volatile int*)ctr < target) { }
            __threadfence();
        }
        __syncthreads();
    }
}

__global__ void __launch_bounds__(256) word_attn_kernel(const float* __restrict__ aw)
{
    extern __shared__ float tup[];
    __shared__ float sc[T_LEN];
    const int s = blockIdx.x;
    const int lane = threadIdx.x & 31, wid = threadIdx.x >> 5;
    for (int t = wid; t < T_LEN; t += 8) {
        const float* f = g_seq_f + ((size_t)t * S_TOT + s) * HIDN;
        const float* b = g_seq_b + ((size_t)t * S_TOT + s) * HIDN;
        float sum = 0.f;
        for (int d = lane; d < HIDN; d += 32) {
            float v = f[d] + b[d];
            tup[t * HIDN + d] = v;
            sum += tanhf(v) * aw[d];
        }
        #pragma unroll
        for (int o = 16; o > 0; o >>= 1) sum += __shfl_xor_sync(0xffffffffu, sum, o);
        if (lane == 0) sc[t] = sum;
    }
    __syncthreads();
    if (threadIdx.x == 0) {
        float m = sc[0];
        for (int t = 1; t < T_LEN; t++) m = fmaxf(m, sc[t]);
        float ssum = 0.f;
        for (int t = 0; t < T_LEN; t++) { float e2 = expf(sc[t] - m); sc[t] = e2; ssum += e2; }
        float inv = 1.f / ssum;
        for (int t = 0; t < T_LEN; t++) sc[t] *= inv;
    }
    __syncthreads();
    for (int d = threadIdx.x; d < HIDN; d += 256) {
        float acc = 0.f;
        #pragma unroll 7
        for (int t = 0; t < T_LEN; t++) acc += sc[t] * tup[t * HIDN + d];
        g_H[(size_t)s * HIDN + d] = acc;
    }
}

__global__ void __launch_bounds__(128) bag_kernel(
    const float* __restrict__ sen_a, const float* __restrict__ sen_r,
    const float* __restrict__ rel, const float* __restrict__ sen_d,
    const int* __restrict__ label, float* __restrict__ logits)
{
    const int b = blockIdx.x;
    __shared__ float Hs[NSEN][HIDN];
    __shared__ float ew[NSEN];
    __shared__ float Sv[HIDN];
    __shared__ float red[128];
    for (int e = threadIdx.x; e < NSEN * HIDN; e += 128)
        Hs[e / HIDN][e % HIDN] = g_H[(size_t)b * NSEN * HIDN + e];
    __syncthreads();
    const int lane = threadIdx.x & 31, wid = threadIdx.x >> 5;
    for (int n = wid; n < NSEN; n += 4) {
        float sum = 0.f;
        for (int d = lane; d < HIDN; d += 32)
            sum += Hs[n][d] * sen_a[d] * sen_r[d];
        #pragma unroll
        for (int o = 16; o > 0; o >>= 1) sum += __shfl_xor_sync(0xffffffffu, sum, o);
        if (lane == 0) ew[n] = sum;
    }
    __syncthreads();
    if (threadIdx.x == 0) {
        float m = ew[0];
        for (int n = 1; n < NSEN; n++) m = fmaxf(m, ew[n]);
        float s2 = 0.f;
        for (int n = 0; n < NSEN; n++) { float e2 = expf(ew[n] - m); ew[n] = e2; s2 += e2; }
        float inv = 1.f / s2;
        for (int n = 0; n < NSEN; n++) ew[n] *= inv;
    }
    __syncthreads();
    for (int d = threadIdx.x; d < HIDN; d += 128) {
        float acc = 0.f;
        for (int n = 0; n < NSEN; n++) acc += ew[n] * Hs[n][d];
        Sv[d] = acc;
    }
    __syncthreads();
    int lab = label[b];
    float bce = 0.f;
    if (threadIdx.x < NREL) {
        int r = threadIdx.x;
        float l = sen_d[r];
        for (int d = 0; d < HIDN; d++) l += Sv[d] * rel[(size_t)r * HIDN + d];
        logits[(size_t)b * NREL + r] = l;
        float tgt = (lab == r) ? 1.f : 0.f;
        bce = fmaxf(l, 0.f) - l * tgt + log1pf(expf(-fabsf(l)));
    }
    red[threadIdx.x] = bce;
    __syncthreads();
    for (int o = 64; o > 0; o >>= 1) {
        if (threadIdx.x < o) red[threadIdx.x] += red[threadIdx.x + o];
        __syncthreads();
    }
    if (threadIdx.x == 0) g_bagloss[b] = red[0] / (float)NREL;
}

__global__ void loss_sum_kernel(float* __restrict__ out) {
    __shared__ float red[128];
    red[threadIdx.x] = g_bagloss[threadIdx.x];
    __syncthreads();
    for (int o = 64; o > 0; o >>= 1) {
        if (threadIdx.x < o) red[threadIdx.x] += red[threadIdx.x + o];
        __syncthreads();
    }
    if (threadIdx.x == 0) out[0] = red[0];
}

extern "C" void kernel_launch(void* const* d_in, const int* in_sizes, int n_in,
                              void* d_out, int out_size)
{
    const int*   tok   = (const int*)d_in[0];
    const int*   p1    = (const int*)d_in[1];
    const int*   p2    = (const int*)d_in[2];
    const int*   lab   = (const int*)d_in[3];
    const float* emb   = (const float*)d_in[4];
    const float* pemb  = (const float*)d_in[5];
    const float* Wih_f = (const float*)d_in[6];
    const float* Whh_f = (const float*)d_in[7];
    const float* bih_f = (const float*)d_in[8];
    const float* bhh_f = (const float*)d_in[9];
    const float* Wih_b = (const float*)d_in[10];
    const float* Whh_b = (const float*)d_in[11];
    const float* bih_b = (const float*)d_in[12];
    const float* bhh_b = (const float*)d_in[13];
    const float* aw    = (const float*)d_in[14];
    const float* sen_a = (const float*)d_in[15];
    const float* sen_r = (const float*)d_in[16];
    const float* rel   = (const float*)d_in[17];
    const float* sen_d = (const float*)d_in[18];
    float* out = (float*)d_out;

    int initN = 2 * 2 * S_TOT * HPAD / 2;
    init_kernel<<<(initN + 255) / 256, 256>>>();
    gather_kernel<<<(S_TOT * T_LEN * IND + 255) / 256, 256>>>(tok, p1, p2, emb, pemb);

    cudaFuncSetAttribute(xp_mma_kernel,
                         cudaFuncAttributeMaxDynamicSharedMemorySize, XP_SMEM);
    dim3 g2(S_TOT * T_LEN / 128, 7, 2);
    xp_mma_kernel<<<g2, 128, XP_SMEM>>>(Wih_f, Wih_b, bih_f, bih_b);

    cudaFuncSetAttribute(gru_mma_kernel,
                         cudaFuncAttributeMaxDynamicSharedMemorySize, GRU_SMEM);
    dim3 g3(7, 20, 2);
    gru_mma_kernel<<<g3, 128, GRU_SMEM>>>(Whh_f, Whh_b, bhh_f, bhh_b);

    static const int attn_smem = T_LEN * HIDN * (int)sizeof(float);
    cudaFuncSetAttribute(word_attn_kernel,
                         cudaFuncAttributeMaxDynamicSharedMemorySize, attn_smem);
    word_attn_kernel<<<S_TOT, 256, attn_smem>>>(aw);
    bag_kernel<<<NBAG, 128>>>(sen_a, sen_r, rel, sen_d, lab, out + 1);
    loss_sum_kernel<<<1, 128>>>(out);
}

// round 13
// speedup vs baseline: 1.6935x; 1.1425x over previous
#include <cuda_runtime.h>
#include <cuda_bf16.h>
#include <math.h>
#include <stdint.h>

#define S_TOT 2560
#define T_LEN 70
#define HIDN  200
#define G3    600
#define IND   60
#define NBAG  128
#define NSEN  20
#define NREL  100
#define HPAD  208

typedef unsigned long long ULL;

__device__ float g_x[S_TOT * T_LEN * IND];
__device__ float g_xp_f[(size_t)T_LEN * S_TOT * G3];
__device__ float g_xp_b[(size_t)T_LEN * S_TOT * G3];
__device__ float g_seq_f[(size_t)T_LEN * S_TOT * HIDN];
__device__ float g_seq_b[(size_t)T_LEN * S_TOT * HIDN];
__device__ __nv_bfloat16 g_hbh[2][2][S_TOT * HPAD];   // [dir][parity]
__device__ __nv_bfloat16 g_hbl[2][2][S_TOT * HPAD];
__device__ float g_H[S_TOT * HIDN];
__device__ float g_bagloss[NBAG];
__device__ int   g_ctr[2][20];

__device__ __forceinline__ float sigm(float x) { return 1.f / (1.f + expf(-x)); }
__device__ __forceinline__ uint32_t smem_u32(const void* p) {
    uint32_t a;
    asm("{ .reg .u64 t; cvta.to.shared.u64 t, %1; cvt.u32.u64 %0, t; }" : "=r"(a) : "l"(p));
    return a;
}
__device__ __forceinline__ void ldsm4(uint32_t& r0, uint32_t& r1, uint32_t& r2,
                                      uint32_t& r3, uint32_t addr) {
    asm volatile("ldmatrix.sync.aligned.m8n8.x4.shared.b16 {%0,%1,%2,%3}, [%4];"
                 : "=r"(r0), "=r"(r1), "=r"(r2), "=r"(r3) : "r"(addr));
}
__device__ __forceinline__ void mma_bf16(float* d, const uint32_t* a,
                                         uint32_t b0, uint32_t b1) {
    asm volatile(
        "mma.sync.aligned.m16n8k16.row.col.f32.bf16.bf16.f32 "
        "{%0,%1,%2,%3}, {%4,%5,%6,%7}, {%8,%9}, {%0,%1,%2,%3};"
        : "+f"(d[0]), "+f"(d[1]), "+f"(d[2]), "+f"(d[3])
        : "r"(a[0]), "r"(a[1]), "r"(a[2]), "r"(a[3]), "r"(b0), "r"(b1));
}
__device__ __forceinline__ uint32_t bf16x2_hi(float x, float y) {
    __nv_bfloat162 v; v.x = __float2bfloat16(x); v.y = __float2bfloat16(y);
    return *(uint32_t*)&v;
}
__device__ __forceinline__ uint32_t bf16x2_lo(float x, float y) {
    __nv_bfloat16 hx = __float2bfloat16(x), hy = __float2bfloat16(y);
    __nv_bfloat162 v;
    v.x = __float2bfloat16(x - __bfloat162float(hx));
    v.y = __float2bfloat16(y - __bfloat162float(hy));
    return *(uint32_t*)&v;
}
__device__ __forceinline__ void pf_l2(const void* p) {
    asm volatile("prefetch.global.L2 [%0];" :: "l"(p));
}

__global__ void init_kernel() {
    size_t i = (size_t)blockIdx.x * blockDim.x + threadIdx.x;
    size_t n = (size_t)2 * 2 * S_TOT * HPAD / 2;
    if (i < n) { ((uint32_t*)g_hbh)[i] = 0u; ((uint32_t*)g_hbl)[i] = 0u; }
    if (i < 40) ((int*)g_ctr)[i] = 0;
}

__global__ void gather_kernel(const int* __restrict__ tok, const int* __restrict__ p1,
                              const int* __restrict__ p2, const float* __restrict__ emb,
                              const float* __restrict__ pemb) {
    int idx = blockIdx.x * blockDim.x + threadIdx.x;
    if (idx >= S_TOT * T_LEN * IND) return;
    int st = idx / IND, c = idx - st * IND;
    float v;
    if (c < 50)      v = emb[(size_t)tok[st] * 50 + c];
    else if (c < 55) v = pemb[(size_t)p1[st] * 5 + (c - 50)];
    else             v = pemb[(size_t)p2[st] * 5 + (c - 55)];
    g_x[idx] = v;
}

// ---------------- xp = x @ W_ih^T + b_ih via warp-MMA (bf16 hi/lo) ----------
#define XKA   144
#define XBIAS 0
#define XAHI  512
#define XABYT (128 * XKA)
#define XALO  (XAHI + XABYT)
#define XWHI  (XALO + XABYT)
#define XWBYT (96 * XKA)
#define XWLO  (XWHI + XWBYT)
#define XP_SMEM (XWLO + XWBYT)

__global__ void __launch_bounds__(128) xp_mma_kernel(
    const float* __restrict__ Wf, const float* __restrict__ Wb,
    const float* __restrict__ bf, const float* __restrict__ bb)
{
    extern __shared__ char smem[];
    float* bias_sm = (float*)(smem + XBIAS);
    const uint32_t smb = smem_u32(smem);
    const int mb = blockIdx.x, jbb = blockIdx.y, dir = blockIdx.z;
    const float* W    = dir ? Wb : Wf;
    const float* bias = dir ? bb : bf;
    float* xp = dir ? g_xp_b : g_xp_f;
    const int m0 = mb * 128, c0 = jbb * 96;
    const int tid = threadIdx.x, wid = tid >> 5, lane = tid & 31;

    {
        const float* xr = g_x + (size_t)(m0 + tid) * IND;
        uint32_t* ah = (uint32_t*)(smem + XAHI + tid * XKA);
        uint32_t* al = (uint32_t*)(smem + XALO + tid * XKA);
        #pragma unroll
        for (int i = 0; i < 30; i++) {
            float2 v = *(const float2*)&xr[2 * i];
            ah[i] = bf16x2_hi(v.x, v.y);
            al[i] = bf16x2_lo(v.x, v.y);
        }
        ah[30] = 0u; ah[31] = 0u; al[30] = 0u; al[31] = 0u;
    }
    for (int e = tid; e < 96 * 32; e += 128) {
        int n = e >> 5, i = e & 31;
        int col = c0 + n, k = 2 * i;
        float w0 = 0.f, w1 = 0.f;
        if (col < G3) {
            if (k < IND)     w0 = W[(size_t)col * IND + k];
            if (k + 1 < IND) w1 = W[(size_t)col * IND + k + 1];
        }
        ((uint32_t*)(smem + XWHI + n * XKA))[i] = bf16x2_hi(w0, w1);
        ((uint32_t*)(smem + XWLO + n * XKA))[i] = bf16x2_lo(w0, w1);
    }
    for (int n = tid; n < 96; n += 128)
        bias_sm[n] = (c0 + n < G3) ? bias[c0 + n] : 0.f;
    __syncthreads();

    const int a_r  = (lane & 7) + ((lane >> 3) & 1) * 8;
    const int a_c2 = ((lane >> 4) & 1) * 16;
    const int b_n  = ((lane >> 4) ? 8 : 0) + (lane & 7);
    const int b_k2 = ((lane >> 3) & 1) * 16;

    float acc[2][12][4];
    #pragma unroll
    for (int m = 0; m < 2; m++)
        #pragma unroll
        for (int n = 0; n < 12; n++)
            #pragma unroll
            for (int e = 0; e < 4; e++) acc[m][n][e] = 0.f;

    #pragma unroll
    for (int kc = 0; kc < 4; kc++) {
        uint32_t AH[2][4], AL[2][4];
        #pragma unroll
        for (int mt = 0; mt < 2; mt++) {
            uint32_t ra = smb + XAHI + (wid * 32 + mt * 16 + a_r) * XKA + kc * 32 + a_c2;
            ldsm4(AH[mt][0], AH[mt][1], AH[mt][2], AH[mt][3], ra);
            ldsm4(AL[mt][0], AL[mt][1], AL[mt][2], AL[mt][3], ra + XABYT);
        }
        #pragma unroll
        for (int ng = 0; ng < 6; ng++) {
            uint32_t bh0, bh1, bh2, bh3, bl0, bl1, bl2, bl3;
            uint32_t rb = smb + XWHI + (ng * 16 + b_n) * XKA + kc * 32 + b_k2;
            ldsm4(bh0, bh1, bh2, bh3, rb);
            ldsm4(bl0, bl1, bl2, bl3, rb + XWBYT);
            #pragma unroll
            for (int mt = 0; mt < 2; mt++) {
                mma_bf16(acc[mt][2*ng],   AH[mt], bh0, bh1);
                mma_bf16(acc[mt][2*ng],   AL[mt], bh0, bh1);
                mma_bf16(acc[mt][2*ng],   AH[mt], bl0, bl1);
                mma_bf16(acc[mt][2*ng+1], AH[mt], bh2, bh3);
                mma_bf16(acc[mt][2*ng+1], AL[mt], bh2, bh3);
                mma_bf16(acc[mt][2*ng+1], AH[mt], bl2, bl3);
            }
        }
    }

    const int r_l = lane >> 2, cb = (lane & 3) * 2;
    #pragma unroll
    for (int mt = 0; mt < 2; mt++) {
        #pragma unroll
        for (int q = 0; q < 12; q++) {
            int c = c0 + q * 8 + cb;
            if (c >= G3) continue;
            float b0 = bias_sm[q * 8 + cb], b1 = bias_sm[q * 8 + cb + 1];
            #pragma unroll
            for (int hf = 0; hf < 2; hf++) {
                int m = m0 + wid * 32 + mt * 16 + hf * 8 + r_l;
                int s = m / T_LEN, t = m - s * T_LEN;
                int e0 = hf * 2;
                float2 out = make_float2(acc[mt][q][e0] + b0, acc[mt][q][e0 + 1] + b1);
                *(float2*)&xp[((size_t)t * S_TOT + s) * G3 + c] = out;
            }
        }
    }
}

// ---------------- warp-MMA persistent GRU, 256 threads (8 warps) ------------
// grid (7,20,2), 2 CTA/SM. Each warp: 16 rows x 96 gate-cols. Staging: 2 thr/row.
#define KW   216
#define SBIAS 0
#define ASTG  512
#define ABUF  6144              // 128*48
#define ALOFF (ASTG + 2*ABUF)
#define WHI   25088
#define WBYT  (96 * KW * 2)
#define WLO   (WHI + WBYT)
#define GRU_SMEM (WLO + WBYT)   // 108032

__global__ void __launch_bounds__(256, 2) gru_mma_kernel(
    const float* __restrict__ Whh_f, const float* __restrict__ Whh_b,
    const float* __restrict__ bhh_f, const float* __restrict__ bhh_b)
{
    extern __shared__ char smem[];
    float* bias_sm = (float*)(smem + SBIAS);
    const uint32_t smb = smem_u32(smem);
    const int jb = blockIdx.x, rowt = blockIdx.y, dir = blockIdx.z;
    const int tid = threadIdx.x, wid = tid >> 5, lane = tid & 31;
    const int row0 = rowt * 128, j0 = jb * 32;
    const int srow = tid >> 1, shalf = tid & 1;      // staging: 2 threads per row

    const float* W   = dir ? Whh_b : Whh_f;
    const float* bhh = dir ? bhh_b : bhh_f;
    const float* xpb = dir ? g_xp_b : g_xp_f;
    float*      seqb = dir ? g_seq_b : g_seq_f;

    for (int e = tid; e < 96 * KW; e += 256) {
        int n = e / KW, k = e - n * KW;
        int g = n >> 5, jj = n & 31, col = j0 + jj;
        float w = (col < HIDN && k < HIDN) ? W[((size_t)g * HIDN + col) * HIDN + k] : 0.f;
        __nv_bfloat16 hi = __float2bfloat16(w);
        __nv_bfloat16 lo = __float2bfloat16(w - __bfloat162float(hi));
        *(__nv_bfloat16*)(smem + WHI + (size_t)e * 2) = hi;
        *(__nv_bfloat16*)(smem + WLO + (size_t)e * 2) = lo;
    }
    for (int n = tid; n < 96; n += 256) {
        int g = n >> 5, jj = n & 31, col = j0 + jj;
        bias_sm[n] = (col < HIDN) ? bhh[g * HIDN + col] : 0.f;
    }
    __syncthreads();

    const int a_r  = (lane & 7) + ((lane >> 3) & 1) * 8;
    const int a_c2 = ((lane >> 4) & 1) * 16;
    const int b_n  = ((lane >> 4) ? 8 : 0) + (lane & 7);
    const int b_k2 = ((lane >> 3) & 1) * 16;
    int* ctr = &g_ctr[dir][rowt];

    for (int s = 0; s < T_LEN; s++) {
        const int t = dir ? (T_LEN - 1 - s) : s;
        const int tprev = dir ? (t + 1) : (t - 1);
        const float* xp_t  = xpb + (size_t)t * S_TOT * G3;
        float*       seq_t = seqb + (size_t)t * S_TOT * HIDN;
        const float* seqp  = seqb + (size_t)tprev * S_TOT * HIDN;
        const int par = s & 1;
        const bool mm = (s > 0);

        // L2 prefetch of this step's epilogue working set (overlaps MMA loop)
        {
            int r0e = row0 + wid * 16 + (lane >> 2);
            #pragma unroll
            for (int hf = 0; hf < 2; hf++) {
                const float* pr = xp_t + (size_t)(r0e + hf * 8) * G3 + j0;
                pf_l2(pr); pf_l2(pr + HIDN); pf_l2(pr + 2 * HIDN);
                if (mm) pf_l2(seqp + (size_t)(r0e + hf * 8) * HIDN + j0);
            }
        }

        float acc[12][4];
        #pragma unroll
        for (int n = 0; n < 12; n++)
            #pragma unroll
            for (int e = 0; e < 4; e++) acc[n][e] = 0.f;

        if (mm) {
            const __nv_bfloat16* hh = g_hbh[dir][par ^ 1] + (size_t)(row0 + srow) * HPAD;
            const __nv_bfloat16* hl = g_hbl[dir][par ^ 1] + (size_t)(row0 + srow) * HPAD;
            // stage chunk 0
            {
                uint4 h0 = *(const uint4*)&hh[shalf * 8];
                uint4 l0 = *(const uint4*)&hl[shalf * 8];
                *(uint4*)(smem + ASTG + srow * 48 + shalf * 16) = h0;
                *(uint4*)(smem + ALOFF + srow * 48 + shalf * 16) = l0;
            }
            __syncthreads();

            for (int kc = 0; kc < 13; kc++) {
                const int buf = kc & 1;
                const bool more = (kc < 12);
                uint4 nh, nl;
                if (more) {
                    int k0 = (kc + 1) * 16 + shalf * 8;
                    nh = *(const uint4*)&hh[k0];
                    nl = *(const uint4*)&hl[k0];
                }
                uint32_t AH[4], AL[4];
                {
                    uint32_t ra = smb + ASTG + buf * ABUF + (wid * 16 + a_r) * 48 + a_c2;
                    ldsm4(AH[0], AH[1], AH[2], AH[3], ra);
                    ldsm4(AL[0], AL[1], AL[2], AL[3], ra + (ALOFF - ASTG));
                }
                #pragma unroll
                for (int ng = 0; ng < 6; ng++) {
                    uint32_t bh0, bh1, bh2, bh3, bl0, bl1, bl2, bl3;
                    uint32_t rb = smb + WHI + (ng * 16 + b_n) * (KW * 2) + kc * 32 + b_k2;
                    ldsm4(bh0, bh1, bh2, bh3, rb);
                    ldsm4(bl0, bl1, bl2, bl3, rb + WBYT);
                    mma_bf16(acc[2*ng],   AH, bh0, bh1);
                    mma_bf16(acc[2*ng],   AL, bh0, bh1);
                    mma_bf16(acc[2*ng],   AH, bl0, bl1);
                    mma_bf16(acc[2*ng+1], AH, bh2, bh3);
                    mma_bf16(acc[2*ng+1], AL, bh2, bh3);
                    mma_bf16(acc[2*ng+1], AH, bl2, bl3);
                }
                if (more) {
                    *(uint4*)(smem + ASTG + (buf ^ 1) * ABUF + srow * 48 + shalf * 16) = nh;
                    *(uint4*)(smem + ALOFF + (buf ^ 1) * ABUF + srow * 48 + shalf * 16) = nl;
                }
                __syncthreads();
            }
        }

        // fused GRU epilogue on mma fragment layout
        {
            const int rb0 = row0 + wid * 16 + (lane >> 2);
            const int cb  = (lane & 3) * 2;
            #pragma unroll
            for (int q = 0; q < 4; q++) {
                int jj = q * 8 + cb;
                int j = j0 + jj;
                if (j >= HIDN) continue;
                float rbias0 = bias_sm[jj],      rbias1 = bias_sm[jj + 1];
                float zbias0 = bias_sm[32 + jj], zbias1 = bias_sm[32 + jj + 1];
                float nbias0 = bias_sm[64 + jj], nbias1 = bias_sm[64 + jj + 1];
                #pragma unroll
                for (int hf = 0; hf < 2; hf++) {
                    int row = rb0 + hf * 8;
                    int e0 = hf * 2, e1 = hf * 2 + 1;
                    const float* xr = xp_t + (size_t)row * G3;
                    float2 xrv = *(const float2*)&xr[j];
                    float2 xzv = *(const float2*)&xr[HIDN + j];
                    float2 xnv = *(const float2*)&xr[2 * HIDN + j];
                    float2 hpv = mm ? *(const float2*)&seqp[(size_t)row * HIDN + j]
                                    : make_float2(0.f, 0.f);
                    float gr0 = acc[q][e0],     gr1 = acc[q][e1];
                    float gz0 = acc[q + 4][e0], gz1 = acc[q + 4][e1];
                    float gn0 = acc[q + 8][e0], gn1 = acc[q + 8][e1];
                    float r0 = sigm(xrv.x + gr0 + rbias0);
                    float z0 = sigm(xzv.x + gz0 + zbias0);
                    float n0 = tanhf(xnv.x + r0 * (gn0 + nbias0));
                    float h0 = (1.f - z0) * n0 + z0 * hpv.x;
                    float r1 = sigm(xrv.y + gr1 + rbias1);
                    float z1 = sigm(xzv.y + gz1 + zbias1);
                    float n1 = tanhf(xnv.y + r1 * (gn1 + nbias1));
                    float h1 = (1.f - z1) * n1 + z1 * hpv.y;
                    *(float2*)&seq_t[(size_t)row * HIDN + j] = make_float2(h0, h1);
                    *(uint32_t*)&g_hbh[dir][par][(size_t)row * HPAD + j] = bf16x2_hi(h0, h1);
                    *(uint32_t*)&g_hbl[dir][par][(size_t)row * HPAD + j] = bf16x2_lo(h0, h1);
                }
            }
        }

        __threadfence();
        __syncthreads();
        if (tid == 0) {
            atomicAdd(ctr, 1);
            int target = 7 * (s + 1);
            while (*(volatile int*)ctr < target) { }
            __threadfence();
        }
        __syncthreads();
    }
}

__global__ void __launch_bounds__(256) word_attn_kernel(const float* __restrict__ aw)
{
    extern __shared__ float tup[];
    __shared__ float sc[T_LEN];
    const int s = blockIdx.x;
    const int lane = threadIdx.x & 31, wid = threadIdx.x >> 5;
    for (int t = wid; t < T_LEN; t += 8) {
        const float* f = g_seq_f + ((size_t)t * S_TOT + s) * HIDN;
        const float* b = g_seq_b + ((size_t)t * S_TOT + s) * HIDN;
        float sum = 0.f;
        for (int d = lane; d < HIDN; d += 32) {
            float v = f[d] + b[d];
            tup[t * HIDN + d] = v;
            sum += tanhf(v) * aw[d];
        }
        #pragma unroll
        for (int o = 16; o > 0; o >>= 1) sum += __shfl_xor_sync(0xffffffffu, sum, o);
        if (lane == 0) sc[t] = sum;
    }
    __syncthreads();
    if (threadIdx.x == 0) {
        float m = sc[0];
        for (int t = 1; t < T_LEN; t++) m = fmaxf(m, sc[t]);
        float ssum = 0.f;
        for (int t = 0; t < T_LEN; t++) { float e2 = expf(sc[t] - m); sc[t] = e2; ssum += e2; }
        float inv = 1.f / ssum;
        for (int t = 0; t < T_LEN; t++) sc[t] *= inv;
    }
    __syncthreads();
    for (int d = threadIdx.x; d < HIDN; d += 256) {
        float acc = 0.f;
        #pragma unroll 7
        for (int t = 0; t < T_LEN; t++) acc += sc[t] * tup[t * HIDN + d];
        g_H[(size_t)s * HIDN + d] = acc;
    }
}

__global__ void __launch_bounds__(128) bag_kernel(
    const float* __restrict__ sen_a, const float* __restrict__ sen_r,
    const float* __restrict__ rel, const float* __restrict__ sen_d,
    const int* __restrict__ label, float* __restrict__ logits)
{
    const int b = blockIdx.x;
    __shared__ float Hs[NSEN][HIDN];
    __shared__ float ew[NSEN];
    __shared__ float Sv[HIDN];
    __shared__ float red[128];
    for (int e = threadIdx.x; e < NSEN * HIDN; e += 128)
        Hs[e / HIDN][e % HIDN] = g_H[(size_t)b * NSEN * HIDN + e];
    __syncthreads();
    const int lane = threadIdx.x & 31, wid = threadIdx.x >> 5;
    for (int n = wid; n < NSEN; n += 4) {
        float sum = 0.f;
        for (int d = lane; d < HIDN; d += 32)
            sum += Hs[n][d] * sen_a[d] * sen_r[d];
        #pragma unroll
        for (int o = 16; o > 0; o >>= 1) sum += __shfl_xor_sync(0xffffffffu, sum, o);
        if (lane == 0) ew[n] = sum;
    }
    __syncthreads();
    if (threadIdx.x == 0) {
        float m = ew[0];
        for (int n = 1; n < NSEN; n++) m = fmaxf(m, ew[n]);
        float s2 = 0.f;
        for (int n = 0; n < NSEN; n++) { float e2 = expf(ew[n] - m); ew[n] = e2; s2 += e2; }
        float inv = 1.f / s2;
        for (int n = 0; n < NSEN; n++) ew[n] *= inv;
    }
    __syncthreads();
    for (int d = threadIdx.x; d < HIDN; d += 128) {
        float acc = 0.f;
        for (int n = 0; n < NSEN; n++) acc += ew[n] * Hs[n][d];
        Sv[d] = acc;
    }
    __syncthreads();
    int lab = label[b];
    float bce = 0.f;
    if (threadIdx.x < NREL) {
        int r = threadIdx.x;
        float l = sen_d[r];
        for (int d = 0; d < HIDN; d++) l += Sv[d] * rel[(size_t)r * HIDN + d];
        logits[(size_t)b * NREL + r] = l;
        float tgt = (lab == r) ? 1.f : 0.f;
        bce = fmaxf(l, 0.f) - l * tgt + log1pf(expf(-fabsf(l)));
    }
    red[threadIdx.x] = bce;
    __syncthreads();
    for (int o = 64; o > 0; o >>= 1) {
        if (threadIdx.x < o) red[threadIdx.x] += red[threadIdx.x + o];
        __syncthreads();
    }
    if (threadIdx.x == 0) g_bagloss[b] = red[0] / (float)NREL;
}

__global__ void loss_sum_kernel(float* __restrict__ out) {
    __shared__ float red[128];
    red[threadIdx.x] = g_bagloss[threadIdx.x];
    __syncthreads();
    for (int o = 64; o > 0; o >>= 1) {
        if (threadIdx.x < o) red[threadIdx.x] += red[threadIdx.x + o];
        __syncthreads();
    }
    if (threadIdx.x == 0) out[0] = red[0];
}

extern "C" void kernel_launch(void* const* d_in, const int* in_sizes, int n_in,
                              void* d_out, int out_size)
{
    const int*   tok   = (const int*)d_in[0];
    const int*   p1    = (const int*)d_in[1];
    const int*   p2    = (const int*)d_in[2];
    const int*   lab   = (const int*)d_in[3];
    const float* emb   = (const float*)d_in[4];
    const float* pemb  = (const float*)d_in[5];
    const float* Wih_f = (const float*)d_in[6];
    const float* Whh_f = (const float*)d_in[7];
    const float* bih_f = (const float*)d_in[8];
    const float* bhh_f = (const float*)d_in[9];
    const float* Wih_b = (const float*)d_in[10];
    const float* Whh_b = (const float*)d_in[11];
    const float* bih_b = (const float*)d_in[12];
    const float* bhh_b = (const float*)d_in[13];
    const float* aw    = (const float*)d_in[14];
    const float* sen_a = (const float*)d_in[15];
    const float* sen_r = (const float*)d_in[16];
    const float* rel   = (const float*)d_in[17];
    const float* sen_d = (const float*)d_in[18];
    float* out = (float*)d_out;

    int initN = 2 * 2 * S_TOT * HPAD / 2;
    init_kernel<<<(initN + 255) / 256, 256>>>();
    gather_kernel<<<(S_TOT * T_LEN * IND + 255) / 256, 256>>>(tok, p1, p2, emb, pemb);

    cudaFuncSetAttribute(xp_mma_kernel,
                         cudaFuncAttributeMaxDynamicSharedMemorySize, XP_SMEM);
    dim3 g2(S_TOT * T_LEN / 128, 7, 2);
    xp_mma_kernel<<<g2, 128, XP_SMEM>>>(Wih_f, Wih_b, bih_f, bih_b);

    cudaFuncSetAttribute(gru_mma_kernel,
                         cudaFuncAttributeMaxDynamicSharedMemorySize, GRU_SMEM);
    dim3 g3(7, 20, 2);
    gru_mma_kernel<<<g3, 256, GRU_SMEM>>>(Whh_f, Whh_b, bhh_f, bhh_b);

    static const int attn_smem = T_LEN * HIDN * (int)sizeof(float);
    cudaFuncSetAttribute(word_attn_kernel,
                         cudaFuncAttributeMaxDynamicSharedMemorySize, attn_smem);
    word_attn_kernel<<<S_TOT, 256, attn_smem>>>(aw);
    bag_kernel<<<NBAG, 128>>>(sen_a, sen_r, rel, sen_d, lab, out + 1);
    loss_sum_kernel<<<1, 128>>>(out);
}

// round 14
// speedup vs baseline: 1.9006x; 1.1223x over previous
#include <cuda_runtime.h>
#include <cuda_bf16.h>
#include <math.h>
#include <stdint.h>

#define S_TOT 2560
#define T_LEN 70
#define HIDN  200
#define G3    600
#define IND   60
#define NBAG  128
#define NSEN  20
#define NREL  100
#define HPAD  208

typedef unsigned long long ULL;

__device__ float g_x[S_TOT * T_LEN * IND];
__device__ float g_xp_f[(size_t)T_LEN * S_TOT * G3];
__device__ float g_xp_b[(size_t)T_LEN * S_TOT * G3];
__device__ float g_seq_f[(size_t)T_LEN * S_TOT * HIDN];
__device__ float g_seq_b[(size_t)T_LEN * S_TOT * HIDN];
__device__ __nv_bfloat16 g_hbh[2][2][S_TOT * HPAD];   // [dir][parity]
__device__ __nv_bfloat16 g_hbl[2][2][S_TOT * HPAD];
__device__ float g_H[S_TOT * HIDN];
__device__ float g_bagloss[NBAG];
__device__ int   g_ctr[2][20];

__device__ __forceinline__ float sigm(float x) { return 1.f / (1.f + expf(-x)); }
__device__ __forceinline__ uint32_t smem_u32(const void* p) {
    uint32_t a;
    asm("{ .reg .u64 t; cvta.to.shared.u64 t, %1; cvt.u32.u64 %0, t; }" : "=r"(a) : "l"(p));
    return a;
}
__device__ __forceinline__ void ldsm4(uint32_t& r0, uint32_t& r1, uint32_t& r2,
                                      uint32_t& r3, uint32_t addr) {
    asm volatile("ldmatrix.sync.aligned.m8n8.x4.shared.b16 {%0,%1,%2,%3}, [%4];"
                 : "=r"(r0), "=r"(r1), "=r"(r2), "=r"(r3) : "r"(addr));
}
__device__ __forceinline__ void mma_bf16(float* d, const uint32_t* a,
                                         uint32_t b0, uint32_t b1) {
    asm volatile(
        "mma.sync.aligned.m16n8k16.row.col.f32.bf16.bf16.f32 "
        "{%0,%1,%2,%3}, {%4,%5,%6,%7}, {%8,%9}, {%0,%1,%2,%3};"
        : "+f"(d[0]), "+f"(d[1]), "+f"(d[2]), "+f"(d[3])
        : "r"(a[0]), "r"(a[1]), "r"(a[2]), "r"(a[3]), "r"(b0), "r"(b1));
}
__device__ __forceinline__ uint32_t bf16x2_hi(float x, float y) {
    __nv_bfloat162 v; v.x = __float2bfloat16(x); v.y = __float2bfloat16(y);
    return *(uint32_t*)&v;
}
__device__ __forceinline__ uint32_t bf16x2_lo(float x, float y) {
    __nv_bfloat16 hx = __float2bfloat16(x), hy = __float2bfloat16(y);
    __nv_bfloat162 v;
    v.x = __float2bfloat16(x - __bfloat162float(hx));
    v.y = __float2bfloat16(y - __bfloat162float(hy));
    return *(uint32_t*)&v;
}
__device__ __forceinline__ void pf_l2(const void* p) {
    asm volatile("prefetch.global.L2 [%0];" :: "l"(p));
}
__device__ __forceinline__ void cpa16(uint32_t dst, const void* src) {
    asm volatile("cp.async.cg.shared.global [%0], [%1], 16;" :: "r"(dst), "l"(src));
}
#define CP_COMMIT() asm volatile("cp.async.commit_group;" ::: "memory")
#define CP_WAIT0()  asm volatile("cp.async.wait_group 0;" ::: "memory")

__global__ void init_kernel() {
    size_t i = (size_t)blockIdx.x * blockDim.x + threadIdx.x;
    size_t n = (size_t)2 * 2 * S_TOT * HPAD / 2;
    if (i < n) { ((uint32_t*)g_hbh)[i] = 0u; ((uint32_t*)g_hbl)[i] = 0u; }
    if (i < 40) ((int*)g_ctr)[i] = 0;
}

__global__ void gather_kernel(const int* __restrict__ tok, const int* __restrict__ p1,
                              const int* __restrict__ p2, const float* __restrict__ emb,
                              const float* __restrict__ pemb) {
    int idx = blockIdx.x * blockDim.x + threadIdx.x;
    if (idx >= S_TOT * T_LEN * IND) return;
    int st = idx / IND, c = idx - st * IND;
    float v;
    if (c < 50)      v = emb[(size_t)tok[st] * 50 + c];
    else if (c < 55) v = pemb[(size_t)p1[st] * 5 + (c - 50)];
    else             v = pemb[(size_t)p2[st] * 5 + (c - 55)];
    g_x[idx] = v;
}

// ---------------- xp = x @ W_ih^T + bias via warp-MMA (bf16 hi/lo) ----------
// bias = b_ih + b_hh for gates r,z (cols < 400); b_ih only for gate n.
#define XKA   144
#define XBIAS 0
#define XAHI  512
#define XABYT (128 * XKA)
#define XALO  (XAHI + XABYT)
#define XWHI  (XALO + XABYT)
#define XWBYT (96 * XKA)
#define XWLO  (XWHI + XWBYT)
#define XP_SMEM (XWLO + XWBYT)

__global__ void __launch_bounds__(128) xp_mma_kernel(
    const float* __restrict__ Wf, const float* __restrict__ Wb,
    const float* __restrict__ bf, const float* __restrict__ bb,
    const float* __restrict__ bhf, const float* __restrict__ bhb)
{
    extern __shared__ char smem[];
    float* bias_sm = (float*)(smem + XBIAS);
    const uint32_t smb = smem_u32(smem);
    const int mb = blockIdx.x, jbb = blockIdx.y, dir = blockIdx.z;
    const float* W    = dir ? Wb : Wf;
    const float* bias = dir ? bb : bf;
    const float* bhh  = dir ? bhb : bhf;
    float* xp = dir ? g_xp_b : g_xp_f;
    const int m0 = mb * 128, c0 = jbb * 96;
    const int tid = threadIdx.x, wid = tid >> 5, lane = tid & 31;

    {
        const float* xr = g_x + (size_t)(m0 + tid) * IND;
        uint32_t* ah = (uint32_t*)(smem + XAHI + tid * XKA);
        uint32_t* al = (uint32_t*)(smem + XALO + tid * XKA);
        #pragma unroll
        for (int i = 0; i < 30; i++) {
            float2 v = *(const float2*)&xr[2 * i];
            ah[i] = bf16x2_hi(v.x, v.y);
            al[i] = bf16x2_lo(v.x, v.y);
        }
        ah[30] = 0u; ah[31] = 0u; al[30] = 0u; al[31] = 0u;
    }
    for (int e = tid; e < 96 * 32; e += 128) {
        int n = e >> 5, i = e & 31;
        int col = c0 + n, k = 2 * i;
        float w0 = 0.f, w1 = 0.f;
        if (col < G3) {
            if (k < IND)     w0 = W[(size_t)col * IND + k];
            if (k + 1 < IND) w1 = W[(size_t)col * IND + k + 1];
        }
        ((uint32_t*)(smem + XWHI + n * XKA))[i] = bf16x2_hi(w0, w1);
        ((uint32_t*)(smem + XWLO + n * XKA))[i] = bf16x2_lo(w0, w1);
    }
    for (int n = tid; n < 96; n += 128) {
        int c = c0 + n;
        float v = 0.f;
        if (c < G3) {
            v = bias[c];
            if (c < 2 * HIDN) v += bhh[c];     // fold b_hh for r,z gates
        }
        bias_sm[n] = v;
    }
    __syncthreads();

    const int a_r  = (lane & 7) + ((lane >> 3) & 1) * 8;
    const int a_c2 = ((lane >> 4) & 1) * 16;
    const int b_n  = ((lane >> 4) ? 8 : 0) + (lane & 7);
    const int b_k2 = ((lane >> 3) & 1) * 16;

    float acc[2][12][4];
    #pragma unroll
    for (int m = 0; m < 2; m++)
        #pragma unroll
        for (int n = 0; n < 12; n++)
            #pragma unroll
            for (int e = 0; e < 4; e++) acc[m][n][e] = 0.f;

    #pragma unroll
    for (int kc = 0; kc < 4; kc++) {
        uint32_t AH[2][4], AL[2][4];
        #pragma unroll
        for (int mt = 0; mt < 2; mt++) {
            uint32_t ra = smb + XAHI + (wid * 32 + mt * 16 + a_r) * XKA + kc * 32 + a_c2;
            ldsm4(AH[mt][0], AH[mt][1], AH[mt][2], AH[mt][3], ra);
            ldsm4(AL[mt][0], AL[mt][1], AL[mt][2], AL[mt][3], ra + XABYT);
        }
        #pragma unroll
        for (int ng = 0; ng < 6; ng++) {
            uint32_t bh0, bh1, bh2, bh3, bl0, bl1, bl2, bl3;
            uint32_t rb = smb + XWHI + (ng * 16 + b_n) * XKA + kc * 32 + b_k2;
            ldsm4(bh0, bh1, bh2, bh3, rb);
            ldsm4(bl0, bl1, bl2, bl3, rb + XWBYT);
            #pragma unroll
            for (int mt = 0; mt < 2; mt++) {
                mma_bf16(acc[mt][2*ng],   AH[mt], bh0, bh1);
                mma_bf16(acc[mt][2*ng],   AL[mt], bh0, bh1);
                mma_bf16(acc[mt][2*ng],   AH[mt], bl0, bl1);
                mma_bf16(acc[mt][2*ng+1], AH[mt], bh2, bh3);
                mma_bf16(acc[mt][2*ng+1], AL[mt], bh2, bh3);
                mma_bf16(acc[mt][2*ng+1], AH[mt], bl2, bl3);
            }
        }
    }

    const int r_l = lane >> 2, cb = (lane & 3) * 2;
    #pragma unroll
    for (int mt = 0; mt < 2; mt++) {
        #pragma unroll
        for (int q = 0; q < 12; q++) {
            int c = c0 + q * 8 + cb;
            if (c >= G3) continue;
            float b0 = bias_sm[q * 8 + cb], b1 = bias_sm[q * 8 + cb + 1];
            #pragma unroll
            for (int hf = 0; hf < 2; hf++) {
                int m = m0 + wid * 32 + mt * 16 + hf * 8 + r_l;
                int s = m / T_LEN, t = m - s * T_LEN;
                int e0 = hf * 2;
                float2 out = make_float2(acc[mt][q][e0] + b0, acc[mt][q][e0 + 1] + b1);
                *(float2*)&xp[((size_t)t * S_TOT + s) * G3 + c] = out;
            }
        }
    }
}

// ---------------- warp-MMA persistent GRU, 256 threads (8 warps) ------------
// hprev kept in registers; A staging via cp.async; 14 syncs/step.
#define KW   216
#define SBIAS 0
#define ASTG  512
#define ABUF  6144
#define ALOFF (ASTG + 2*ABUF)
#define WHI   25088
#define WBYT  (96 * KW * 2)
#define WLO   (WHI + WBYT)
#define GRU_SMEM (WLO + WBYT)   // 108032

__global__ void __launch_bounds__(256, 2) gru_mma_kernel(
    const float* __restrict__ Whh_f, const float* __restrict__ Whh_b,
    const float* __restrict__ bhh_f, const float* __restrict__ bhh_b)
{
    extern __shared__ char smem[];
    float* bias_sm = (float*)(smem + SBIAS);
    const uint32_t smb = smem_u32(smem);
    const int jb = blockIdx.x, rowt = blockIdx.y, dir = blockIdx.z;
    const int tid = threadIdx.x, wid = tid >> 5, lane = tid & 31;
    const int row0 = rowt * 128, j0 = jb * 32;
    const int srow = tid >> 1, shalf = tid & 1;

    const float* W   = dir ? Whh_b : Whh_f;
    const float* bhh = dir ? bhh_b : bhh_f;
    const float* xpb = dir ? g_xp_b : g_xp_f;
    float*      seqb = dir ? g_seq_b : g_seq_f;

    for (int e = tid; e < 96 * KW; e += 256) {
        int n = e / KW, k = e - n * KW;
        int g = n >> 5, jj = n & 31, col = j0 + jj;
        float w = (col < HIDN && k < HIDN) ? W[((size_t)g * HIDN + col) * HIDN + k] : 0.f;
        __nv_bfloat16 hi = __float2bfloat16(w);
        __nv_bfloat16 lo = __float2bfloat16(w - __bfloat162float(hi));
        *(__nv_bfloat16*)(smem + WHI + (size_t)e * 2) = hi;
        *(__nv_bfloat16*)(smem + WLO + (size_t)e * 2) = lo;
    }
    for (int n = tid; n < 96; n += 256) {
        int g = n >> 5, jj = n & 31, col = j0 + jj;
        bias_sm[n] = (col < HIDN) ? bhh[g * HIDN + col] : 0.f;
    }
    __syncthreads();

    const int a_r  = (lane & 7) + ((lane >> 3) & 1) * 8;
    const int a_c2 = ((lane >> 4) & 1) * 16;
    const int b_n  = ((lane >> 4) ? 8 : 0) + (lane & 7);
    const int b_k2 = ((lane >> 3) & 1) * 16;
    int* ctr = &g_ctr[dir][rowt];

    // hprev in registers: [q][hf*2 + e], matching the epilogue fragment map
    float hprev_reg[4][4];
    #pragma unroll
    for (int q = 0; q < 4; q++)
        #pragma unroll
        for (int e = 0; e < 4; e++) hprev_reg[q][e] = 0.f;

    const uint32_t st_dst_h = smb + ASTG  + srow * 48 + shalf * 16;
    const uint32_t st_dst_l = smb + ALOFF + srow * 48 + shalf * 16;

    for (int s = 0; s < T_LEN; s++) {
        const int t = dir ? (T_LEN - 1 - s) : s;
        const float* xp_t  = xpb + (size_t)t * S_TOT * G3;
        float*       seq_t = seqb + (size_t)t * S_TOT * HIDN;
        const int par = s & 1;
        const bool mm = (s > 0);

        // L2 prefetch of this step's xp working set (overlaps MMA loop)
        {
            int r0e = row0 + wid * 16 + (lane >> 2);
            #pragma unroll
            for (int hf = 0; hf < 2; hf++) {
                const float* pr = xp_t + (size_t)(r0e + hf * 8) * G3 + j0;
                pf_l2(pr); pf_l2(pr + HIDN); pf_l2(pr + 2 * HIDN);
            }
        }

        float acc[12][4];
        #pragma unroll
        for (int n = 0; n < 12; n++)
            #pragma unroll
            for (int e = 0; e < 4; e++) acc[n][e] = 0.f;

        if (mm) {
            const __nv_bfloat16* hh = g_hbh[dir][par ^ 1] + (size_t)(row0 + srow) * HPAD;
            const __nv_bfloat16* hl = g_hbl[dir][par ^ 1] + (size_t)(row0 + srow) * HPAD;
            // chunk 0 staging via cp.async
            cpa16(st_dst_h, hh + shalf * 8);
            cpa16(st_dst_l, hl + shalf * 8);
            CP_COMMIT();
            CP_WAIT0();
            __syncthreads();

            for (int kc = 0; kc < 13; kc++) {
                const int buf = kc & 1;
                const bool more = (kc < 12);
                if (more) {
                    int k0 = (kc + 1) * 16 + shalf * 8;
                    cpa16(st_dst_h + (buf ^ 1) * ABUF, hh + k0);
                    cpa16(st_dst_l + (buf ^ 1) * ABUF, hl + k0);
                    CP_COMMIT();
                }
                uint32_t AH[4], AL[4];
                {
                    uint32_t ra = smb + ASTG + buf * ABUF + (wid * 16 + a_r) * 48 + a_c2;
                    ldsm4(AH[0], AH[1], AH[2], AH[3], ra);
                    ldsm4(AL[0], AL[1], AL[2], AL[3], ra + (ALOFF - ASTG));
                }
                #pragma unroll
                for (int ng = 0; ng < 6; ng++) {
                    uint32_t bh0, bh1, bh2, bh3, bl0, bl1, bl2, bl3;
                    uint32_t rb = smb + WHI + (ng * 16 + b_n) * (KW * 2) + kc * 32 + b_k2;
                    ldsm4(bh0, bh1, bh2, bh3, rb);
                    ldsm4(bl0, bl1, bl2, bl3, rb + WBYT);
                    mma_bf16(acc[2*ng],   AH, bh0, bh1);
                    mma_bf16(acc[2*ng],   AL, bh0, bh1);
                    mma_bf16(acc[2*ng],   AH, bl0, bl1);
                    mma_bf16(acc[2*ng+1], AH, bh2, bh3);
                    mma_bf16(acc[2*ng+1], AL, bh2, bh3);
                    mma_bf16(acc[2*ng+1], AH, bl2, bl3);
                }
                if (more) {
                    CP_WAIT0();
                    __syncthreads();
                }
            }
        }

        // fused GRU epilogue (hprev from registers; r,z biases folded into xp)
        {
            const int rb0 = row0 + wid * 16 + (lane >> 2);
            const int cb  = (lane & 3) * 2;
            #pragma unroll
            for (int q = 0; q < 4; q++) {
                int jj = q * 8 + cb;
                int j = j0 + jj;
                if (j >= HIDN) continue;
                float nbias0 = bias_sm[64 + jj], nbias1 = bias_sm[64 + jj + 1];
                #pragma unroll
                for (int hf = 0; hf < 2; hf++) {
                    int row = rb0 + hf * 8;
                    int e0 = hf * 2, e1 = hf * 2 + 1;
                    const float* xr = xp_t + (size_t)row * G3;
                    float2 xrv = *(const float2*)&xr[j];
                    float2 xzv = *(const float2*)&xr[HIDN + j];
                    float2 xnv = *(const float2*)&xr[2 * HIDN + j];
                    float hp0 = hprev_reg[q][e0], hp1 = hprev_reg[q][e1];
                    float r0 = sigm(xrv.x + acc[q][e0]);
                    float z0 = sigm(xzv.x + acc[q + 4][e0]);
                    float n0 = tanhf(xnv.x + r0 * (acc[q + 8][e0] + nbias0));
                    float h0 = (1.f - z0) * n0 + z0 * hp0;
                    float r1 = sigm(xrv.y + acc[q][e1]);
                    float z1 = sigm(xzv.y + acc[q + 4][e1]);
                    float n1 = tanhf(xnv.y + r1 * (acc[q + 8][e1] + nbias1));
                    float h1 = (1.f - z1) * n1 + z1 * hp1;
                    *(float2*)&seq_t[(size_t)row * HIDN + j] = make_float2(h0, h1);
                    *(uint32_t*)&g_hbh[dir][par][(size_t)row * HPAD + j] = bf16x2_hi(h0, h1);
                    *(uint32_t*)&g_hbl[dir][par][(size_t)row * HPAD + j] = bf16x2_lo(h0, h1);
                    hprev_reg[q][e0] = h0;
                    hprev_reg[q][e1] = h1;
                }
            }
        }

        __threadfence();
        __syncthreads();
        if (tid == 0) {
            atomicAdd(ctr, 1);
            int target = 7 * (s + 1);
            while (*(volatile int*)ctr < target) { }
            __threadfence();
        }
        __syncthreads();
    }
}

__global__ void __launch_bounds__(256) word_attn_kernel(const float* __restrict__ aw)
{
    extern __shared__ float tup[];
    __shared__ float sc[T_LEN];
    const int s = blockIdx.x;
    const int lane = threadIdx.x & 31, wid = threadIdx.x >> 5;
    for (int t = wid; t < T_LEN; t += 8) {
        const float* f = g_seq_f + ((size_t)t * S_TOT + s) * HIDN;
        const float* b = g_seq_b + ((size_t)t * S_TOT + s) * HIDN;
        float sum = 0.f;
        for (int d = lane; d < HIDN; d += 32) {
            float v = f[d] + b[d];
            tup[t * HIDN + d] = v;
            sum += tanhf(v) * aw[d];
        }
        #pragma unroll
        for (int o = 16; o > 0; o >>= 1) sum += __shfl_xor_sync(0xffffffffu, sum, o);
        if (lane == 0) sc[t] = sum;
    }
    __syncthreads();
    if (threadIdx.x == 0) {
        float m = sc[0];
        for (int t = 1; t < T_LEN; t++) m = fmaxf(m, sc[t]);
        float ssum = 0.f;
        for (int t = 0; t < T_LEN; t++) { float e2 = expf(sc[t] - m); sc[t] = e2; ssum += e2; }
        float inv = 1.f / ssum;
        for (int t = 0; t < T_LEN; t++) sc[t] *= inv;
    }
    __syncthreads();
    for (int d = threadIdx.x; d < HIDN; d += 256) {
        float acc = 0.f;
        #pragma unroll 7
        for (int t = 0; t < T_LEN; t++) acc += sc[t] * tup[t * HIDN + d];
        g_H[(size_t)s * HIDN + d] = acc;
    }
}

__global__ void __launch_bounds__(128) bag_kernel(
    const float* __restrict__ sen_a, const float* __restrict__ sen_r,
    const float* __restrict__ rel, const float* __restrict__ sen_d,
    const int* __restrict__ label, float* __restrict__ logits)
{
    const int b = blockIdx.x;
    __shared__ float Hs[NSEN][HIDN];
    __shared__ float ew[NSEN];
    __shared__ float Sv[HIDN];
    __shared__ float red[128];
    for (int e = threadIdx.x; e < NSEN * HIDN; e += 128)
        Hs[e / HIDN][e % HIDN] = g_H[(size_t)b * NSEN * HIDN + e];
    __syncthreads();
    const int lane = threadIdx.x & 31, wid = threadIdx.x >> 5;
    for (int n = wid; n < NSEN; n += 4) {
        float sum = 0.f;
        for (int d = lane; d < HIDN; d += 32)
            sum += Hs[n][d] * sen_a[d] * sen_r[d];
        #pragma unroll
        for (int o = 16; o > 0; o >>= 1) sum += __shfl_xor_sync(0xffffffffu, sum, o);
        if (lane == 0) ew[n] = sum;
    }
    __syncthreads();
    if (threadIdx.x == 0) {
        float m = ew[0];
        for (int n = 1; n < NSEN; n++) m = fmaxf(m, ew[n]);
        float s2 = 0.f;
        for (int n = 0; n < NSEN; n++) { float e2 = expf(ew[n] - m); ew[n] = e2; s2 += e2; }
        float inv = 1.f / s2;
        for (int n = 0; n < NSEN; n++) ew[n] *= inv;
    }
    __syncthreads();
    for (int d = threadIdx.x; d < HIDN; d += 128) {
        float acc = 0.f;
        for (int n = 0; n < NSEN; n++) acc += ew[n] * Hs[n][d];
        Sv[d] = acc;
    }
    __syncthreads();
    int lab = label[b];
    float bce = 0.f;
    if (threadIdx.x < NREL) {
        int r = threadIdx.x;
        float l = sen_d[r];
        for (int d = 0; d < HIDN; d++) l += Sv[d] * rel[(size_t)r * HIDN + d];
        logits[(size_t)b * NREL + r] = l;
        float tgt = (lab == r) ? 1.f : 0.f;
        bce = fmaxf(l, 0.f) - l * tgt + log1pf(expf(-fabsf(l)));
    }
    red[threadIdx.x] = bce;
    __syncthreads();
    for (int o = 64; o > 0; o >>= 1) {
        if (threadIdx.x < o) red[threadIdx.x] += red[threadIdx.x + o];
        __syncthreads();
    }
    if (threadIdx.x == 0) g_bagloss[b] = red[0] / (float)NREL;
}

__global__ void loss_sum_kernel(float* __restrict__ out) {
    __shared__ float red[128];
    red[threadIdx.x] = g_bagloss[threadIdx.x];
    __syncthreads();
    for (int o = 64; o > 0; o >>= 1) {
        if (threadIdx.x < o) red[threadIdx.x] += red[threadIdx.x + o];
        __syncthreads();
    }
    if (threadIdx.x == 0) out[0] = red[0];
}

extern "C" void kernel_launch(void* const* d_in, const int* in_sizes, int n_in,
                              void* d_out, int out_size)
{
    const int*   tok   = (const int*)d_in[0];
    const int*   p1    = (const int*)d_in[1];
    const int*   p2    = (const int*)d_in[2];
    const int*   lab   = (const int*)d_in[3];
    const float* emb   = (const float*)d_in[4];
    const float* pemb  = (const float*)d_in[5];
    const float* Wih_f = (const float*)d_in[6];
    const float* Whh_f = (const float*)d_in[7];
    const float* bih_f = (const float*)d_in[8];
    const float* bhh_f = (const float*)d_in[9];
    const float* Wih_b = (const float*)d_in[10];
    const float* Whh_b = (const float*)d_in[11];
    const float* bih_b = (const float*)d_in[12];
    const float* bhh_b = (const float*)d_in[13];
    const float* aw    = (const float*)d_in[14];
    const float* sen_a = (const float*)d_in[15];
    const float* sen_r = (const float*)d_in[16];
    const float* rel   = (const float*)d_in[17];
    const float* sen_d = (const float*)d_in[18];
    float* out = (float*)d_out;

    int initN = 2 * 2 * S_TOT * HPAD / 2;
    init_kernel<<<(initN + 255) / 256, 256>>>();
    gather_kernel<<<(S_TOT * T_LEN * IND + 255) / 256, 256>>>(tok, p1, p2, emb, pemb);

    cudaFuncSetAttribute(xp_mma_kernel,
                         cudaFuncAttributeMaxDynamicSharedMemorySize, XP_SMEM);
    dim3 g2(S_TOT * T_LEN / 128, 7, 2);
    xp_mma_kernel<<<g2, 128, XP_SMEM>>>(Wih_f, Wih_b, bih_f, bih_b, bhh_f, bhh_b);

    cudaFuncSetAttribute(gru_mma_kernel,
                         cudaFuncAttributeMaxDynamicSharedMemorySize, GRU_SMEM);
    dim3 g3(7, 20, 2);
    gru_mma_kernel<<<g3, 256, GRU_SMEM>>>(Whh_f, Whh_b, bhh_f, bhh_b);

    static const int attn_smem = T_LEN * HIDN * (int)sizeof(float);
    cudaFuncSetAttribute(word_attn_kernel,
                         cudaFuncAttributeMaxDynamicSharedMemorySize, attn_smem);
    word_attn_kernel<<<S_TOT, 256, attn_smem>>>(aw);
    bag_kernel<<<NBAG, 128>>>(sen_a, sen_r, rel, sen_d, lab, out + 1);
    loss_sum_kernel<<<1, 128>>>(out);
}

// round 15
// speedup vs baseline: 2.0732x; 1.0908x over previous
#include <cuda_runtime.h>
#include <cuda_bf16.h>
#include <math.h>
#include <stdint.h>

#define S_TOT 2560
#define T_LEN 70
#define HIDN  200
#define G3    600
#define IND   60
#define NBAG  128
#define NSEN  20
#define NREL  100
#define HPAD  208

typedef unsigned long long ULL;

__device__ float g_x[S_TOT * T_LEN * IND];
__device__ float g_xp_f[(size_t)T_LEN * S_TOT * G3];
__device__ float g_xp_b[(size_t)T_LEN * S_TOT * G3];
__device__ float g_seq_f[(size_t)T_LEN * S_TOT * HIDN];
__device__ float g_seq_b[(size_t)T_LEN * S_TOT * HIDN];
__device__ __nv_bfloat16 g_hbh[2][2][S_TOT * HPAD];   // [dir][parity]
__device__ __nv_bfloat16 g_hbl[2][2][S_TOT * HPAD];
__device__ float g_H[S_TOT * HIDN];
__device__ float g_bagloss[NBAG];
__device__ int   g_ctr[2][20];

__device__ __forceinline__ float sigm(float x) { return 1.f / (1.f + expf(-x)); }
__device__ __forceinline__ uint32_t smem_u32(const void* p) {
    uint32_t a;
    asm("{ .reg .u64 t; cvta.to.shared.u64 t, %1; cvt.u32.u64 %0, t; }" : "=r"(a) : "l"(p));
    return a;
}
__device__ __forceinline__ void ldsm4(uint32_t& r0, uint32_t& r1, uint32_t& r2,
                                      uint32_t& r3, uint32_t addr) {
    asm volatile("ldmatrix.sync.aligned.m8n8.x4.shared.b16 {%0,%1,%2,%3}, [%4];"
                 : "=r"(r0), "=r"(r1), "=r"(r2), "=r"(r3) : "r"(addr));
}
__device__ __forceinline__ void mma_bf16(float* d, const uint32_t* a,
                                         uint32_t b0, uint32_t b1) {
    asm volatile(
        "mma.sync.aligned.m16n8k16.row.col.f32.bf16.bf16.f32 "
        "{%0,%1,%2,%3}, {%4,%5,%6,%7}, {%8,%9}, {%0,%1,%2,%3};"
        : "+f"(d[0]), "+f"(d[1]), "+f"(d[2]), "+f"(d[3])
        : "r"(a[0]), "r"(a[1]), "r"(a[2]), "r"(a[3]), "r"(b0), "r"(b1));
}
__device__ __forceinline__ uint32_t bf16x2_hi(float x, float y) {
    __nv_bfloat162 v; v.x = __float2bfloat16(x); v.y = __float2bfloat16(y);
    return *(uint32_t*)&v;
}
__device__ __forceinline__ uint32_t bf16x2_lo(float x, float y) {
    __nv_bfloat16 hx = __float2bfloat16(x), hy = __float2bfloat16(y);
    __nv_bfloat162 v;
    v.x = __float2bfloat16(x - __bfloat162float(hx));
    v.y = __float2bfloat16(y - __bfloat162float(hy));
    return *(uint32_t*)&v;
}
__device__ __forceinline__ void pf_l2(const void* p) {
    asm volatile("prefetch.global.L2 [%0];" :: "l"(p));
}
__device__ __forceinline__ void cpa16(uint32_t dst, const void* src) {
    asm volatile("cp.async.cg.shared.global [%0], [%1], 16;" :: "r"(dst), "l"(src));
}
#define CP_COMMIT() asm volatile("cp.async.commit_group;" ::: "memory")
#define CP_WAIT0()  asm volatile("cp.async.wait_group 0;" ::: "memory")

__global__ void init_kernel() {
    size_t i = (size_t)blockIdx.x * blockDim.x + threadIdx.x;
    size_t n = (size_t)2 * 2 * S_TOT * HPAD / 2;
    if (i < n) { ((uint32_t*)g_hbh)[i] = 0u; ((uint32_t*)g_hbl)[i] = 0u; }
    if (i < 40) ((int*)g_ctr)[i] = 0;
}

__global__ void gather_kernel(const int* __restrict__ tok, const int* __restrict__ p1,
                              const int* __restrict__ p2, const float* __restrict__ emb,
                              const float* __restrict__ pemb) {
    int idx = blockIdx.x * blockDim.x + threadIdx.x;
    if (idx >= S_TOT * T_LEN * IND) return;
    int st = idx / IND, c = idx - st * IND;
    float v;
    if (c < 50)      v = emb[(size_t)tok[st] * 50 + c];
    else if (c < 55) v = pemb[(size_t)p1[st] * 5 + (c - 50)];
    else             v = pemb[(size_t)p2[st] * 5 + (c - 55)];
    g_x[idx] = v;
}

// ---------------- xp = x @ W_ih^T + bias via warp-MMA (bf16 hi/lo) ----------
#define XKA   144
#define XBIAS 0
#define XAHI  512
#define XABYT (128 * XKA)
#define XALO  (XAHI + XABYT)
#define XWHI  (XALO + XABYT)
#define XWBYT (96 * XKA)
#define XWLO  (XWHI + XWBYT)
#define XP_SMEM (XWLO + XWBYT)

__global__ void __launch_bounds__(128) xp_mma_kernel(
    const float* __restrict__ Wf, const float* __restrict__ Wb,
    const float* __restrict__ bf, const float* __restrict__ bb,
    const float* __restrict__ bhf, const float* __restrict__ bhb)
{
    extern __shared__ char smem[];
    float* bias_sm = (float*)(smem + XBIAS);
    const uint32_t smb = smem_u32(smem);
    const int mb = blockIdx.x, jbb = blockIdx.y, dir = blockIdx.z;
    const float* W    = dir ? Wb : Wf;
    const float* bias = dir ? bb : bf;
    const float* bhh  = dir ? bhb : bhf;
    float* xp = dir ? g_xp_b : g_xp_f;
    const int m0 = mb * 128, c0 = jbb * 96;
    const int tid = threadIdx.x, wid = tid >> 5, lane = tid & 31;

    {
        const float* xr = g_x + (size_t)(m0 + tid) * IND;
        uint32_t* ah = (uint32_t*)(smem + XAHI + tid * XKA);
        uint32_t* al = (uint32_t*)(smem + XALO + tid * XKA);
        #pragma unroll
        for (int i = 0; i < 30; i++) {
            float2 v = *(const float2*)&xr[2 * i];
            ah[i] = bf16x2_hi(v.x, v.y);
            al[i] = bf16x2_lo(v.x, v.y);
        }
        ah[30] = 0u; ah[31] = 0u; al[30] = 0u; al[31] = 0u;
    }
    for (int e = tid; e < 96 * 32; e += 128) {
        int n = e >> 5, i = e & 31;
        int col = c0 + n, k = 2 * i;
        float w0 = 0.f, w1 = 0.f;
        if (col < G3) {
            if (k < IND)     w0 = W[(size_t)col * IND + k];
            if (k + 1 < IND) w1 = W[(size_t)col * IND + k + 1];
        }
        ((uint32_t*)(smem + XWHI + n * XKA))[i] = bf16x2_hi(w0, w1);
        ((uint32_t*)(smem + XWLO + n * XKA))[i] = bf16x2_lo(w0, w1);
    }
    for (int n = tid; n < 96; n += 128) {
        int c = c0 + n;
        float v = 0.f;
        if (c < G3) {
            v = bias[c];
            if (c < 2 * HIDN) v += bhh[c];     // fold b_hh for r,z gates
        }
        bias_sm[n] = v;
    }
    __syncthreads();

    const int a_r  = (lane & 7) + ((lane >> 3) & 1) * 8;
    const int a_c2 = ((lane >> 4) & 1) * 16;
    const int b_n  = ((lane >> 4) ? 8 : 0) + (lane & 7);
    const int b_k2 = ((lane >> 3) & 1) * 16;

    float acc[2][12][4];
    #pragma unroll
    for (int m = 0; m < 2; m++)
        #pragma unroll
        for (int n = 0; n < 12; n++)
            #pragma unroll
            for (int e = 0; e < 4; e++) acc[m][n][e] = 0.f;

    #pragma unroll
    for (int kc = 0; kc < 4; kc++) {
        uint32_t AH[2][4], AL[2][4];
        #pragma unroll
        for (int mt = 0; mt < 2; mt++) {
            uint32_t ra = smb + XAHI + (wid * 32 + mt * 16 + a_r) * XKA + kc * 32 + a_c2;
            ldsm4(AH[mt][0], AH[mt][1], AH[mt][2], AH[mt][3], ra);
            ldsm4(AL[mt][0], AL[mt][1], AL[mt][2], AL[mt][3], ra + XABYT);
        }
        #pragma unroll
        for (int ng = 0; ng < 6; ng++) {
            uint32_t bh0, bh1, bh2, bh3, bl0, bl1, bl2, bl3;
            uint32_t rb = smb + XWHI + (ng * 16 + b_n) * XKA + kc * 32 + b_k2;
            ldsm4(bh0, bh1, bh2, bh3, rb);
            ldsm4(bl0, bl1, bl2, bl3, rb + XWBYT);
            #pragma unroll
            for (int mt = 0; mt < 2; mt++) {
                mma_bf16(acc[mt][2*ng],   AH[mt], bh0, bh1);
                mma_bf16(acc[mt][2*ng],   AL[mt], bh0, bh1);
                mma_bf16(acc[mt][2*ng],   AH[mt], bl0, bl1);
                mma_bf16(acc[mt][2*ng+1], AH[mt], bh2, bh3);
                mma_bf16(acc[mt][2*ng+1], AL[mt], bh2, bh3);
                mma_bf16(acc[mt][2*ng+1], AH[mt], bl2, bl3);
            }
        }
    }

    const int r_l = lane >> 2, cb = (lane & 3) * 2;
    #pragma unroll
    for (int mt = 0; mt < 2; mt++) {
        #pragma unroll
        for (int q = 0; q < 12; q++) {
            int c = c0 + q * 8 + cb;
            if (c >= G3) continue;
            float b0 = bias_sm[q * 8 + cb], b1 = bias_sm[q * 8 + cb + 1];
            #pragma unroll
            for (int hf = 0; hf < 2; hf++) {
                int m = m0 + wid * 32 + mt * 16 + hf * 8 + r_l;
                int s = m / T_LEN, t = m - s * T_LEN;
                int e0 = hf * 2;
                float2 out = make_float2(acc[mt][q][e0] + b0, acc[mt][q][e0 + 1] + b1);
                *(float2*)&xp[((size_t)t * S_TOT + s) * G3 + c] = out;
            }
        }
    }
}

// ---------------- warp-MMA persistent GRU, 256 threads (8 warps) ------------
// Warp-autonomous A staging (each warp stages its own 16 rows via cp.async).
// No block syncs inside the chunk loop; 2 block syncs per step total.
#define KW   216
#define SBIAS 0
#define ASTG  512
#define ABUF  6144
#define ALOFF (ASTG + 2*ABUF)
#define WHI   25088
#define WBYT  (96 * KW * 2)
#define WLO   (WHI + WBYT)
#define GRU_SMEM (WLO + WBYT)   // 108032

__global__ void __launch_bounds__(256, 2) gru_mma_kernel(
    const float* __restrict__ Whh_f, const float* __restrict__ Whh_b,
    const float* __restrict__ bhh_f, const float* __restrict__ bhh_b)
{
    extern __shared__ char smem[];
    float* bias_sm = (float*)(smem + SBIAS);
    const uint32_t smb = smem_u32(smem);
    const int jb = blockIdx.x, rowt = blockIdx.y, dir = blockIdx.z;
    const int tid = threadIdx.x, wid = tid >> 5, lane = tid & 31;
    const int row0 = rowt * 128, j0 = jb * 32;

    const float* W   = dir ? Whh_b : Whh_f;
    const float* bhh = dir ? bhh_b : bhh_f;
    const float* xpb = dir ? g_xp_b : g_xp_f;
    float*      seqb = dir ? g_seq_b : g_seq_f;

    for (int e = tid; e < 96 * KW; e += 256) {
        int n = e / KW, k = e - n * KW;
        int g = n >> 5, jj = n & 31, col = j0 + jj;
        float w = (col < HIDN && k < HIDN) ? W[((size_t)g * HIDN + col) * HIDN + k] : 0.f;
        __nv_bfloat16 hi = __float2bfloat16(w);
        __nv_bfloat16 lo = __float2bfloat16(w - __bfloat162float(hi));
        *(__nv_bfloat16*)(smem + WHI + (size_t)e * 2) = hi;
        *(__nv_bfloat16*)(smem + WLO + (size_t)e * 2) = lo;
    }
    for (int n = tid; n < 96; n += 256) {
        int g = n >> 5, jj = n & 31, col = j0 + jj;
        bias_sm[n] = (col < HIDN) ? bhh[g * HIDN + col] : 0.f;
    }
    __syncthreads();

    const int a_r  = (lane & 7) + ((lane >> 3) & 1) * 8;
    const int a_c2 = ((lane >> 4) & 1) * 16;
    const int b_n  = ((lane >> 4) ? 8 : 0) + (lane & 7);
    const int b_k2 = ((lane >> 3) & 1) * 16;
    int* ctr = &g_ctr[dir][rowt];

    // warp-local staging: lane -> (row = wid*16 + lane/2, half = lane&1)
    const int wrow  = wid * 16 + (lane >> 1);
    const int whalf = lane & 1;
    const uint32_t dsth = smb + ASTG  + wrow * 48 + whalf * 16;
    const uint32_t dstl = smb + ALOFF + wrow * 48 + whalf * 16;

    // hprev in registers: [q][hf*2 + e], matching the epilogue fragment map
    float hprev_reg[4][4];
    #pragma unroll
    for (int q = 0; q < 4; q++)
        #pragma unroll
        for (int e = 0; e < 4; e++) hprev_reg[q][e] = 0.f;

    for (int s = 0; s < T_LEN; s++) {
        const int t = dir ? (T_LEN - 1 - s) : s;
        const float* xp_t  = xpb + (size_t)t * S_TOT * G3;
        float*       seq_t = seqb + (size_t)t * S_TOT * HIDN;
        const int par = s & 1;
        const bool mm = (s > 0);

        // L2 prefetch of this step's xp working set (overlaps MMA loop)
        {
            int r0e = row0 + wid * 16 + (lane >> 2);
            #pragma unroll
            for (int hf = 0; hf < 2; hf++) {
                const float* pr = xp_t + (size_t)(r0e + hf * 8) * G3 + j0;
                pf_l2(pr); pf_l2(pr + HIDN); pf_l2(pr + 2 * HIDN);
            }
        }

        float acc[12][4];
        #pragma unroll
        for (int n = 0; n < 12; n++)
            #pragma unroll
            for (int e = 0; e < 4; e++) acc[n][e] = 0.f;

        if (mm) {
            const __nv_bfloat16* hh = g_hbh[dir][par ^ 1] + (size_t)(row0 + wrow) * HPAD;
            const __nv_bfloat16* hl = g_hbl[dir][par ^ 1] + (size_t)(row0 + wrow) * HPAD;
            // stage chunk 0 into buf 0 (warp-local)
            cpa16(dsth, hh + whalf * 8);
            cpa16(dstl, hl + whalf * 8);
            CP_COMMIT();

            for (int kc = 0; kc < 13; kc++) {
                const int buf = kc & 1;
                const bool more = (kc < 12);
                CP_WAIT0();
                __syncwarp();
                uint32_t AH[4], AL[4];
                {
                    uint32_t ra = smb + ASTG + buf * ABUF + (wid * 16 + a_r) * 48 + a_c2;
                    ldsm4(AH[0], AH[1], AH[2], AH[3], ra);
                    ldsm4(AL[0], AL[1], AL[2], AL[3], ra + (ALOFF - ASTG));
                }
                __syncwarp();
                if (more) {
                    int k0 = (kc + 1) * 16 + whalf * 8;
                    cpa16(dsth + (buf ^ 1) * ABUF, hh + k0);
                    cpa16(dstl + (buf ^ 1) * ABUF, hl + k0);
                    CP_COMMIT();
                }
                #pragma unroll
                for (int ng = 0; ng < 6; ng++) {
                    uint32_t bh0, bh1, bh2, bh3, bl0, bl1, bl2, bl3;
                    uint32_t rb = smb + WHI + (ng * 16 + b_n) * (KW * 2) + kc * 32 + b_k2;
                    ldsm4(bh0, bh1, bh2, bh3, rb);
                    ldsm4(bl0, bl1, bl2, bl3, rb + WBYT);
                    mma_bf16(acc[2*ng],   AH, bh0, bh1);
                    mma_bf16(acc[2*ng],   AL, bh0, bh1);
                    mma_bf16(acc[2*ng],   AH, bl0, bl1);
                    mma_bf16(acc[2*ng+1], AH, bh2, bh3);
                    mma_bf16(acc[2*ng+1], AL, bh2, bh3);
                    mma_bf16(acc[2*ng+1], AH, bl2, bl3);
                }
            }
        }

        // fused GRU epilogue (hprev from registers; r,z biases folded into xp)
        {
            const int rb0 = row0 + wid * 16 + (lane >> 2);
            const int cb  = (lane & 3) * 2;
            #pragma unroll
            for (int q = 0; q < 4; q++) {
                int jj = q * 8 + cb;
                int j = j0 + jj;
                if (j >= HIDN) continue;
                float nbias0 = bias_sm[64 + jj], nbias1 = bias_sm[64 + jj + 1];
                #pragma unroll
                for (int hf = 0; hf < 2; hf++) {
                    int row = rb0 + hf * 8;
                    int e0 = hf * 2, e1 = hf * 2 + 1;
                    const float* xr = xp_t + (size_t)row * G3;
                    float2 xrv = *(const float2*)&xr[j];
                    float2 xzv = *(const float2*)&xr[HIDN + j];
                    float2 xnv = *(const float2*)&xr[2 * HIDN + j];
                    float hp0 = hprev_reg[q][e0], hp1 = hprev_reg[q][e1];
                    float r0 = sigm(xrv.x + acc[q][e0]);
                    float z0 = sigm(xzv.x + acc[q + 4][e0]);
                    float n0 = tanhf(xnv.x + r0 * (acc[q + 8][e0] + nbias0));
                    float h0 = (1.f - z0) * n0 + z0 * hp0;
                    float r1 = sigm(xrv.y + acc[q][e1]);
                    float z1 = sigm(xzv.y + acc[q + 4][e1]);
                    float n1 = tanhf(xnv.y + r1 * (acc[q + 8][e1] + nbias1));
                    float h1 = (1.f - z1) * n1 + z1 * hp1;
                    *(float2*)&seq_t[(size_t)row * HIDN + j] = make_float2(h0, h1);
                    *(uint32_t*)&g_hbh[dir][par][(size_t)row * HPAD + j] = bf16x2_hi(h0, h1);
                    *(uint32_t*)&g_hbl[dir][par][(size_t)row * HPAD + j] = bf16x2_lo(h0, h1);
                    hprev_reg[q][e0] = h0;
                    hprev_reg[q][e1] = h1;
                }
            }
        }

        __threadfence();
        __syncthreads();
        if (tid == 0) {
            atomicAdd(ctr, 1);
            int target = 7 * (s + 1);
            while (*(volatile int*)ctr < target) { }
            __threadfence();
        }
        __syncthreads();
    }
}

__global__ void __launch_bounds__(256) word_attn_kernel(const float* __restrict__ aw)
{
    extern __shared__ float tup[];
    __shared__ float sc[T_LEN];
    const int s = blockIdx.x;
    const int lane = threadIdx.x & 31, wid = threadIdx.x >> 5;
    for (int t = wid; t < T_LEN; t += 8) {
        const float* f = g_seq_f + ((size_t)t * S_TOT + s) * HIDN;
        const float* b = g_seq_b + ((size_t)t * S_TOT + s) * HIDN;
        float sum = 0.f;
        for (int d = lane; d < HIDN; d += 32) {
            float v = f[d] + b[d];
            tup[t * HIDN + d] = v;
            sum += tanhf(v) * aw[d];
        }
        #pragma unroll
        for (int o = 16; o > 0; o >>= 1) sum += __shfl_xor_sync(0xffffffffu, sum, o);
        if (lane == 0) sc[t] = sum;
    }
    __syncthreads();
    if (threadIdx.x == 0) {
        float m = sc[0];
        for (int t = 1; t < T_LEN; t++) m = fmaxf(m, sc[t]);
        float ssum = 0.f;
        for (int t = 0; t < T_LEN; t++) { float e2 = expf(sc[t] - m); sc[t] = e2; ssum += e2; }
        float inv = 1.f / ssum;
        for (int t = 0; t < T_LEN; t++) sc[t] *= inv;
    }
    __syncthreads();
    for (int d = threadIdx.x; d < HIDN; d += 256) {
        float acc = 0.f;
        #pragma unroll 7
        for (int t = 0; t < T_LEN; t++) acc += sc[t] * tup[t * HIDN + d];
        g_H[(size_t)s * HIDN + d] = acc;
    }
}

__global__ void __launch_bounds__(128) bag_kernel(
    const float* __restrict__ sen_a, const float* __restrict__ sen_r,
    const float* __restrict__ rel, const float* __restrict__ sen_d,
    const int* __restrict__ label, float* __restrict__ logits)
{
    const int b = blockIdx.x;
    __shared__ float Hs[NSEN][HIDN];
    __shared__ float ew[NSEN];
    __shared__ float Sv[HIDN];
    __shared__ float red[128];
    for (int e = threadIdx.x; e < NSEN * HIDN; e += 128)
        Hs[e / HIDN][e % HIDN] = g_H[(size_t)b * NSEN * HIDN + e];
    __syncthreads();
    const int lane = threadIdx.x & 31, wid = threadIdx.x >> 5;
    for (int n = wid; n < NSEN; n += 4) {
        float sum = 0.f;
        for (int d = lane; d < HIDN; d += 32)
            sum += Hs[n][d] * sen_a[d] * sen_r[d];
        #pragma unroll
        for (int o = 16; o > 0; o >>= 1) sum += __shfl_xor_sync(0xffffffffu, sum, o);
        if (lane == 0) ew[n] = sum;
    }
    __syncthreads();
    if (threadIdx.x == 0) {
        float m = ew[0];
        for (int n = 1; n < NSEN; n++) m = fmaxf(m, ew[n]);
        float s2 = 0.f;
        for (int n = 0; n < NSEN; n++) { float e2 = expf(ew[n] - m); ew[n] = e2; s2 += e2; }
        float inv = 1.f / s2;
        for (int n = 0; n < NSEN; n++) ew[n] *= inv;
    }
    __syncthreads();
    for (int d = threadIdx.x; d < HIDN; d += 128) {
        float acc = 0.f;
        for (int n = 0; n < NSEN; n++) acc += ew[n] * Hs[n][d];
        Sv[d] = acc;
    }
    __syncthreads();
    int lab = label[b];
    float bce = 0.f;
    if (threadIdx.x < NREL) {
        int r = threadIdx.x;
        float l = sen_d[r];
        for (int d = 0; d < HIDN; d++) l += Sv[d] * rel[(size_t)r * HIDN + d];
        logits[(size_t)b * NREL + r] = l;
        float tgt = (lab == r) ? 1.f : 0.f;
        bce = fmaxf(l, 0.f) - l * tgt + log1pf(expf(-fabsf(l)));
    }
    red[threadIdx.x] = bce;
    __syncthreads();
    for (int o = 64; o > 0; o >>= 1) {
        if (threadIdx.x < o) red[threadIdx.x] += red[threadIdx.x + o];
        __syncthreads();
    }
    if (threadIdx.x == 0) g_bagloss[b] = red[0] / (float)NREL;
}

__global__ void loss_sum_kernel(float* __restrict__ out) {
    __shared__ float red[128];
    red[threadIdx.x] = g_bagloss[threadIdx.x];
    __syncthreads();
    for (int o = 64; o > 0; o >>= 1) {
        if (threadIdx.x < o) red[threadIdx.x] += red[threadIdx.x + o];
        __syncthreads();
    }
    if (threadIdx.x == 0) out[0] = red[0];
}

extern "C" void kernel_launch(void* const* d_in, const int* in_sizes, int n_in,
                              void* d_out, int out_size)
{
    const int*   tok   = (const int*)d_in[0];
    const int*   p1    = (const int*)d_in[1];
    const int*   p2    = (const int*)d_in[2];
    const int*   lab   = (const int*)d_in[3];
    const float* emb   = (const float*)d_in[4];
    const float* pemb  = (const float*)d_in[5];
    const float* Wih_f = (const float*)d_in[6];
    const float* Whh_f = (const float*)d_in[7];
    const float* bih_f = (const float*)d_in[8];
    const float* bhh_f = (const float*)d_in[9];
    const float* Wih_b = (const float*)d_in[10];
    const float* Whh_b = (const float*)d_in[11];
    const float* bih_b = (const float*)d_in[12];
    const float* bhh_b = (const float*)d_in[13];
    const float* aw    = (const float*)d_in[14];
    const float* sen_a = (const float*)d_in[15];
    const float* sen_r = (const float*)d_in[16];
    const float* rel   = (const float*)d_in[17];
    const float* sen_d = (const float*)d_in[18];
    float* out = (float*)d_out;

    int initN = 2 * 2 * S_TOT * HPAD / 2;
    init_kernel<<<(initN + 255) / 256, 256>>>();
    gather_kernel<<<(S_TOT * T_LEN * IND + 255) / 256, 256>>>(tok, p1, p2, emb, pemb);

    cudaFuncSetAttribute(xp_mma_kernel,
                         cudaFuncAttributeMaxDynamicSharedMemorySize, XP_SMEM);
    dim3 g2(S_TOT * T_LEN / 128, 7, 2);
    xp_mma_kernel<<<g2, 128, XP_SMEM>>>(Wih_f, Wih_b, bih_f, bih_b, bhh_f, bhh_b);

    cudaFuncSetAttribute(gru_mma_kernel,
                         cudaFuncAttributeMaxDynamicSharedMemorySize, GRU_SMEM);
    dim3 g3(7, 20, 2);
    gru_mma_kernel<<<g3, 256, GRU_SMEM>>>(Whh_f, Whh_b, bhh_f, bhh_b);

    static const int attn_smem = T_LEN * HIDN * (int)sizeof(float);
    cudaFuncSetAttribute(word_attn_kernel,
                         cudaFuncAttributeMaxDynamicSharedMemorySize, attn_smem);
    word_attn_kernel<<<S_TOT, 256, attn_smem>>>(aw);
    bag_kernel<<<NBAG, 128>>>(sen_a, sen_r, rel, sen_d, lab, out + 1);
    loss_sum_kernel<<<1, 128>>>(out);
}

// round 16
// speedup vs baseline: 2.3380x; 1.1277x over previous
#include <cuda_runtime.h>
#include <cuda_bf16.h>
#include <cuda_fp16.h>
#include <math.h>
#include <stdint.h>

#define S_TOT 2560
#define T_LEN 70
#define HIDN  200
#define G3    600
#define IND   60
#define NBAG  128
#define NSEN  20
#define NREL  100
#define HPAD  208

typedef unsigned long long ULL;

__device__ float g_x[S_TOT * T_LEN * IND];
__device__ float g_xp_f[(size_t)T_LEN * S_TOT * G3];
__device__ float g_xp_b[(size_t)T_LEN * S_TOT * G3];
__device__ float g_seq_f[(size_t)T_LEN * S_TOT * HIDN];
__device__ float g_seq_b[(size_t)T_LEN * S_TOT * HIDN];
__device__ __half g_hh16[2][2][S_TOT * HPAD];   // [dir][parity] h in fp16
__device__ float g_H[S_TOT * HIDN];
__device__ float g_bagloss[NBAG];
__device__ int   g_ctr[2][20];

__device__ __forceinline__ float sigm(float x) { return 1.f / (1.f + expf(-x)); }
__device__ __forceinline__ uint32_t smem_u32(const void* p) {
    uint32_t a;
    asm("{ .reg .u64 t; cvta.to.shared.u64 t, %1; cvt.u32.u64 %0, t; }" : "=r"(a) : "l"(p));
    return a;
}
__device__ __forceinline__ void ldsm4(uint32_t& r0, uint32_t& r1, uint32_t& r2,
                                      uint32_t& r3, uint32_t addr) {
    asm volatile("ldmatrix.sync.aligned.m8n8.x4.shared.b16 {%0,%1,%2,%3}, [%4];"
                 : "=r"(r0), "=r"(r1), "=r"(r2), "=r"(r3) : "r"(addr));
}
__device__ __forceinline__ void mma_bf16(float* d, const uint32_t* a,
                                         uint32_t b0, uint32_t b1) {
    asm volatile(
        "mma.sync.aligned.m16n8k16.row.col.f32.bf16.bf16.f32 "
        "{%0,%1,%2,%3}, {%4,%5,%6,%7}, {%8,%9}, {%0,%1,%2,%3};"
        : "+f"(d[0]), "+f"(d[1]), "+f"(d[2]), "+f"(d[3])
        : "r"(a[0]), "r"(a[1]), "r"(a[2]), "r"(a[3]), "r"(b0), "r"(b1));
}
__device__ __forceinline__ void mma_fp16(float* d, const uint32_t* a,
                                         uint32_t b0, uint32_t b1) {
    asm volatile(
        "mma.sync.aligned.m16n8k16.row.col.f32.f16.f16.f32 "
        "{%0,%1,%2,%3}, {%4,%5,%6,%7}, {%8,%9}, {%0,%1,%2,%3};"
        : "+f"(d[0]), "+f"(d[1]), "+f"(d[2]), "+f"(d[3])
        : "r"(a[0]), "r"(a[1]), "r"(a[2]), "r"(a[3]), "r"(b0), "r"(b1));
}
__device__ __forceinline__ uint32_t bf16x2_hi(float x, float y) {
    __nv_bfloat162 v; v.x = __float2bfloat16(x); v.y = __float2bfloat16(y);
    return *(uint32_t*)&v;
}
__device__ __forceinline__ uint32_t bf16x2_lo(float x, float y) {
    __nv_bfloat16 hx = __float2bfloat16(x), hy = __float2bfloat16(y);
    __nv_bfloat162 v;
    v.x = __float2bfloat16(x - __bfloat162float(hx));
    v.y = __float2bfloat16(y - __bfloat162float(hy));
    return *(uint32_t*)&v;
}
__device__ __forceinline__ uint32_t h2pack(float x, float y) {
    __half2 v; v.x = __float2half(x); v.y = __float2half(y);
    return *(uint32_t*)&v;
}
__device__ __forceinline__ void pf_l2(const void* p) {
    asm volatile("prefetch.global.L2 [%0];" :: "l"(p));
}
__device__ __forceinline__ void cpa16(uint32_t dst, const void* src) {
    asm volatile("cp.async.cg.shared.global [%0], [%1], 16;" :: "r"(dst), "l"(src));
}
#define CP_COMMIT() asm volatile("cp.async.commit_group;" ::: "memory")
#define CP_WAIT0()  asm volatile("cp.async.wait_group 0;" ::: "memory")

__global__ void init_kernel() {
    size_t i = (size_t)blockIdx.x * blockDim.x + threadIdx.x;
    size_t n = (size_t)2 * 2 * S_TOT * HPAD / 2;   // uint32 count
    if (i < n) ((uint32_t*)g_hh16)[i] = 0u;
    if (i < 40) ((int*)g_ctr)[i] = 0;
}

__global__ void gather_kernel(const int* __restrict__ tok, const int* __restrict__ p1,
                              const int* __restrict__ p2, const float* __restrict__ emb,
                              const float* __restrict__ pemb) {
    int idx = blockIdx.x * blockDim.x + threadIdx.x;
    if (idx >= S_TOT * T_LEN * IND) return;
    int st = idx / IND, c = idx - st * IND;
    float v;
    if (c < 50)      v = emb[(size_t)tok[st] * 50 + c];
    else if (c < 55) v = pemb[(size_t)p1[st] * 5 + (c - 50)];
    else             v = pemb[(size_t)p2[st] * 5 + (c - 55)];
    g_x[idx] = v;
}

// ---------------- xp = x @ W_ih^T + bias via warp-MMA (bf16 hi/lo) ----------
#define XKA   144
#define XBIAS 0
#define XAHI  512
#define XABYT (128 * XKA)
#define XALO  (XAHI + XABYT)
#define XWHI  (XALO + XABYT)
#define XWBYT (96 * XKA)
#define XWLO  (XWHI + XWBYT)
#define XP_SMEM (XWLO + XWBYT)

__global__ void __launch_bounds__(128) xp_mma_kernel(
    const float* __restrict__ Wf, const float* __restrict__ Wb,
    const float* __restrict__ bf, const float* __restrict__ bb,
    const float* __restrict__ bhf, const float* __restrict__ bhb)
{
    extern __shared__ char smem[];
    float* bias_sm = (float*)(smem + XBIAS);
    const uint32_t smb = smem_u32(smem);
    const int mb = blockIdx.x, jbb = blockIdx.y, dir = blockIdx.z;
    const float* W    = dir ? Wb : Wf;
    const float* bias = dir ? bb : bf;
    const float* bhh  = dir ? bhb : bhf;
    float* xp = dir ? g_xp_b : g_xp_f;
    const int m0 = mb * 128, c0 = jbb * 96;
    const int tid = threadIdx.x, wid = tid >> 5, lane = tid & 31;

    {
        const float* xr = g_x + (size_t)(m0 + tid) * IND;
        uint32_t* ah = (uint32_t*)(smem + XAHI + tid * XKA);
        uint32_t* al = (uint32_t*)(smem + XALO + tid * XKA);
        #pragma unroll
        for (int i = 0; i < 30; i++) {
            float2 v = *(const float2*)&xr[2 * i];
            ah[i] = bf16x2_hi(v.x, v.y);
            al[i] = bf16x2_lo(v.x, v.y);
        }
        ah[30] = 0u; ah[31] = 0u; al[30] = 0u; al[31] = 0u;
    }
    for (int e = tid; e < 96 * 32; e += 128) {
        int n = e >> 5, i = e & 31;
        int col = c0 + n, k = 2 * i;
        float w0 = 0.f, w1 = 0.f;
        if (col < G3) {
            if (k < IND)     w0 = W[(size_t)col * IND + k];
            if (k + 1 < IND) w1 = W[(size_t)col * IND + k + 1];
        }
        ((uint32_t*)(smem + XWHI + n * XKA))[i] = bf16x2_hi(w0, w1);
        ((uint32_t*)(smem + XWLO + n * XKA))[i] = bf16x2_lo(w0, w1);
    }
    for (int n = tid; n < 96; n += 128) {
        int c = c0 + n;
        float v = 0.f;
        if (c < G3) {
            v = bias[c];
            if (c < 2 * HIDN) v += bhh[c];     // fold b_hh for r,z gates
        }
        bias_sm[n] = v;
    }
    __syncthreads();

    const int a_r  = (lane & 7) + ((lane >> 3) & 1) * 8;
    const int a_c2 = ((lane >> 4) & 1) * 16;
    const int b_n  = ((lane >> 4) ? 8 : 0) + (lane & 7);
    const int b_k2 = ((lane >> 3) & 1) * 16;

    float acc[2][12][4];
    #pragma unroll
    for (int m = 0; m < 2; m++)
        #pragma unroll
        for (int n = 0; n < 12; n++)
            #pragma unroll
            for (int e = 0; e < 4; e++) acc[m][n][e] = 0.f;

    #pragma unroll
    for (int kc = 0; kc < 4; kc++) {
        uint32_t AH[2][4], AL[2][4];
        #pragma unroll
        for (int mt = 0; mt < 2; mt++) {
            uint32_t ra = smb + XAHI + (wid * 32 + mt * 16 + a_r) * XKA + kc * 32 + a_c2;
            ldsm4(AH[mt][0], AH[mt][1], AH[mt][2], AH[mt][3], ra);
            ldsm4(AL[mt][0], AL[mt][1], AL[mt][2], AL[mt][3], ra + XABYT);
        }
        #pragma unroll
        for (int ng = 0; ng < 6; ng++) {
            uint32_t bh0, bh1, bh2, bh3, bl0, bl1, bl2, bl3;
            uint32_t rb = smb + XWHI + (ng * 16 + b_n) * XKA + kc * 32 + b_k2;
            ldsm4(bh0, bh1, bh2, bh3, rb);
            ldsm4(bl0, bl1, bl2, bl3, rb + XWBYT);
            #pragma unroll
            for (int mt = 0; mt < 2; mt++) {
                mma_bf16(acc[mt][2*ng],   AH[mt], bh0, bh1);
                mma_bf16(acc[mt][2*ng],   AL[mt], bh0, bh1);
                mma_bf16(acc[mt][2*ng],   AH[mt], bl0, bl1);
                mma_bf16(acc[mt][2*ng+1], AH[mt], bh2, bh3);
                mma_bf16(acc[mt][2*ng+1], AL[mt], bh2, bh3);
                mma_bf16(acc[mt][2*ng+1], AH[mt], bl2, bl3);
            }
        }
    }

    const int r_l = lane >> 2, cb = (lane & 3) * 2;
    #pragma unroll
    for (int mt = 0; mt < 2; mt++) {
        #pragma unroll
        for (int q = 0; q < 12; q++) {
            int c = c0 + q * 8 + cb;
            if (c >= G3) continue;
            float b0 = bias_sm[q * 8 + cb], b1 = bias_sm[q * 8 + cb + 1];
            #pragma unroll
            for (int hf = 0; hf < 2; hf++) {
                int m = m0 + wid * 32 + mt * 16 + hf * 8 + r_l;
                int s = m / T_LEN, t = m - s * T_LEN;
                int e0 = hf * 2;
                float2 out = make_float2(acc[mt][q][e0] + b0, acc[mt][q][e0 + 1] + b1);
                *(float2*)&xp[((size_t)t * S_TOT + s) * G3 + c] = out;
            }
        }
    }
}

// ---------------- warp-MMA persistent GRU, fp16 2-term ----------------------
// h in fp16 (1 term), W in fp16 hi+lo (2 terms): 24 MMAs/chunk vs 36.
#define KW   216
#define SBIAS 0
#define ASTG  512
#define ABUF  6144
#define WHI   (ASTG + 2 * ABUF)        // 12800
#define WBYT  (96 * KW * 2)            // 41472
#define WLO   (WHI + WBYT)
#define GRU_SMEM (WLO + WBYT)          // 95744

__global__ void __launch_bounds__(256, 2) gru_mma_kernel(
    const float* __restrict__ Whh_f, const float* __restrict__ Whh_b,
    const float* __restrict__ bhh_f, const float* __restrict__ bhh_b)
{
    extern __shared__ char smem[];
    float* bias_sm = (float*)(smem + SBIAS);
    const uint32_t smb = smem_u32(smem);
    const int jb = blockIdx.x, rowt = blockIdx.y, dir = blockIdx.z;
    const int tid = threadIdx.x, wid = tid >> 5, lane = tid & 31;
    const int row0 = rowt * 128, j0 = jb * 32;

    const float* W   = dir ? Whh_b : Whh_f;
    const float* bhh = dir ? bhh_b : bhh_f;
    const float* xpb = dir ? g_xp_b : g_xp_f;
    float*      seqb = dir ? g_seq_b : g_seq_f;

    for (int e = tid; e < 96 * KW; e += 256) {
        int n = e / KW, k = e - n * KW;
        int g = n >> 5, jj = n & 31, col = j0 + jj;
        float w = (col < HIDN && k < HIDN) ? W[((size_t)g * HIDN + col) * HIDN + k] : 0.f;
        __half hi = __float2half(w);
        __half lo = __float2half(w - __half2float(hi));
        *(__half*)(smem + WHI + (size_t)e * 2) = hi;
        *(__half*)(smem + WLO + (size_t)e * 2) = lo;
    }
    for (int n = tid; n < 96; n += 256) {
        int g = n >> 5, jj = n & 31, col = j0 + jj;
        bias_sm[n] = (col < HIDN) ? bhh[g * HIDN + col] : 0.f;
    }
    __syncthreads();

    const int a_r  = (lane & 7) + ((lane >> 3) & 1) * 8;
    const int a_c2 = ((lane >> 4) & 1) * 16;
    const int b_n  = ((lane >> 4) ? 8 : 0) + (lane & 7);
    const int b_k2 = ((lane >> 3) & 1) * 16;
    int* ctr = &g_ctr[dir][rowt];

    // warp-local staging: lane -> (row = wid*16 + lane/2, half = lane&1)
    const int wrow  = wid * 16 + (lane >> 1);
    const int whalf = lane & 1;
    const uint32_t dsth = smb + ASTG + wrow * 48 + whalf * 16;

    float hprev_reg[4][4];
    #pragma unroll
    for (int q = 0; q < 4; q++)
        #pragma unroll
        for (int e = 0; e < 4; e++) hprev_reg[q][e] = 0.f;

    for (int s = 0; s < T_LEN; s++) {
        const int t = dir ? (T_LEN - 1 - s) : s;
        const float* xp_t  = xpb + (size_t)t * S_TOT * G3;
        float*       seq_t = seqb + (size_t)t * S_TOT * HIDN;
        const int par = s & 1;
        const bool mm = (s > 0);

        // L2 prefetch of this step's xp working set (overlaps MMA loop)
        {
            int r0e = row0 + wid * 16 + (lane >> 2);
            #pragma unroll
            for (int hf = 0; hf < 2; hf++) {
                const float* pr = xp_t + (size_t)(r0e + hf * 8) * G3 + j0;
                pf_l2(pr); pf_l2(pr + HIDN); pf_l2(pr + 2 * HIDN);
            }
        }

        float acc[12][4];
        #pragma unroll
        for (int n = 0; n < 12; n++)
            #pragma unroll
            for (int e = 0; e < 4; e++) acc[n][e] = 0.f;

        if (mm) {
            const __half* hh = g_hh16[dir][par ^ 1] + (size_t)(row0 + wrow) * HPAD;
            cpa16(dsth, hh + whalf * 8);
            CP_COMMIT();

            for (int kc = 0; kc < 13; kc++) {
                const int buf = kc & 1;
                const bool more = (kc < 12);
                CP_WAIT0();
                __syncwarp();
                uint32_t AH[4];
                {
                    uint32_t ra = smb + ASTG + buf * ABUF + (wid * 16 + a_r) * 48 + a_c2;
                    ldsm4(AH[0], AH[1], AH[2], AH[3], ra);
                }
                __syncwarp();
                if (more) {
                    int k0 = (kc + 1) * 16 + whalf * 8;
                    cpa16(dsth + (buf ^ 1) * ABUF, hh + k0);
                    CP_COMMIT();
                }
                #pragma unroll
                for (int ng = 0; ng < 6; ng++) {
                    uint32_t bh0, bh1, bh2, bh3, bl0, bl1, bl2, bl3;
                    uint32_t rb = smb + WHI + (ng * 16 + b_n) * (KW * 2) + kc * 32 + b_k2;
                    ldsm4(bh0, bh1, bh2, bh3, rb);
                    ldsm4(bl0, bl1, bl2, bl3, rb + WBYT);
                    mma_fp16(acc[2*ng],   AH, bh0, bh1);
                    mma_fp16(acc[2*ng],   AH, bl0, bl1);
                    mma_fp16(acc[2*ng+1], AH, bh2, bh3);
                    mma_fp16(acc[2*ng+1], AH, bl2, bl3);
                }
            }
        }

        // fused GRU epilogue (hprev from registers; r,z biases folded into xp)
        {
            const int rb0 = row0 + wid * 16 + (lane >> 2);
            const int cb  = (lane & 3) * 2;
            #pragma unroll
            for (int q = 0; q < 4; q++) {
                int jj = q * 8 + cb;
                int j = j0 + jj;
                if (j >= HIDN) continue;
                float nbias0 = bias_sm[64 + jj], nbias1 = bias_sm[64 + jj + 1];
                #pragma unroll
                for (int hf = 0; hf < 2; hf++) {
                    int row = rb0 + hf * 8;
                    int e0 = hf * 2, e1 = hf * 2 + 1;
                    const float* xr = xp_t + (size_t)row * G3;
                    float2 xrv = *(const float2*)&xr[j];
                    float2 xzv = *(const float2*)&xr[HIDN + j];
                    float2 xnv = *(const float2*)&xr[2 * HIDN + j];
                    float hp0 = hprev_reg[q][e0], hp1 = hprev_reg[q][e1];
                    float r0 = sigm(xrv.x + acc[q][e0]);
                    float z0 = sigm(xzv.x + acc[q + 4][e0]);
                    float n0 = tanhf(xnv.x + r0 * (acc[q + 8][e0] + nbias0));
                    float h0 = (1.f - z0) * n0 + z0 * hp0;
                    float r1 = sigm(xrv.y + acc[q][e1]);
                    float z1 = sigm(xzv.y + acc[q + 4][e1]);
                    float n1 = tanhf(xnv.y + r1 * (acc[q + 8][e1] + nbias1));
                    float h1 = (1.f - z1) * n1 + z1 * hp1;
                    *(float2*)&seq_t[(size_t)row * HIDN + j] = make_float2(h0, h1);
                    *(uint32_t*)&g_hh16[dir][par][(size_t)row * HPAD + j] = h2pack(h0, h1);
                    hprev_reg[q][e0] = h0;
                    hprev_reg[q][e1] = h1;
                }
            }
        }

        __threadfence();
        __syncthreads();
        if (tid == 0) {
            atomicAdd(ctr, 1);
            int target = 7 * (s + 1);
            while (*(volatile int*)ctr < target) { }
            __threadfence();
        }
        __syncthreads();
    }
}

__global__ void __launch_bounds__(256) word_attn_kernel(const float* __restrict__ aw)
{
    extern __shared__ float tup[];
    __shared__ float sc[T_LEN];
    const int s = blockIdx.x;
    const int lane = threadIdx.x & 31, wid = threadIdx.x >> 5;
    for (int t = wid; t < T_LEN; t += 8) {
        const float* f = g_seq_f + ((size_t)t * S_TOT + s) * HIDN;
        const float* b = g_seq_b + ((size_t)t * S_TOT + s) * HIDN;
        float sum = 0.f;
        for (int d = lane; d < HIDN; d += 32) {
            float v = f[d] + b[d];
            tup[t * HIDN + d] = v;
            sum += tanhf(v) * aw[d];
        }
        #pragma unroll
        for (int o = 16; o > 0; o >>= 1) sum += __shfl_xor_sync(0xffffffffu, sum, o);
        if (lane == 0) sc[t] = sum;
    }
    __syncthreads();
    if (threadIdx.x == 0) {
        float m = sc[0];
        for (int t = 1; t < T_LEN; t++) m = fmaxf(m, sc[t]);
        float ssum = 0.f;
        for (int t = 0; t < T_LEN; t++) { float e2 = expf(sc[t] - m); sc[t] = e2; ssum += e2; }
        float inv = 1.f / ssum;
        for (int t = 0; t < T_LEN; t++) sc[t] *= inv;
    }
    __syncthreads();
    for (int d = threadIdx.x; d < HIDN; d += 256) {
        float acc = 0.f;
        #pragma unroll 7
        for (int t = 0; t < T_LEN; t++) acc += sc[t] * tup[t * HIDN + d];
        g_H[(size_t)s * HIDN + d] = acc;
    }
}

__global__ void __launch_bounds__(128) bag_kernel(
    const float* __restrict__ sen_a, const float* __restrict__ sen_r,
    const float* __restrict__ rel, const float* __restrict__ sen_d,
    const int* __restrict__ label, float* __restrict__ logits)
{
    const int b = blockIdx.x;
    __shared__ float Hs[NSEN][HIDN];
    __shared__ float ew[NSEN];
    __shared__ float Sv[HIDN];
    __shared__ float red[128];
    for (int e = threadIdx.x; e < NSEN * HIDN; e += 128)
        Hs[e / HIDN][e % HIDN] = g_H[(size_t)b * NSEN * HIDN + e];
    __syncthreads();
    const int lane = threadIdx.x & 31, wid = threadIdx.x >> 5;
    for (int n = wid; n < NSEN; n += 4) {
        float sum = 0.f;
        for (int d = lane; d < HIDN; d += 32)
            sum += Hs[n][d] * sen_a[d] * sen_r[d];
        #pragma unroll
        for (int o = 16; o > 0; o >>= 1) sum += __shfl_xor_sync(0xffffffffu, sum, o);
        if (lane == 0) ew[n] = sum;
    }
    __syncthreads();
    if (threadIdx.x == 0) {
        float m = ew[0];
        for (int n = 1; n < NSEN; n++) m = fmaxf(m, ew[n]);
        float s2 = 0.f;
        for (int n = 0; n < NSEN; n++) { float e2 = expf(ew[n] - m); ew[n] = e2; s2 += e2; }
        float inv = 1.f / s2;
        for (int n = 0; n < NSEN; n++) ew[n] *= inv;
    }
    __syncthreads();
    for (int d = threadIdx.x; d < HIDN; d += 128) {
        float acc = 0.f;
        for (int n = 0; n < NSEN; n++) acc += ew[n] * Hs[n][d];
        Sv[d] = acc;
    }
    __syncthreads();
    int lab = label[b];
    float bce = 0.f;
    if (threadIdx.x < NREL) {
        int r = threadIdx.x;
        float l = sen_d[r];
        for (int d = 0; d < HIDN; d++) l += Sv[d] * rel[(size_t)r * HIDN + d];
        logits[(size_t)b * NREL + r] = l;
        float tgt = (lab == r) ? 1.f : 0.f;
        bce = fmaxf(l, 0.f) - l * tgt + log1pf(expf(-fabsf(l)));
    }
    red[threadIdx.x] = bce;
    __syncthreads();
    for (int o = 64; o > 0; o >>= 1) {
        if (threadIdx.x < o) red[threadIdx.x] += red[threadIdx.x + o];
        __syncthreads();
    }
    if (threadIdx.x == 0) g_bagloss[b] = red[0] / (float)NREL;
}

__global__ void loss_sum_kernel(float* __restrict__ out) {
    __shared__ float red[128];
    red[threadIdx.x] = g_bagloss[threadIdx.x];
    __syncthreads();
    for (int o = 64; o > 0; o >>= 1) {
        if (threadIdx.x < o) red[threadIdx.x] += red[threadIdx.x + o];
        __syncthreads();
    }
    if (threadIdx.x == 0) out[0] = red[0];
}

extern "C" void kernel_launch(void* const* d_in, const int* in_sizes, int n_in,
                              void* d_out, int out_size)
{
    const int*   tok   = (const int*)d_in[0];
    const int*   p1    = (const int*)d_in[1];
    const int*   p2    = (const int*)d_in[2];
    const int*   lab   = (const int*)d_in[3];
    const float* emb   = (const float*)d_in[4];
    const float* pemb  = (const float*)d_in[5];
    const float* Wih_f = (const float*)d_in[6];
    const float* Whh_f = (const float*)d_in[7];
    const float* bih_f = (const float*)d_in[8];
    const float* bhh_f = (const float*)d_in[9];
    const float* Wih_b = (const float*)d_in[10];
    const float* Whh_b = (const float*)d_in[11];
    const float* bih_b = (const float*)d_in[12];
    const float* bhh_b = (const float*)d_in[13];
    const float* aw    = (const float*)d_in[14];
    const float* sen_a = (const float*)d_in[15];
    const float* sen_r = (const float*)d_in[16];
    const float* rel   = (const float*)d_in[17];
    const float* sen_d = (const float*)d_in[18];
    float* out = (float*)d_out;

    int initN = 2 * 2 * S_TOT * HPAD / 2;
    init_kernel<<<(initN + 255) / 256, 256>>>();
    gather_kernel<<<(S_TOT * T_LEN * IND + 255) / 256, 256>>>(tok, p1, p2, emb, pemb);

    cudaFuncSetAttribute(xp_mma_kernel,
                         cudaFuncAttributeMaxDynamicSharedMemorySize, XP_SMEM);
    dim3 g2(S_TOT * T_LEN / 128, 7, 2);
    xp_mma_kernel<<<g2, 128, XP_SMEM>>>(Wih_f, Wih_b, bih_f, bih_b, bhh_f, bhh_b);

    cudaFuncSetAttribute(gru_mma_kernel,
                         cudaFuncAttributeMaxDynamicSharedMemorySize, GRU_SMEM);
    dim3 g3(7, 20, 2);
    gru_mma_kernel<<<g3, 256, GRU_SMEM>>>(Whh_f, Whh_b, bhh_f, bhh_b);

    static const int attn_smem = T_LEN * HIDN * (int)sizeof(float);
    cudaFuncSetAttribute(word_attn_kernel,
                         cudaFuncAttributeMaxDynamicSharedMemorySize, attn_smem);
    word_attn_kernel<<<S_TOT, 256, attn_smem>>>(aw);
    bag_kernel<<<NBAG, 128>>>(sen_a, sen_r, rel, sen_d, lab, out + 1);
    loss_sum_kernel<<<1, 128>>>(out);
}

// round 17
// speedup vs baseline: 2.5515x; 1.0913x over previous
#include <cuda_runtime.h>
#include <cuda_bf16.h>
#include <cuda_fp16.h>
#include <math.h>
#include <stdint.h>

#define S_TOT 2560
#define T_LEN 70
#define HIDN  200
#define G3    600
#define IND   60
#define NBAG  128
#define NSEN  20
#define NREL  100
#define HPAD  208

typedef unsigned long long ULL;

__device__ float g_x[S_TOT * T_LEN * IND];
__device__ __half g_xp_f[(size_t)T_LEN * S_TOT * G3];
__device__ __half g_xp_b[(size_t)T_LEN * S_TOT * G3];
__device__ float g_seq_f[(size_t)T_LEN * S_TOT * HIDN];
__device__ float g_seq_b[(size_t)T_LEN * S_TOT * HIDN];
__device__ __half g_hh16[2][2][S_TOT * HPAD];   // [dir][parity] h in fp16
__device__ float g_H[S_TOT * HIDN];
__device__ float g_bagloss[NBAG];
__device__ int   g_ctr[2][20];

__device__ __forceinline__ float sigm(float x) { return 1.f / (1.f + expf(-x)); }
__device__ __forceinline__ uint32_t smem_u32(const void* p) {
    uint32_t a;
    asm("{ .reg .u64 t; cvta.to.shared.u64 t, %1; cvt.u32.u64 %0, t; }" : "=r"(a) : "l"(p));
    return a;
}
__device__ __forceinline__ void ldsm4(uint32_t& r0, uint32_t& r1, uint32_t& r2,
                                      uint32_t& r3, uint32_t addr) {
    asm volatile("ldmatrix.sync.aligned.m8n8.x4.shared.b16 {%0,%1,%2,%3}, [%4];"
                 : "=r"(r0), "=r"(r1), "=r"(r2), "=r"(r3) : "r"(addr));
}
__device__ __forceinline__ void mma_fp16(float* d, const uint32_t* a,
                                         uint32_t b0, uint32_t b1) {
    asm volatile(
        "mma.sync.aligned.m16n8k16.row.col.f32.f16.f16.f32 "
        "{%0,%1,%2,%3}, {%4,%5,%6,%7}, {%8,%9}, {%0,%1,%2,%3};"
        : "+f"(d[0]), "+f"(d[1]), "+f"(d[2]), "+f"(d[3])
        : "r"(a[0]), "r"(a[1]), "r"(a[2]), "r"(a[3]), "r"(b0), "r"(b1));
}
__device__ __forceinline__ uint32_t h2pack(float x, float y) {
    __half2 v; v.x = __float2half(x); v.y = __float2half(y);
    return *(uint32_t*)&v;
}
__device__ __forceinline__ void pf_l2(const void* p) {
    asm volatile("prefetch.global.L2 [%0];" :: "l"(p));
}
__device__ __forceinline__ void cpa16(uint32_t dst, const void* src) {
    asm volatile("cp.async.cg.shared.global [%0], [%1], 16;" :: "r"(dst), "l"(src));
}
#define CP_COMMIT() asm volatile("cp.async.commit_group;" ::: "memory")
#define CP_WAIT0()  asm volatile("cp.async.wait_group 0;" ::: "memory")

__global__ void init_kernel() {
    size_t i = (size_t)blockIdx.x * blockDim.x + threadIdx.x;
    size_t n = (size_t)2 * 2 * S_TOT * HPAD / 2;   // uint32 count
    if (i < n) ((uint32_t*)g_hh16)[i] = 0u;
    if (i < 40) ((int*)g_ctr)[i] = 0;
}

__global__ void gather_kernel(const int* __restrict__ tok, const int* __restrict__ p1,
                              const int* __restrict__ p2, const float* __restrict__ emb,
                              const float* __restrict__ pemb) {
    int idx = blockIdx.x * blockDim.x + threadIdx.x;
    if (idx >= S_TOT * T_LEN * IND) return;
    int st = idx / IND, c = idx - st * IND;
    float v;
    if (c < 50)      v = emb[(size_t)tok[st] * 50 + c];
    else if (c < 55) v = pemb[(size_t)p1[st] * 5 + (c - 50)];
    else             v = pemb[(size_t)p2[st] * 5 + (c - 55)];
    g_x[idx] = v;
}

// ---------------- xp = x @ W_ih^T + bias via warp-MMA (fp16 1-term) ---------
#define XKA   144
#define XBIAS 0
#define XAHI  512
#define XABYT (128 * XKA)
#define XWHI  (XAHI + XABYT)           // 18944
#define XWBYT (96 * XKA)
#define XP_SMEM (XWHI + XWBYT)         // 32768

__global__ void __launch_bounds__(128) xp_mma_kernel(
    const float* __restrict__ Wf, const float* __restrict__ Wb,
    const float* __restrict__ bf, const float* __restrict__ bb,
    const float* __restrict__ bhf, const float* __restrict__ bhb)
{
    extern __shared__ char smem[];
    float* bias_sm = (float*)(smem + XBIAS);
    const uint32_t smb = smem_u32(smem);
    const int mb = blockIdx.x, jbb = blockIdx.y, dir = blockIdx.z;
    const float* W    = dir ? Wb : Wf;
    const float* bias = dir ? bb : bf;
    const float* bhh  = dir ? bhb : bhf;
    __half* xp = dir ? g_xp_b : g_xp_f;
    const int m0 = mb * 128, c0 = jbb * 96;
    const int tid = threadIdx.x, wid = tid >> 5, lane = tid & 31;

    {
        const float* xr = g_x + (size_t)(m0 + tid) * IND;
        uint32_t* ah = (uint32_t*)(smem + XAHI + tid * XKA);
        #pragma unroll
        for (int i = 0; i < 30; i++) {
            float2 v = *(const float2*)&xr[2 * i];
            ah[i] = h2pack(v.x, v.y);
        }
        ah[30] = 0u; ah[31] = 0u;
    }
    for (int e = tid; e < 96 * 32; e += 128) {
        int n = e >> 5, i = e & 31;
        int col = c0 + n, k = 2 * i;
        float w0 = 0.f, w1 = 0.f;
        if (col < G3) {
            if (k < IND)     w0 = W[(size_t)col * IND + k];
            if (k + 1 < IND) w1 = W[(size_t)col * IND + k + 1];
        }
        ((uint32_t*)(smem + XWHI + n * XKA))[i] = h2pack(w0, w1);
    }
    for (int n = tid; n < 96; n += 128) {
        int c = c0 + n;
        float v = 0.f;
        if (c < G3) {
            v = bias[c];
            if (c < 2 * HIDN) v += bhh[c];     // fold b_hh for r,z gates
        }
        bias_sm[n] = v;
    }
    __syncthreads();

    const int a_r  = (lane & 7) + ((lane >> 3) & 1) * 8;
    const int a_c2 = ((lane >> 4) & 1) * 16;
    const int b_n  = ((lane >> 4) ? 8 : 0) + (lane & 7);
    const int b_k2 = ((lane >> 3) & 1) * 16;

    float acc[2][12][4];
    #pragma unroll
    for (int m = 0; m < 2; m++)
        #pragma unroll
        for (int n = 0; n < 12; n++)
            #pragma unroll
            for (int e = 0; e < 4; e++) acc[m][n][e] = 0.f;

    #pragma unroll
    for (int kc = 0; kc < 4; kc++) {
        uint32_t AH[2][4];
        #pragma unroll
        for (int mt = 0; mt < 2; mt++) {
            uint32_t ra = smb + XAHI + (wid * 32 + mt * 16 + a_r) * XKA + kc * 32 + a_c2;
            ldsm4(AH[mt][0], AH[mt][1], AH[mt][2], AH[mt][3], ra);
        }
        #pragma unroll
        for (int ng = 0; ng < 6; ng++) {
            uint32_t bh0, bh1, bh2, bh3;
            uint32_t rb = smb + XWHI + (ng * 16 + b_n) * XKA + kc * 32 + b_k2;
            ldsm4(bh0, bh1, bh2, bh3, rb);
            #pragma unroll
            for (int mt = 0; mt < 2; mt++) {
                mma_fp16(acc[mt][2*ng],   AH[mt], bh0, bh1);
                mma_fp16(acc[mt][2*ng+1], AH[mt], bh2, bh3);
            }
        }
    }

    const int r_l = lane >> 2, cb = (lane & 3) * 2;
    #pragma unroll
    for (int mt = 0; mt < 2; mt++) {
        #pragma unroll
        for (int q = 0; q < 12; q++) {
            int c = c0 + q * 8 + cb;
            if (c >= G3) continue;
            float b0 = bias_sm[q * 8 + cb], b1 = bias_sm[q * 8 + cb + 1];
            #pragma unroll
            for (int hf = 0; hf < 2; hf++) {
                int m = m0 + wid * 32 + mt * 16 + hf * 8 + r_l;
                int s = m / T_LEN, t = m - s * T_LEN;
                int e0 = hf * 2;
                *(uint32_t*)&xp[((size_t)t * S_TOT + s) * G3 + c] =
                    h2pack(acc[mt][q][e0] + b0, acc[mt][q][e0 + 1] + b1);
            }
        }
    }
}

// ---------------- warp-MMA persistent GRU, fp16 1-term ----------------------
// h fp16 (1 term), W fp16 (1 term): 12 MMAs/chunk, 6 B-ldsm/chunk.
#define KW   216
#define SBIAS 0
#define ASTG  512
#define ABUF  6144
#define WHI   (ASTG + 2 * ABUF)        // 12800
#define WBYT  (96 * KW * 2)            // 41472
#define GRU_SMEM (WHI + WBYT)          // 54272

__global__ void __launch_bounds__(256, 2) gru_mma_kernel(
    const float* __restrict__ Whh_f, const float* __restrict__ Whh_b,
    const float* __restrict__ bhh_f, const float* __restrict__ bhh_b)
{
    extern __shared__ char smem[];
    float* bias_sm = (float*)(smem + SBIAS);
    const uint32_t smb = smem_u32(smem);
    const int jb = blockIdx.x, rowt = blockIdx.y, dir = blockIdx.z;
    const int tid = threadIdx.x, wid = tid >> 5, lane = tid & 31;
    const int row0 = rowt * 128, j0 = jb * 32;

    const float* W   = dir ? Whh_b : Whh_f;
    const float* bhh = dir ? bhh_b : bhh_f;
    const __half* xpb = dir ? g_xp_b : g_xp_f;
    float*      seqb = dir ? g_seq_b : g_seq_f;

    for (int e = tid; e < 96 * KW; e += 256) {
        int n = e / KW, k = e - n * KW;
        int g = n >> 5, jj = n & 31, col = j0 + jj;
        float w = (col < HIDN && k < HIDN) ? W[((size_t)g * HIDN + col) * HIDN + k] : 0.f;
        *(__half*)(smem + WHI + (size_t)e * 2) = __float2half(w);
    }
    for (int n = tid; n < 96; n += 256) {
        int g = n >> 5, jj = n & 31, col = j0 + jj;
        bias_sm[n] = (col < HIDN) ? bhh[g * HIDN + col] : 0.f;
    }
    __syncthreads();

    const int a_r  = (lane & 7) + ((lane >> 3) & 1) * 8;
    const int a_c2 = ((lane >> 4) & 1) * 16;
    const int b_n  = ((lane >> 4) ? 8 : 0) + (lane & 7);
    const int b_k2 = ((lane >> 3) & 1) * 16;
    int* ctr = &g_ctr[dir][rowt];

    // warp-local staging: lane -> (row = wid*16 + lane/2, half = lane&1)
    const int wrow  = wid * 16 + (lane >> 1);
    const int whalf = lane & 1;
    const uint32_t dsth = smb + ASTG + wrow * 48 + whalf * 16;

    float hprev_reg[4][4];
    #pragma unroll
    for (int q = 0; q < 4; q++)
        #pragma unroll
        for (int e = 0; e < 4; e++) hprev_reg[q][e] = 0.f;

    for (int s = 0; s < T_LEN; s++) {
        const int t = dir ? (T_LEN - 1 - s) : s;
        const __half* xp_t = xpb + (size_t)t * S_TOT * G3;
        float*       seq_t = seqb + (size_t)t * S_TOT * HIDN;
        const int par = s & 1;
        const bool mm = (s > 0);

        // L2 prefetch of this step's xp working set (overlaps MMA loop)
        {
            int r0e = row0 + wid * 16 + (lane >> 2);
            #pragma unroll
            for (int hf = 0; hf < 2; hf++) {
                const __half* pr = xp_t + (size_t)(r0e + hf * 8) * G3 + j0;
                pf_l2(pr); pf_l2(pr + HIDN); pf_l2(pr + 2 * HIDN);
            }
        }

        float acc[12][4];
        #pragma unroll
        for (int n = 0; n < 12; n++)
            #pragma unroll
            for (int e = 0; e < 4; e++) acc[n][e] = 0.f;

        if (mm) {
            const __half* hh = g_hh16[dir][par ^ 1] + (size_t)(row0 + wrow) * HPAD;
            cpa16(dsth, hh + whalf * 8);
            CP_COMMIT();

            for (int kc = 0; kc < 13; kc++) {
                const int buf = kc & 1;
                const bool more = (kc < 12);
                CP_WAIT0();
                __syncwarp();
                uint32_t AH[4];
                {
                    uint32_t ra = smb + ASTG + buf * ABUF + (wid * 16 + a_r) * 48 + a_c2;
                    ldsm4(AH[0], AH[1], AH[2], AH[3], ra);
                }
                __syncwarp();
                if (more) {
                    int k0 = (kc + 1) * 16 + whalf * 8;
                    cpa16(dsth + (buf ^ 1) * ABUF, hh + k0);
                    CP_COMMIT();
                }
                #pragma unroll
                for (int ng = 0; ng < 6; ng++) {
                    uint32_t bh0, bh1, bh2, bh3;
                    uint32_t rb = smb + WHI + (ng * 16 + b_n) * (KW * 2) + kc * 32 + b_k2;
                    ldsm4(bh0, bh1, bh2, bh3, rb);
                    mma_fp16(acc[2*ng],   AH, bh0, bh1);
                    mma_fp16(acc[2*ng+1], AH, bh2, bh3);
                }
            }
        }

        // fused GRU epilogue (hprev in registers; r,z biases folded into xp)
        {
            const int rb0 = row0 + wid * 16 + (lane >> 2);
            const int cb  = (lane & 3) * 2;
            #pragma unroll
            for (int q = 0; q < 4; q++) {
                int jj = q * 8 + cb;
                int j = j0 + jj;
                if (j >= HIDN) continue;
                float nbias0 = bias_sm[64 + jj], nbias1 = bias_sm[64 + jj + 1];
                #pragma unroll
                for (int hf = 0; hf < 2; hf++) {
                    int row = rb0 + hf * 8;
                    int e0 = hf * 2, e1 = hf * 2 + 1;
                    const __half* xr = xp_t + (size_t)row * G3;
                    float2 xrv = __half22float2(*(const __half2*)&xr[j]);
                    float2 xzv = __half22float2(*(const __half2*)&xr[HIDN + j]);
                    float2 xnv = __half22float2(*(const __half2*)&xr[2 * HIDN + j]);
                    float hp0 = hprev_reg[q][e0], hp1 = hprev_reg[q][e1];
                    float r0 = sigm(xrv.x + acc[q][e0]);
                    float z0 = sigm(xzv.x + acc[q + 4][e0]);
                    float n0 = tanhf(xnv.x + r0 * (acc[q + 8][e0] + nbias0));
                    float h0 = (1.f - z0) * n0 + z0 * hp0;
                    float r1 = sigm(xrv.y + acc[q][e1]);
                    float z1 = sigm(xzv.y + acc[q + 4][e1]);
                    float n1 = tanhf(xnv.y + r1 * (acc[q + 8][e1] + nbias1));
                    float h1 = (1.f - z1) * n1 + z1 * hp1;
                    *(float2*)&seq_t[(size_t)row * HIDN + j] = make_float2(h0, h1);
                    *(uint32_t*)&g_hh16[dir][par][(size_t)row * HPAD + j] = h2pack(h0, h1);
                    hprev_reg[q][e0] = h0;
                    hprev_reg[q][e1] = h1;
                }
            }
        }

        __threadfence();
        __syncthreads();
        if (tid == 0) {
            atomicAdd(ctr, 1);
            int target = 7 * (s + 1);
            while (*(volatile int*)ctr < target) { }
            __threadfence();
        }
        __syncthreads();
    }
}

__global__ void __launch_bounds__(256) word_attn_kernel(const float* __restrict__ aw)
{
    extern __shared__ float tup[];
    __shared__ float sc[T_LEN];
    const int s = blockIdx.x;
    const int lane = threadIdx.x & 31, wid = threadIdx.x >> 5;
    for (int t = wid; t < T_LEN; t += 8) {
        const float* f = g_seq_f + ((size_t)t * S_TOT + s) * HIDN;
        const float* b = g_seq_b + ((size_t)t * S_TOT + s) * HIDN;
        float sum = 0.f;
        for (int d = lane; d < HIDN; d += 32) {
            float v = f[d] + b[d];
            tup[t * HIDN + d] = v;
            sum += tanhf(v) * aw[d];
        }
        #pragma unroll
        for (int o = 16; o > 0; o >>= 1) sum += __shfl_xor_sync(0xffffffffu, sum, o);
        if (lane == 0) sc[t] = sum;
    }
    __syncthreads();
    if (threadIdx.x == 0) {
        float m = sc[0];
        for (int t = 1; t < T_LEN; t++) m = fmaxf(m, sc[t]);
        float ssum = 0.f;
        for (int t = 0; t < T_LEN; t++) { float e2 = expf(sc[t] - m); sc[t] = e2; ssum += e2; }
        float inv = 1.f / ssum;
        for (int t = 0; t < T_LEN; t++) sc[t] *= inv;
    }
    __syncthreads();
    for (int d = threadIdx.x; d < HIDN; d += 256) {
        float acc = 0.f;
        #pragma unroll 7
        for (int t = 0; t < T_LEN; t++) acc += sc[t] * tup[t * HIDN + d];
        g_H[(size_t)s * HIDN + d] = acc;
    }
}

__global__ void __launch_bounds__(128) bag_kernel(
    const float* __restrict__ sen_a, const float* __restrict__ sen_r,
    const float* __restrict__ rel, const float* __restrict__ sen_d,
    const int* __restrict__ label, float* __restrict__ logits)
{
    const int b = blockIdx.x;
    __shared__ float Hs[NSEN][HIDN];
    __shared__ float ew[NSEN];
    __shared__ float Sv[HIDN];
    __shared__ float red[128];
    for (int e = threadIdx.x; e < NSEN * HIDN; e += 128)
        Hs[e / HIDN][e % HIDN] = g_H[(size_t)b * NSEN * HIDN + e];
    __syncthreads();
    const int lane = threadIdx.x & 31, wid = threadIdx.x >> 5;
    for (int n = wid; n < NSEN; n += 4) {
        float sum = 0.f;
        for (int d = lane; d < HIDN; d += 32)
            sum += Hs[n][d] * sen_a[d] * sen_r[d];
        #pragma unroll
        for (int o = 16; o > 0; o >>= 1) sum += __shfl_xor_sync(0xffffffffu, sum, o);
        if (lane == 0) ew[n] = sum;
    }
    __syncthreads();
    if (threadIdx.x == 0) {
        float m = ew[0];
        for (int n = 1; n < NSEN; n++) m = fmaxf(m, ew[n]);
        float s2 = 0.f;
        for (int n = 0; n < NSEN; n++) { float e2 = expf(ew[n] - m); ew[n] = e2; s2 += e2; }
        float inv = 1.f / s2;
        for (int n = 0; n < NSEN; n++) ew[n] *= inv;
    }
    __syncthreads();
    for (int d = threadIdx.x; d < HIDN; d += 128) {
        float acc = 0.f;
        for (int n = 0; n < NSEN; n++) acc += ew[n] * Hs[n][d];
        Sv[d] = acc;
    }
    __syncthreads();
    int lab = label[b];
    float bce = 0.f;
    if (threadIdx.x < NREL) {
        int r = threadIdx.x;
        float l = sen_d[r];
        for (int d = 0; d < HIDN; d++) l += Sv[d] * rel[(size_t)r * HIDN + d];
        logits[(size_t)b * NREL + r] = l;
        float tgt = (lab == r) ? 1.f : 0.f;
        bce = fmaxf(l, 0.f) - l * tgt + log1pf(expf(-fabsf(l)));
    }
    red[threadIdx.x] = bce;
    __syncthreads();
    for (int o = 64; o > 0; o >>= 1) {
        if (threadIdx.x < o) red[threadIdx.x] += red[threadIdx.x + o];
        __syncthreads();
    }
    if (threadIdx.x == 0) g_bagloss[b] = red[0] / (float)NREL;
}

__global__ void loss_sum_kernel(float* __restrict__ out) {
    __shared__ float red[128];
    red[threadIdx.x] = g_bagloss[threadIdx.x];
    __syncthreads();
    for (int o = 64; o > 0; o >>= 1) {
        if (threadIdx.x < o) red[threadIdx.x] += red[threadIdx.x + o];
        __syncthreads();
    }
    if (threadIdx.x == 0) out[0] = red[0];
}

extern "C" void kernel_launch(void* const* d_in, const int* in_sizes, int n_in,
                              void* d_out, int out_size)
{
    const int*   tok   = (const int*)d_in[0];
    const int*   p1    = (const int*)d_in[1];
    const int*   p2    = (const int*)d_in[2];
    const int*   lab   = (const int*)d_in[3];
    const float* emb   = (const float*)d_in[4];
    const float* pemb  = (const float*)d_in[5];
    const float* Wih_f = (const float*)d_in[6];
    const float* Whh_f = (const float*)d_in[7];
    const float* bih_f = (const float*)d_in[8];
    const float* bhh_f = (const float*)d_in[9];
    const float* Wih_b = (const float*)d_in[10];
    const float* Whh_b = (const float*)d_in[11];
    const float* bih_b = (const float*)d_in[12];
    const float* bhh_b = (const float*)d_in[13];
    const float* aw    = (const float*)d_in[14];
    const float* sen_a = (const float*)d_in[15];
    const float* sen_r = (const float*)d_in[16];
    const float* rel   = (const float*)d_in[17];
    const float* sen_d = (const float*)d_in[18];
    float* out = (float*)d_out;

    int initN = 2 * 2 * S_TOT * HPAD / 2;
    init_kernel<<<(initN + 255) / 256, 256>>>();
    gather_kernel<<<(S_TOT * T_LEN * IND + 255) / 256, 256>>>(tok, p1, p2, emb, pemb);

    cudaFuncSetAttribute(xp_mma_kernel,
                         cudaFuncAttributeMaxDynamicSharedMemorySize, XP_SMEM);
    dim3 g2(S_TOT * T_LEN / 128, 7, 2);
    xp_mma_kernel<<<g2, 128, XP_SMEM>>>(Wih_f, Wih_b, bih_f, bih_b, bhh_f, bhh_b);

    cudaFuncSetAttribute(gru_mma_kernel,
                         cudaFuncAttributeMaxDynamicSharedMemorySize, GRU_SMEM);
    dim3 g3(7, 20, 2);
    gru_mma_kernel<<<g3, 256, GRU_SMEM>>>(Whh_f, Whh_b, bhh_f, bhh_b);

    static const int attn_smem = T_LEN * HIDN * (int)sizeof(float);
    cudaFuncSetAttribute(word_attn_kernel,
                         cudaFuncAttributeMaxDynamicSharedMemorySize, attn_smem);
    word_attn_kernel<<<S_TOT, 256, attn_smem>>>(aw);
    bag_kernel<<<NBAG, 128>>>(sen_a, sen_r, rel, sen_d, lab, out + 1);
    loss_sum_kernel<<<1, 128>>>(out);
}